// round 7
// baseline (speedup 1.0000x reference)
#include <cuda_runtime.h>
#include <cuda_bf16.h>
#include <cstdint>

typedef unsigned long long ull;

// ===========================================================================
// mma.sync / ldmatrix / cp.async helpers (base sm_103 target — no tcgen05)
// ===========================================================================
__device__ __forceinline__ uint32_t smem_u32_of(const void* p) {
    uint32_t a;
    asm("{ .reg .u64 t; cvta.to.shared.u64 t, %1; cvt.u32.u64 %0, t; }"
        : "=r"(a) : "l"(p));
    return a;
}
__device__ __forceinline__ void ldsm4(uint32_t r[4], uint32_t addr) {
    asm volatile("ldmatrix.sync.aligned.m8n8.x4.shared.b16 {%0,%1,%2,%3}, [%4];"
        : "=r"(r[0]), "=r"(r[1]), "=r"(r[2]), "=r"(r[3]) : "r"(addr));
}
__device__ __forceinline__ void ldsm4t(uint32_t r[4], uint32_t addr) {
    asm volatile("ldmatrix.sync.aligned.m8n8.x4.trans.shared.b16 {%0,%1,%2,%3}, [%4];"
        : "=r"(r[0]), "=r"(r[1]), "=r"(r[2]), "=r"(r[3]) : "r"(addr));
}
__device__ __forceinline__ void mma16816(float c[4], const uint32_t a[4],
                                         const uint32_t b[2]) {
    asm volatile(
        "mma.sync.aligned.m16n8k16.row.col.f32.bf16.bf16.f32 "
        "{%0,%1,%2,%3}, {%4,%5,%6,%7}, {%8,%9}, {%0,%1,%2,%3};"
        : "+f"(c[0]), "+f"(c[1]), "+f"(c[2]), "+f"(c[3])
        : "r"(a[0]), "r"(a[1]), "r"(a[2]), "r"(a[3]), "r"(b[0]), "r"(b[1]));
}
__device__ __forceinline__ void cp16(uint32_t dst, const void* src) {
    asm volatile("cp.async.cg.shared.global [%0], [%1], 16;" :: "r"(dst), "l"(src));
}
#define CP_COMMIT() asm volatile("cp.async.commit_group;" ::: "memory")
template <int N>
__device__ __forceinline__ void cp_wait() {
    asm volatile("cp.async.wait_group %0;" :: "n"(N) : "memory");
}

// pack two floats into bf16x2 (lo = a, hi = b) + residual bf16x2
__device__ __forceinline__ void pack_split(float a, float b, uint32_t& hi, uint32_t& lo) {
    asm("cvt.rn.bf16x2.f32 %0, %1, %2;" : "=r"(hi) : "f"(b), "f"(a));
    float ha = __uint_as_float(hi << 16);
    float hb = __uint_as_float(hi & 0xffff0000u);
    float ra = a - ha, rb = b - hb;
    asm("cvt.rn.bf16x2.f32 %0, %1, %2;" : "=r"(lo) : "f"(rb), "f"(ra));
}

// ===========================================================================
// Problem constants
// ===========================================================================
#define BATCH   4
#define S_LEN   2048
#define EMB     1024
#define NHEAD   16
#define DHEAD   64
#define MROWS   (BATCH * S_LEN)   // 8192

// Scratch (device globals — allocations forbidden)
__device__ __nv_bfloat16 g_Aqhi[MROWS * EMB];
__device__ __nv_bfloat16 g_Aqlo[MROWS * EMB];
__device__ __nv_bfloat16 g_Akhi[MROWS * EMB];
__device__ __nv_bfloat16 g_Aklo[MROWS * EMB];
__device__ __nv_bfloat16 g_Avhi[MROWS * EMB];
__device__ __nv_bfloat16 g_Avlo[MROWS * EMB];
__device__ __nv_bfloat16 g_Bqhi[EMB * EMB];
__device__ __nv_bfloat16 g_Bqlo[EMB * EMB];
__device__ __nv_bfloat16 g_Bkhi[EMB * EMB];
__device__ __nv_bfloat16 g_Bklo[EMB * EMB];
__device__ __nv_bfloat16 g_Bvhi[EMB * EMB];
__device__ __nv_bfloat16 g_Bvlo[EMB * EMB];
__device__ __nv_bfloat16 g_Bohi[EMB * EMB];
__device__ __nv_bfloat16 g_Bolo[EMB * EMB];
__device__ __nv_bfloat16 g_Qhi[MROWS * EMB];
__device__ __nv_bfloat16 g_Qlo[MROWS * EMB];
__device__ __nv_bfloat16 g_Khi[MROWS * EMB];
__device__ __nv_bfloat16 g_Klo[MROWS * EMB];
__device__ __nv_bfloat16 g_Vhi[MROWS * EMB];
__device__ __nv_bfloat16 g_Vlo[MROWS * EMB];
__device__ __nv_bfloat16 g_Chi[MROWS * EMB];
__device__ __nv_bfloat16 g_Clo[MROWS * EMB];
__device__ int g_idx[BATCH * S_LEN];
__device__ int g_cnt[BATCH];

// ===========================================================================
// Stable mask compaction
// ===========================================================================
__global__ __launch_bounds__(1024) void mask_compact_kernel(
    const int* __restrict__ mask, int* __restrict__ idx, int* __restrict__ cnt)
{
    const int b = blockIdx.x, t = threadIdx.x;
    const int wid = t >> 5, lane = t & 31;
    __shared__ int wsum[32], woff[32], chunk_total;
    int base = 0;
    #pragma unroll
    for (int half = 0; half < 2; half++) {
        int e = half * 1024 + t;
        int m = mask[b * S_LEN + e];
        unsigned bal = __ballot_sync(0xffffffffu, m != 0);
        int wtot = __popc(bal);
        int pos  = __popc(bal & ((1u << lane) - 1u));
        if (lane == 0) wsum[wid] = wtot;
        __syncthreads();
        if (t < 32) {
            int v = wsum[t], s = v;
            #pragma unroll
            for (int o = 1; o < 32; o <<= 1) {
                int u = __shfl_up_sync(0xffffffffu, s, o);
                if (t >= o) s += u;
            }
            woff[t] = s - v;
            if (t == 31) chunk_total = s;
        }
        __syncthreads();
        if (m) idx[b * S_LEN + base + woff[wid] + pos] = e;
        base += chunk_total;
        __syncthreads();
    }
    if (t == 0) cnt[b] = base;
}

// ===========================================================================
// Merged input conversion: z=0 dense q, z=1 gather k, z=2 gather v
// ===========================================================================
__global__ __launch_bounds__(256) void cvt_inputs_kernel(
    const float* __restrict__ q, const float* __restrict__ k,
    const float* __restrict__ v,
    const int* __restrict__ idx, const int* __restrict__ cnt,
    __nv_bfloat16* __restrict__ qh, __nv_bfloat16* __restrict__ ql,
    __nv_bfloat16* __restrict__ kh, __nv_bfloat16* __restrict__ kl,
    __nv_bfloat16* __restrict__ vh, __nv_bfloat16* __restrict__ vl)
{
    const int z = blockIdx.z;
    const float* src = (z == 0) ? q : ((z == 1) ? k : v);
    __nv_bfloat16* H = (z == 0) ? qh : ((z == 1) ? kh : vh);
    __nv_bfloat16* L = (z == 0) ? ql : ((z == 1) ? kl : vl);
    int i = blockIdx.x * blockDim.x + threadIdx.x;   // float4 id
    if (z == 0) {
        float4 x = ((const float4*)src)[i];
        uint2 hh, ll;
        pack_split(x.x, x.y, hh.x, ll.x);
        pack_split(x.z, x.w, hh.y, ll.y);
        ((uint2*)H)[i] = hh;
        ((uint2*)L)[i] = ll;
    } else {
        int rowq = i >> 8;
        int c4 = i & 255;
        int b = rowq >> 11, r = rowq & 2047;
        uint2 hh = make_uint2(0u, 0u), ll = make_uint2(0u, 0u);
        if (r < cnt[b]) {
            int s = idx[b * S_LEN + r];
            float4 x = ((const float4*)(src + ((size_t)(b * S_LEN + s)) * EMB))[c4];
            pack_split(x.x, x.y, hh.x, ll.x);
            pack_split(x.z, x.w, hh.y, ll.y);
        }
        ((uint2*)H)[(size_t)rowq * 256 + c4] = hh;
        ((uint2*)L)[(size_t)rowq * 256 + c4] = ll;
    }
}

// ===========================================================================
// Merged weight conversion: z selects one of 4 weight matrices
// ===========================================================================
struct WJobs {
    const float* s[4];
    __nv_bfloat16* h[4];
    __nv_bfloat16* l[4];
};

__global__ __launch_bounds__(256) void cvt_weights_kernel(WJobs wj)
{
    const int z = blockIdx.z;
    int i = blockIdx.x * blockDim.x + threadIdx.x;
    float4 x = ((const float4*)wj.s[z])[i];
    uint2 hh, ll;
    pack_split(x.x, x.y, hh.x, ll.x);
    pack_split(x.z, x.w, hh.y, ll.y);
    ((uint2*)wj.h[z])[i] = hh;
    ((uint2*)wj.l[z])[i] = ll;
}

// ===========================================================================
// Persistent multi-job split-bf16 3-term GEMM via mma.sync.
// Each job: C[8192,1024] = A*B^T, 128x128 tiles (512 per job), up to 3 jobs.
// 256 threads / 8 warps, warp tile 64x32, 3-stage cp.async, term-major MMAs.
// ===========================================================================
#define CHUNKS 16
#define STG_BYTES 65536
#define NSTAGE 3
#define GSMEM (NSTAGE * STG_BYTES)

struct GJob {
    const __nv_bfloat16 *Ahi, *Alo, *Bhi, *Blo;
    __nv_bfloat16 *Chi, *Clo;
    float* Cf;
    const float* bias;
    const int* cnt;
};
struct GJobs { GJob j[3]; int n; };

__global__ __launch_bounds__(256, 1) void gemm3p_kernel(GJobs jobs)
{
    extern __shared__ __align__(1024) char smem[];
    const uint32_t sb = smem_u32_of(smem);
    const int t = threadIdx.x;
    const int w = t >> 5, lane = t & 31;
    const int wm = (w >> 2) * 64;
    const int wn = (w & 3) * 32;

    // loader mapping: 4 x 16B per thread per 16KB array
    uint32_t lsw[4]; uint32_t lgo[4];
    #pragma unroll
    for (int i = 0; i < 4; i++) {
        int u = t + 256 * i;
        int row = u >> 3, ku = u & 7;
        uint32_t off = row * 128 + ku * 16;
        lsw[i] = off ^ ((off >> 3) & 0x70);
        lgo[i] = (uint32_t)row * EMB + ku * 8;
    }

    // ldmatrix base offsets
    const uint32_t xr  = (lane & 7) << 4;
    const uint32_t ak0 = (uint32_t)(lane & 16) ^ xr;
    const int      arow = lane & 15;
    const uint32_t bk0 = (uint32_t)((lane & 8) << 1) ^ xr;
    const int      brow = (lane & 7) | ((lane & 16) >> 1);
    uint32_t baA[4], baB[2];
    #pragma unroll
    for (int mi = 0; mi < 4; mi++)
        baA[mi] = (uint32_t)(wm + mi * 16 + arow) * 128 + ak0;
    #pragma unroll
    for (int nt = 0; nt < 2; nt++)
        baB[nt] = 32768u + (uint32_t)(wn + nt * 16 + brow) * 128 + bk0;

    const int total = jobs.n << 9;
    for (int tile = blockIdx.x; tile < total; tile += gridDim.x) {
        const GJob J = jobs.j[tile >> 9];
        const int within = tile & 511;
        const int bm = (within >> 3) * 128;
        const int bn = (within & 7) * 128;
        if (J.cnt && (bm & 2047) >= J.cnt[bm >> 11]) continue;

        const __nv_bfloat16* gAhi = J.Ahi + (size_t)bm * EMB;
        const __nv_bfloat16* gAlo = J.Alo + (size_t)bm * EMB;
        const __nv_bfloat16* gBhi = J.Bhi + (size_t)bn * EMB;
        const __nv_bfloat16* gBlo = J.Blo + (size_t)bn * EMB;

        float acc[4][4][4];
        #pragma unroll
        for (int mi = 0; mi < 4; mi++)
            #pragma unroll
            for (int ni = 0; ni < 4; ni++)
                #pragma unroll
                for (int r = 0; r < 4; r++) acc[mi][ni][r] = 0.0f;

        auto load_chunk = [&](int c) {
            const uint32_t so = sb + (uint32_t)(c % NSTAGE) * STG_BYTES;
            const uint32_t ko = (uint32_t)c * 64;
            #pragma unroll
            for (int i = 0; i < 4; i++) {
                cp16(so +      0 + lsw[i], gAhi + lgo[i] + ko);
                cp16(so + 16384u + lsw[i], gAlo + lgo[i] + ko);
                cp16(so + 32768u + lsw[i], gBhi + lgo[i] + ko);
                cp16(so + 49152u + lsw[i], gBlo + lgo[i] + ko);
            }
            CP_COMMIT();
        };

        // barrier: previous tile's last compute must finish before we
        // overwrite stages for this tile
        __syncthreads();

        load_chunk(0);
        load_chunk(1);

        for (int c = 0; c < CHUNKS; c++) {
            if (c + 1 < CHUNKS) { cp_wait<1>(); } else { cp_wait<0>(); }
            __syncthreads();
            if (c + 2 < CHUNKS) load_chunk(c + 2);

            const uint32_t so = sb + (uint32_t)(c % NSTAGE) * STG_BYTES;
            #pragma unroll
            for (int ks = 0; ks < 4; ks++) {
                const uint32_t kx = (uint32_t)ks << 5;
                uint32_t ah[4][4], al[4][4], bh[2][4], bl[2][4];
                #pragma unroll
                for (int mi = 0; mi < 4; mi++) {
                    ldsm4(ah[mi], so + (baA[mi] ^ kx));
                    ldsm4(al[mi], so + 16384u + (baA[mi] ^ kx));
                }
                #pragma unroll
                for (int nt = 0; nt < 2; nt++) {
                    ldsm4(bh[nt], so + (baB[nt] ^ kx));
                    ldsm4(bl[nt], so + 16384u + (baB[nt] ^ kx));
                }
                // term-major: 16 independent accumulators per sweep
                #pragma unroll
                for (int mi = 0; mi < 4; mi++)
                    #pragma unroll
                    for (int ni = 0; ni < 4; ni++)
                        mma16816(acc[mi][ni], ah[mi], &bh[ni >> 1][(ni & 1) * 2]);
                #pragma unroll
                for (int mi = 0; mi < 4; mi++)
                    #pragma unroll
                    for (int ni = 0; ni < 4; ni++)
                        mma16816(acc[mi][ni], al[mi], &bh[ni >> 1][(ni & 1) * 2]);
                #pragma unroll
                for (int mi = 0; mi < 4; mi++)
                    #pragma unroll
                    for (int ni = 0; ni < 4; ni++)
                        mma16816(acc[mi][ni], ah[mi], &bl[ni >> 1][(ni & 1) * 2]);
            }
        }

        // ---- epilogue (registers + gmem only; no smem) ----
        #pragma unroll
        for (int mi = 0; mi < 4; mi++) {
            #pragma unroll
            for (int ni = 0; ni < 4; ni++) {
                int row = bm + wm + mi * 16 + (lane >> 2);
                int col = bn + wn + ni * 8 + (lane & 3) * 2;
                if (J.Cf) {
                    float2 v0 = make_float2(acc[mi][ni][0], acc[mi][ni][1]);
                    float2 v1 = make_float2(acc[mi][ni][2], acc[mi][ni][3]);
                    float b0 = __ldg(J.bias + col), b1 = __ldg(J.bias + col + 1);
                    v0.x += b0; v0.y += b1; v1.x += b0; v1.y += b1;
                    *(float2*)&J.Cf[(size_t)row * EMB + col] = v0;
                    *(float2*)&J.Cf[(size_t)(row + 8) * EMB + col] = v1;
                } else {
                    uint32_t hi, lo;
                    pack_split(acc[mi][ni][0], acc[mi][ni][1], hi, lo);
                    *(uint32_t*)&J.Chi[(size_t)row * EMB + col] = hi;
                    *(uint32_t*)&J.Clo[(size_t)row * EMB + col] = lo;
                    pack_split(acc[mi][ni][2], acc[mi][ni][3], hi, lo);
                    *(uint32_t*)&J.Chi[(size_t)(row + 8) * EMB + col] = hi;
                    *(uint32_t*)&J.Clo[(size_t)(row + 8) * EMB + col] = lo;
                }
            }
        }
    }
}

// ===========================================================================
// Tensor-core flash attention over compacted keys (unchanged, proven).
// ===========================================================================
#define ASTG 32768
#define ANST 3
#define ASMEM (ANST * ASTG)

__global__ __launch_bounds__(256, 1) void attn_mma_kernel(
    const __nv_bfloat16* __restrict__ Qhi, const __nv_bfloat16* __restrict__ Qlo,
    const __nv_bfloat16* __restrict__ Khi, const __nv_bfloat16* __restrict__ Klo,
    const __nv_bfloat16* __restrict__ Vhi, const __nv_bfloat16* __restrict__ Vlo,
    const int* __restrict__ cnt,
    __nv_bfloat16* __restrict__ Chi, __nv_bfloat16* __restrict__ Clo)
{
    extern __shared__ __align__(1024) char smem[];
    const uint32_t sb = smem_u32_of(smem);
    const int t = threadIdx.x, w = t >> 5, lane = t & 31;
    const int qt = blockIdx.x, bh = blockIdx.y;
    const int b = bh >> 4, h = bh & 15;
    const int q0 = qt * 128;
    const int hcol = h * 64;
    const int n = cnt[b];
    const int ntiles = (n + 63) >> 6;

    {
        const size_t qbase = ((size_t)(b * S_LEN + q0)) * EMB + hcol;
        #pragma unroll
        for (int i = 0; i < 8; i++) {
            int u = t + 256 * i;
            int arr = u >> 10;
            int r = (u >> 3) & 127;
            int du = u & 7;
            uint32_t off = r * 128 + du * 16;
            uint32_t sw = off ^ ((off >> 3) & 0x70);
            const __nv_bfloat16* src = (arr ? Qlo : Qhi) + qbase + (size_t)r * EMB + du * 8;
            cp16(sb + (uint32_t)arr * 16384u + sw, src);
        }
        CP_COMMIT();
    }
    cp_wait<0>();
    __syncthreads();

    uint32_t qh[4][4], ql[4][4];
    {
        uint32_t off = (uint32_t)(w * 16 + (lane & 15)) * 128 + ((lane >> 4) * 16);
        uint32_t baQ = off ^ ((off >> 3) & 0x70);
        #pragma unroll
        for (int k16 = 0; k16 < 4; k16++) {
            ldsm4(qh[k16], sb + (baQ ^ (uint32_t)(k16 * 32)));
            ldsm4(ql[k16], sb + 16384u + (baQ ^ (uint32_t)(k16 * 32)));
        }
    }
    __syncthreads();

    uint32_t baK, baV;
    {
        uint32_t keyk = (uint32_t)((lane & 7) | ((lane & 16) >> 1));
        uint32_t offk = keyk * 128 + (uint32_t)((lane & 8) << 1);
        baK = offk ^ ((offk >> 3) & 0x70);
        uint32_t keyv = (uint32_t)(lane & 15);
        uint32_t offv = keyv * 128 + (uint32_t)((lane >> 4) * 16);
        baV = offv ^ ((offv >> 3) & 0x70);
    }

    auto load_tile = [&](int kt, int stg) {
        const size_t gk = ((size_t)(b * S_LEN + kt * 64)) * EMB + hcol;
        const uint32_t sdst = sb + (uint32_t)stg * ASTG;
        #pragma unroll
        for (int i = 0; i < 8; i++) {
            int u = t + 256 * i;
            int arr = u >> 9;
            int r = (u >> 3) & 63;
            int du = u & 7;
            uint32_t off = r * 128 + du * 16;
            uint32_t sw = off ^ ((off >> 3) & 0x70);
            const __nv_bfloat16* p =
                (arr < 2) ? (arr ? Klo : Khi) : ((arr == 2) ? Vhi : Vlo);
            cp16(sdst + (uint32_t)arr * 8192u + sw, p + gk + (size_t)r * EMB + du * 8);
        }
        CP_COMMIT();
    };

    float O[8][4];
    #pragma unroll
    for (int j = 0; j < 8; j++)
        #pragma unroll
        for (int r = 0; r < 4; r++) O[j][r] = 0.0f;
    float m0 = -1e30f, m1 = -1e30f, l0 = 0.0f, l1 = 0.0f;

    if (ntiles == 0) {
        size_t row0 = (size_t)(b * S_LEN + q0 + w * 16 + (lane >> 2));
        #pragma unroll
        for (int j = 0; j < 8; j++) {
            int col = hcol + j * 8 + (lane & 3) * 2;
            *(uint32_t*)&Chi[row0 * EMB + col] = 0u;
            *(uint32_t*)&Clo[row0 * EMB + col] = 0u;
            *(uint32_t*)&Chi[(row0 + 8) * EMB + col] = 0u;
            *(uint32_t*)&Clo[(row0 + 8) * EMB + col] = 0u;
        }
        return;
    }

    load_tile(0, 0);
    if (ntiles > 1) load_tile(1, 1);

    for (int kt = 0; kt < ntiles; kt++) {
        if (kt + 1 < ntiles) { cp_wait<1>(); } else { cp_wait<0>(); }
        __syncthreads();
        if (kt + 2 < ntiles) load_tile(kt + 2, (kt + 2) % ANST);

        const uint32_t so = sb + (uint32_t)(kt % ANST) * ASTG;

        float sc[8][4];
        #pragma unroll
        for (int j = 0; j < 8; j++)
            #pragma unroll
            for (int r = 0; r < 4; r++) sc[j][r] = 0.0f;

        #pragma unroll
        for (int k16 = 0; k16 < 4; k16++) {
            const uint32_t kx = (uint32_t)(k16 * 32);
            uint32_t kh[4][4], kl[4][4];
            #pragma unroll
            for (int np = 0; np < 4; np++) {
                ldsm4(kh[np], so + ((baK + (uint32_t)np * 2048u) ^ kx));
                ldsm4(kl[np], so + 8192u + ((baK + (uint32_t)np * 2048u) ^ kx));
            }
            #pragma unroll
            for (int np = 0; np < 4; np++) {
                mma16816(sc[2 * np],     qh[k16], &kh[np][0]);
                mma16816(sc[2 * np + 1], qh[k16], &kh[np][2]);
            }
            #pragma unroll
            for (int np = 0; np < 4; np++) {
                mma16816(sc[2 * np],     ql[k16], &kh[np][0]);
                mma16816(sc[2 * np + 1], ql[k16], &kh[np][2]);
            }
            #pragma unroll
            for (int np = 0; np < 4; np++) {
                mma16816(sc[2 * np],     qh[k16], &kl[np][0]);
                mma16816(sc[2 * np + 1], qh[k16], &kl[np][2]);
            }
        }

        const int c0 = (lane & 3) * 2;
        const int limit = n - kt * 64;
        float rm0 = m0, rm1 = m1;
        #pragma unroll
        for (int j = 0; j < 8; j++) {
            int kc = j * 8 + c0;
            bool v0 = kc < limit, v1 = kc + 1 < limit;
            sc[j][0] = v0 ? sc[j][0] * 0.125f : -1e10f;
            sc[j][1] = v1 ? sc[j][1] * 0.125f : -1e10f;
            sc[j][2] = v0 ? sc[j][2] * 0.125f : -1e10f;
            sc[j][3] = v1 ? sc[j][3] * 0.125f : -1e10f;
            rm0 = fmaxf(rm0, fmaxf(sc[j][0], sc[j][1]));
            rm1 = fmaxf(rm1, fmaxf(sc[j][2], sc[j][3]));
        }
        rm0 = fmaxf(rm0, __shfl_xor_sync(0xffffffffu, rm0, 1));
        rm0 = fmaxf(rm0, __shfl_xor_sync(0xffffffffu, rm0, 2));
        rm1 = fmaxf(rm1, __shfl_xor_sync(0xffffffffu, rm1, 1));
        rm1 = fmaxf(rm1, __shfl_xor_sync(0xffffffffu, rm1, 2));
        float corr0 = __expf(m0 - rm0);
        float corr1 = __expf(m1 - rm1);
        m0 = rm0; m1 = rm1;
        float ls0 = 0.0f, ls1 = 0.0f;
        #pragma unroll
        for (int j = 0; j < 8; j++) {
            sc[j][0] = __expf(sc[j][0] - m0);
            sc[j][1] = __expf(sc[j][1] - m0);
            sc[j][2] = __expf(sc[j][2] - m1);
            sc[j][3] = __expf(sc[j][3] - m1);
            ls0 += sc[j][0] + sc[j][1];
            ls1 += sc[j][2] + sc[j][3];
        }
        ls0 += __shfl_xor_sync(0xffffffffu, ls0, 1);
        ls0 += __shfl_xor_sync(0xffffffffu, ls0, 2);
        ls1 += __shfl_xor_sync(0xffffffffu, ls1, 1);
        ls1 += __shfl_xor_sync(0xffffffffu, ls1, 2);
        l0 = l0 * corr0 + ls0;
        l1 = l1 * corr1 + ls1;
        #pragma unroll
        for (int j = 0; j < 8; j++) {
            O[j][0] *= corr0; O[j][1] *= corr0;
            O[j][2] *= corr1; O[j][3] *= corr1;
        }

        uint32_t ph[4][4], pl[4][4];
        #pragma unroll
        for (int kb = 0; kb < 4; kb++) {
            pack_split(sc[2 * kb][0],     sc[2 * kb][1],     ph[kb][0], pl[kb][0]);
            pack_split(sc[2 * kb][2],     sc[2 * kb][3],     ph[kb][1], pl[kb][1]);
            pack_split(sc[2 * kb + 1][0], sc[2 * kb + 1][1], ph[kb][2], pl[kb][2]);
            pack_split(sc[2 * kb + 1][2], sc[2 * kb + 1][3], ph[kb][3], pl[kb][3]);
        }

        #pragma unroll
        for (int kb = 0; kb < 4; kb++) {
            const uint32_t kadd = (uint32_t)kb * 2048u;
            uint32_t vh[4][4], vl[4][4];
            #pragma unroll
            for (int dp = 0; dp < 4; dp++) {
                const uint32_t dx = (uint32_t)(dp * 32);
                ldsm4t(vh[dp], so + 16384u + ((baV + kadd) ^ dx));
                ldsm4t(vl[dp], so + 24576u + ((baV + kadd) ^ dx));
            }
            #pragma unroll
            for (int dp = 0; dp < 4; dp++) {
                mma16816(O[2 * dp],     ph[kb], &vh[dp][0]);
                mma16816(O[2 * dp + 1], ph[kb], &vh[dp][2]);
            }
            #pragma unroll
            for (int dp = 0; dp < 4; dp++) {
                mma16816(O[2 * dp],     pl[kb], &vh[dp][0]);
                mma16816(O[2 * dp + 1], pl[kb], &vh[dp][2]);
            }
            #pragma unroll
            for (int dp = 0; dp < 4; dp++) {
                mma16816(O[2 * dp],     ph[kb], &vl[dp][0]);
                mma16816(O[2 * dp + 1], ph[kb], &vl[dp][2]);
            }
        }
    }

    float inv0 = 1.0f / l0, inv1 = 1.0f / l1;
    size_t row0 = (size_t)(b * S_LEN + q0 + w * 16 + (lane >> 2));
    size_t row1 = row0 + 8;
    #pragma unroll
    for (int j = 0; j < 8; j++) {
        int col = hcol + j * 8 + (lane & 3) * 2;
        uint32_t hi, lo;
        pack_split(O[j][0] * inv0, O[j][1] * inv0, hi, lo);
        *(uint32_t*)&Chi[row0 * EMB + col] = hi;
        *(uint32_t*)&Clo[row0 * EMB + col] = lo;
        pack_split(O[j][2] * inv1, O[j][3] * inv1, hi, lo);
        *(uint32_t*)&Chi[row1 * EMB + col] = hi;
        *(uint32_t*)&Clo[row1 * EMB + col] = lo;
    }
}

// ===========================================================================
// Launch
// ===========================================================================
extern "C" void kernel_launch(void* const* d_in, const int* in_sizes, int n_in,
                              void* d_out, int out_size)
{
    const float* q    = (const float*)d_in[0];
    const float* k    = (const float*)d_in[1];
    const float* v    = (const float*)d_in[2];
    const int*   mask = (const int*)  d_in[3];
    const float* Wq   = (const float*)d_in[4];
    const float* Wk   = (const float*)d_in[5];
    const float* Wv   = (const float*)d_in[6];
    const float* Wo   = (const float*)d_in[7];
    const float* bo   = (const float*)d_in[8];
    float* out = (float*)d_out;

    __nv_bfloat16 *Aqhi, *Aqlo, *Akhi, *Aklo, *Avhi, *Avlo;
    __nv_bfloat16 *Bqhi, *Bqlo, *Bkhi, *Bklo, *Bvhi, *Bvlo, *Bohi, *Bolo;
    __nv_bfloat16 *Qhi, *Qlo, *Khi, *Klo, *Vhi, *Vlo, *Chi, *Clo;
    int *idx, *cnt;
    cudaGetSymbolAddress((void**)&Aqhi, g_Aqhi);
    cudaGetSymbolAddress((void**)&Aqlo, g_Aqlo);
    cudaGetSymbolAddress((void**)&Akhi, g_Akhi);
    cudaGetSymbolAddress((void**)&Aklo, g_Aklo);
    cudaGetSymbolAddress((void**)&Avhi, g_Avhi);
    cudaGetSymbolAddress((void**)&Avlo, g_Avlo);
    cudaGetSymbolAddress((void**)&Bqhi, g_Bqhi);
    cudaGetSymbolAddress((void**)&Bqlo, g_Bqlo);
    cudaGetSymbolAddress((void**)&Bkhi, g_Bkhi);
    cudaGetSymbolAddress((void**)&Bklo, g_Bklo);
    cudaGetSymbolAddress((void**)&Bvhi, g_Bvhi);
    cudaGetSymbolAddress((void**)&Bvlo, g_Bvlo);
    cudaGetSymbolAddress((void**)&Bohi, g_Bohi);
    cudaGetSymbolAddress((void**)&Bolo, g_Bolo);
    cudaGetSymbolAddress((void**)&Qhi, g_Qhi);
    cudaGetSymbolAddress((void**)&Qlo, g_Qlo);
    cudaGetSymbolAddress((void**)&Khi, g_Khi);
    cudaGetSymbolAddress((void**)&Klo, g_Klo);
    cudaGetSymbolAddress((void**)&Vhi, g_Vhi);
    cudaGetSymbolAddress((void**)&Vlo, g_Vlo);
    cudaGetSymbolAddress((void**)&Chi, g_Chi);
    cudaGetSymbolAddress((void**)&Clo, g_Clo);
    cudaGetSymbolAddress((void**)&idx, g_idx);
    cudaGetSymbolAddress((void**)&cnt, g_cnt);

    cudaFuncSetAttribute(gemm3p_kernel,
                         cudaFuncAttributeMaxDynamicSharedMemorySize, GSMEM);
    cudaFuncSetAttribute(attn_mma_kernel,
                         cudaFuncAttributeMaxDynamicSharedMemorySize, ASMEM);

    int sms = 148;
    {
        int dev = 0;
        cudaGetDevice(&dev);
        cudaDeviceGetAttribute(&sms, cudaDevAttrMultiProcessorCount, dev);
    }

    const int nA4 = MROWS * EMB / 4;   // 2M float4
    const int nW4 = EMB * EMB / 4;     // 256K float4

    // 1. mask compaction
    mask_compact_kernel<<<BATCH, 1024>>>(mask, idx, cnt);

    // 2. input conversions (q dense, k/v gathered) — one launch
    dim3 gIn(nA4 / 256, 1, 3);
    cvt_inputs_kernel<<<gIn, 256>>>(q, k, v, idx, cnt,
                                    Aqhi, Aqlo, Akhi, Aklo, Avhi, Avlo);

    // 3. all 4 weight conversions — one launch
    WJobs wj;
    wj.s[0] = Wq; wj.h[0] = Bqhi; wj.l[0] = Bqlo;
    wj.s[1] = Wk; wj.h[1] = Bkhi; wj.l[1] = Bklo;
    wj.s[2] = Wv; wj.h[2] = Bvhi; wj.l[2] = Bvlo;
    wj.s[3] = Wo; wj.h[3] = Bohi; wj.l[3] = Bolo;
    dim3 gW(nW4 / 256, 1, 4);
    cvt_weights_kernel<<<gW, 256>>>(wj);

    // 4. merged persistent Q/K/V projections
    GJobs gj;
    gj.j[0].Ahi = Aqhi; gj.j[0].Alo = Aqlo; gj.j[0].Bhi = Bqhi; gj.j[0].Blo = Bqlo;
    gj.j[0].Chi = Qhi;  gj.j[0].Clo = Qlo;  gj.j[0].Cf = nullptr;
    gj.j[0].bias = nullptr; gj.j[0].cnt = nullptr;
    gj.j[1].Ahi = Akhi; gj.j[1].Alo = Aklo; gj.j[1].Bhi = Bkhi; gj.j[1].Blo = Bklo;
    gj.j[1].Chi = Khi;  gj.j[1].Clo = Klo;  gj.j[1].Cf = nullptr;
    gj.j[1].bias = nullptr; gj.j[1].cnt = cnt;
    gj.j[2].Ahi = Avhi; gj.j[2].Alo = Avlo; gj.j[2].Bhi = Bvhi; gj.j[2].Blo = Bvlo;
    gj.j[2].Chi = Vhi;  gj.j[2].Clo = Vlo;  gj.j[2].Cf = nullptr;
    gj.j[2].bias = nullptr; gj.j[2].cnt = cnt;
    gj.n = 3;
    gemm3p_kernel<<<sms, 256, GSMEM>>>(gj);

    // 5. attention over compacted keys
    dim3 gAttn(S_LEN / 128, BATCH * NHEAD);   // (16, 64)
    attn_mma_kernel<<<gAttn, 256, ASMEM>>>(Qhi, Qlo, Khi, Klo, Vhi, Vlo, cnt, Chi, Clo);

    // 6. persistent output projection (+bias)
    GJobs go;
    go.j[0].Ahi = Chi; go.j[0].Alo = Clo; go.j[0].Bhi = Bohi; go.j[0].Blo = Bolo;
    go.j[0].Chi = nullptr; go.j[0].Clo = nullptr; go.j[0].Cf = out;
    go.j[0].bias = bo; go.j[0].cnt = nullptr;
    go.n = 1;
    gemm3p_kernel<<<sms, 256, GSMEM>>>(go);
}

// round 8
// speedup vs baseline: 1.0045x; 1.0045x over previous
#include <cuda_runtime.h>
#include <cuda_bf16.h>
#include <cstdint>

typedef unsigned long long ull;

// ===========================================================================
// mma.sync / ldmatrix / cp.async helpers (base sm_103 target — no tcgen05)
// ===========================================================================
__device__ __forceinline__ uint32_t smem_u32_of(const void* p) {
    uint32_t a;
    asm("{ .reg .u64 t; cvta.to.shared.u64 t, %1; cvt.u32.u64 %0, t; }"
        : "=r"(a) : "l"(p));
    return a;
}
__device__ __forceinline__ void ldsm4(uint32_t r[4], uint32_t addr) {
    asm volatile("ldmatrix.sync.aligned.m8n8.x4.shared.b16 {%0,%1,%2,%3}, [%4];"
        : "=r"(r[0]), "=r"(r[1]), "=r"(r[2]), "=r"(r[3]) : "r"(addr));
}
__device__ __forceinline__ void ldsm4t(uint32_t r[4], uint32_t addr) {
    asm volatile("ldmatrix.sync.aligned.m8n8.x4.trans.shared.b16 {%0,%1,%2,%3}, [%4];"
        : "=r"(r[0]), "=r"(r[1]), "=r"(r[2]), "=r"(r[3]) : "r"(addr));
}
__device__ __forceinline__ void mma16816(float c[4], const uint32_t a[4],
                                         const uint32_t b[2]) {
    asm volatile(
        "mma.sync.aligned.m16n8k16.row.col.f32.bf16.bf16.f32 "
        "{%0,%1,%2,%3}, {%4,%5,%6,%7}, {%8,%9}, {%0,%1,%2,%3};"
        : "+f"(c[0]), "+f"(c[1]), "+f"(c[2]), "+f"(c[3])
        : "r"(a[0]), "r"(a[1]), "r"(a[2]), "r"(a[3]), "r"(b[0]), "r"(b[1]));
}
__device__ __forceinline__ void cp16(uint32_t dst, const void* src) {
    asm volatile("cp.async.cg.shared.global [%0], [%1], 16;" :: "r"(dst), "l"(src));
}
#define CP_COMMIT() asm volatile("cp.async.commit_group;" ::: "memory")
template <int N>
__device__ __forceinline__ void cp_wait() {
    asm volatile("cp.async.wait_group %0;" :: "n"(N) : "memory");
}

// pack two floats into bf16x2 (lo = a, hi = b) + residual bf16x2
__device__ __forceinline__ void pack_split(float a, float b, uint32_t& hi, uint32_t& lo) {
    asm("cvt.rn.bf16x2.f32 %0, %1, %2;" : "=r"(hi) : "f"(b), "f"(a));
    float ha = __uint_as_float(hi << 16);
    float hb = __uint_as_float(hi & 0xffff0000u);
    float ra = a - ha, rb = b - hb;
    asm("cvt.rn.bf16x2.f32 %0, %1, %2;" : "=r"(lo) : "f"(rb), "f"(ra));
}

// ===========================================================================
// Problem constants
// ===========================================================================
#define BATCH   4
#define S_LEN   2048
#define EMB     1024
#define NHEAD   16
#define DHEAD   64
#define MROWS   (BATCH * S_LEN)   // 8192

// Scratch (device globals — allocations forbidden)
__device__ __nv_bfloat16 g_Aqhi[MROWS * EMB];
__device__ __nv_bfloat16 g_Aqlo[MROWS * EMB];
__device__ __nv_bfloat16 g_Akhi[MROWS * EMB];
__device__ __nv_bfloat16 g_Aklo[MROWS * EMB];
__device__ __nv_bfloat16 g_Avhi[MROWS * EMB];
__device__ __nv_bfloat16 g_Avlo[MROWS * EMB];
__device__ __nv_bfloat16 g_Bqhi[EMB * EMB];
__device__ __nv_bfloat16 g_Bqlo[EMB * EMB];
__device__ __nv_bfloat16 g_Bkhi[EMB * EMB];
__device__ __nv_bfloat16 g_Bklo[EMB * EMB];
__device__ __nv_bfloat16 g_Bvhi[EMB * EMB];
__device__ __nv_bfloat16 g_Bvlo[EMB * EMB];
__device__ __nv_bfloat16 g_Bohi[EMB * EMB];
__device__ __nv_bfloat16 g_Bolo[EMB * EMB];
__device__ __nv_bfloat16 g_Qhi[MROWS * EMB];
__device__ __nv_bfloat16 g_Qlo[MROWS * EMB];
__device__ __nv_bfloat16 g_Khi[MROWS * EMB];
__device__ __nv_bfloat16 g_Klo[MROWS * EMB];
__device__ __nv_bfloat16 g_Vhi[MROWS * EMB];
__device__ __nv_bfloat16 g_Vlo[MROWS * EMB];
__device__ __nv_bfloat16 g_Chi[MROWS * EMB];
__device__ __nv_bfloat16 g_Clo[MROWS * EMB];
__device__ int g_idx[BATCH * S_LEN];
__device__ int g_cnt[BATCH];

// ===========================================================================
// Stable mask compaction
// ===========================================================================
__global__ __launch_bounds__(1024) void mask_compact_kernel(
    const int* __restrict__ mask, int* __restrict__ idx, int* __restrict__ cnt)
{
    const int b = blockIdx.x, t = threadIdx.x;
    const int wid = t >> 5, lane = t & 31;
    __shared__ int wsum[32], woff[32], chunk_total;
    int base = 0;
    #pragma unroll
    for (int half = 0; half < 2; half++) {
        int e = half * 1024 + t;
        int m = mask[b * S_LEN + e];
        unsigned bal = __ballot_sync(0xffffffffu, m != 0);
        int wtot = __popc(bal);
        int pos  = __popc(bal & ((1u << lane) - 1u));
        if (lane == 0) wsum[wid] = wtot;
        __syncthreads();
        if (t < 32) {
            int v = wsum[t], s = v;
            #pragma unroll
            for (int o = 1; o < 32; o <<= 1) {
                int u = __shfl_up_sync(0xffffffffu, s, o);
                if (t >= o) s += u;
            }
            woff[t] = s - v;
            if (t == 31) chunk_total = s;
        }
        __syncthreads();
        if (m) idx[b * S_LEN + base + woff[wid] + pos] = e;
        base += chunk_total;
        __syncthreads();
    }
    if (t == 0) cnt[b] = base;
}

// ===========================================================================
// Merged input conversion: z=0 dense q, z=1 gather k, z=2 gather v
// ===========================================================================
__global__ __launch_bounds__(256) void cvt_inputs_kernel(
    const float* __restrict__ q, const float* __restrict__ k,
    const float* __restrict__ v,
    const int* __restrict__ idx, const int* __restrict__ cnt,
    __nv_bfloat16* __restrict__ qh, __nv_bfloat16* __restrict__ ql,
    __nv_bfloat16* __restrict__ kh, __nv_bfloat16* __restrict__ kl,
    __nv_bfloat16* __restrict__ vh, __nv_bfloat16* __restrict__ vl)
{
    const int z = blockIdx.z;
    const float* src = (z == 0) ? q : ((z == 1) ? k : v);
    __nv_bfloat16* H = (z == 0) ? qh : ((z == 1) ? kh : vh);
    __nv_bfloat16* L = (z == 0) ? ql : ((z == 1) ? kl : vl);
    int i = blockIdx.x * blockDim.x + threadIdx.x;
    if (z == 0) {
        float4 x = ((const float4*)src)[i];
        uint2 hh, ll;
        pack_split(x.x, x.y, hh.x, ll.x);
        pack_split(x.z, x.w, hh.y, ll.y);
        ((uint2*)H)[i] = hh;
        ((uint2*)L)[i] = ll;
    } else {
        int rowq = i >> 8;
        int c4 = i & 255;
        int b = rowq >> 11, r = rowq & 2047;
        uint2 hh = make_uint2(0u, 0u), ll = make_uint2(0u, 0u);
        if (r < cnt[b]) {
            int s = idx[b * S_LEN + r];
            float4 x = ((const float4*)(src + ((size_t)(b * S_LEN + s)) * EMB))[c4];
            pack_split(x.x, x.y, hh.x, ll.x);
            pack_split(x.z, x.w, hh.y, ll.y);
        }
        ((uint2*)H)[(size_t)rowq * 256 + c4] = hh;
        ((uint2*)L)[(size_t)rowq * 256 + c4] = ll;
    }
}

// ===========================================================================
// Merged weight conversion
// ===========================================================================
struct WJobs {
    const float* s[4];
    __nv_bfloat16* h[4];
    __nv_bfloat16* l[4];
};

__global__ __launch_bounds__(256) void cvt_weights_kernel(WJobs wj)
{
    const int z = blockIdx.z;
    int i = blockIdx.x * blockDim.x + threadIdx.x;
    float4 x = ((const float4*)wj.s[z])[i];
    uint2 hh, ll;
    pack_split(x.x, x.y, hh.x, ll.x);
    pack_split(x.z, x.w, hh.y, ll.y);
    ((uint2*)wj.h[z])[i] = hh;
    ((uint2*)wj.l[z])[i] = ll;
}

// ===========================================================================
// Persistent multi-job split-bf16 3-term GEMM, ks-level software pipeline:
// double-buffered fragment sets + cp.async spread across ks steps.
// ===========================================================================
#define CHUNKS 16
#define STG_BYTES 65536
#define NSTAGE 3
#define GSMEM (NSTAGE * STG_BYTES)

struct GJob {
    const __nv_bfloat16 *Ahi, *Alo, *Bhi, *Blo;
    __nv_bfloat16 *Chi, *Clo;
    float* Cf;
    const float* bias;
    const int* cnt;
};
struct GJobs { GJob j[3]; int n; };

struct Frags {
    uint32_t ah[4][4];
    uint32_t al[4][4];
    uint32_t bh[2][4];
    uint32_t bl[2][4];
};

__device__ __forceinline__ void load_frags(Frags& f, uint32_t so, uint32_t kx,
                                           const uint32_t baA[4], const uint32_t baB[2])
{
    #pragma unroll
    for (int mi = 0; mi < 4; mi++) {
        ldsm4(f.ah[mi], so + (baA[mi] ^ kx));
        ldsm4(f.al[mi], so + 16384u + (baA[mi] ^ kx));
    }
    #pragma unroll
    for (int nt = 0; nt < 2; nt++) {
        ldsm4(f.bh[nt], so + (baB[nt] ^ kx));
        ldsm4(f.bl[nt], so + 16384u + (baB[nt] ^ kx));
    }
}

__device__ __forceinline__ void sweeps(float acc[4][4][4], const Frags& f)
{
    #pragma unroll
    for (int mi = 0; mi < 4; mi++)
        #pragma unroll
        for (int ni = 0; ni < 4; ni++)
            mma16816(acc[mi][ni], f.ah[mi], &f.bh[ni >> 1][(ni & 1) * 2]);
    #pragma unroll
    for (int mi = 0; mi < 4; mi++)
        #pragma unroll
        for (int ni = 0; ni < 4; ni++)
            mma16816(acc[mi][ni], f.al[mi], &f.bh[ni >> 1][(ni & 1) * 2]);
    #pragma unroll
    for (int mi = 0; mi < 4; mi++)
        #pragma unroll
        for (int ni = 0; ni < 4; ni++)
            mma16816(acc[mi][ni], f.ah[mi], &f.bl[ni >> 1][(ni & 1) * 2]);
}

__global__ __launch_bounds__(256, 1) void gemm3p_kernel(GJobs jobs)
{
    extern __shared__ __align__(1024) char smem[];
    const uint32_t sb = smem_u32_of(smem);
    const int t = threadIdx.x;
    const int w = t >> 5, lane = t & 31;
    const int wm = (w >> 2) * 64;
    const int wn = (w & 3) * 32;

    uint32_t lsw[4]; uint32_t lgo[4];
    #pragma unroll
    for (int i = 0; i < 4; i++) {
        int u = t + 256 * i;
        int row = u >> 3, ku = u & 7;
        uint32_t off = row * 128 + ku * 16;
        lsw[i] = off ^ ((off >> 3) & 0x70);
        lgo[i] = (uint32_t)row * EMB + ku * 8;
    }

    const uint32_t xr  = (lane & 7) << 4;
    const uint32_t ak0 = (uint32_t)(lane & 16) ^ xr;
    const int      arow = lane & 15;
    const uint32_t bk0 = (uint32_t)((lane & 8) << 1) ^ xr;
    const int      brow = (lane & 7) | ((lane & 16) >> 1);
    uint32_t baA[4], baB[2];
    #pragma unroll
    for (int mi = 0; mi < 4; mi++)
        baA[mi] = (uint32_t)(wm + mi * 16 + arow) * 128 + ak0;
    #pragma unroll
    for (int nt = 0; nt < 2; nt++)
        baB[nt] = 32768u + (uint32_t)(wn + nt * 16 + brow) * 128 + bk0;

    const int total = jobs.n << 9;
    for (int tile = blockIdx.x; tile < total; tile += gridDim.x) {
        const GJob J = jobs.j[tile >> 9];
        const int within = tile & 511;
        const int bm = (within >> 3) * 128;
        const int bn = (within & 7) * 128;
        if (J.cnt && (bm & 2047) >= J.cnt[bm >> 11]) continue;

        const __nv_bfloat16* gAhi = J.Ahi + (size_t)bm * EMB;
        const __nv_bfloat16* gAlo = J.Alo + (size_t)bm * EMB;
        const __nv_bfloat16* gBhi = J.Bhi + (size_t)bn * EMB;
        const __nv_bfloat16* gBlo = J.Blo + (size_t)bn * EMB;

        float acc[4][4][4];
        #pragma unroll
        for (int mi = 0; mi < 4; mi++)
            #pragma unroll
            for (int ni = 0; ni < 4; ni++)
                #pragma unroll
                for (int r = 0; r < 4; r++) acc[mi][ni][r] = 0.0f;

        auto load_chunk = [&](int c) {
            const uint32_t so = sb + (uint32_t)(c % NSTAGE) * STG_BYTES;
            const uint32_t ko = (uint32_t)c * 64;
            #pragma unroll
            for (int i = 0; i < 4; i++) {
                cp16(so +      0 + lsw[i], gAhi + lgo[i] + ko);
                cp16(so + 16384u + lsw[i], gAlo + lgo[i] + ko);
                cp16(so + 32768u + lsw[i], gBhi + lgo[i] + ko);
                cp16(so + 49152u + lsw[i], gBlo + lgo[i] + ko);
            }
            CP_COMMIT();
        };
        // one quarter (4 cp16) of the chunk-(c) load, part i
        auto cp_part = [&](int c, int i) {
            if (c < CHUNKS) {
                const uint32_t so2 = sb + (uint32_t)(c % NSTAGE) * STG_BYTES;
                const uint32_t ko = (uint32_t)c * 64;
                cp16(so2 +      0 + lsw[i], gAhi + lgo[i] + ko);
                cp16(so2 + 16384u + lsw[i], gAlo + lgo[i] + ko);
                cp16(so2 + 32768u + lsw[i], gBhi + lgo[i] + ko);
                cp16(so2 + 49152u + lsw[i], gBlo + lgo[i] + ko);
            }
        };

        // barrier: previous tile's compute must finish before stage overwrite
        __syncthreads();
        load_chunk(0);
        load_chunk(1);

        Frags f0, f1;
        for (int c = 0; c < CHUNKS; c++) {
            if (c + 1 < CHUNKS) { cp_wait<1>(); } else { cp_wait<0>(); }
            __syncthreads();

            const uint32_t so = sb + (uint32_t)(c % NSTAGE) * STG_BYTES;

            // ks=0 frags (the one unavoidable LDSM block per chunk)
            load_frags(f0, so, 0u, baA, baB);
            // ks=0: prefetch ks=1 + cp part 0, then compute ks=0
            cp_part(c + 2, 0);
            load_frags(f1, so, 32u, baA, baB);
            sweeps(acc, f0);
            // ks=1: prefetch ks=2 + cp part 1, compute ks=1
            cp_part(c + 2, 1);
            load_frags(f0, so, 64u, baA, baB);
            sweeps(acc, f1);
            // ks=2: prefetch ks=3 + cp part 2, compute ks=2
            cp_part(c + 2, 2);
            load_frags(f1, so, 96u, baA, baB);
            sweeps(acc, f0);
            // ks=3: cp part 3, compute ks=3
            cp_part(c + 2, 3);
            sweeps(acc, f1);
            if (c + 2 < CHUNKS) CP_COMMIT();
        }

        // ---- epilogue ----
        #pragma unroll
        for (int mi = 0; mi < 4; mi++) {
            #pragma unroll
            for (int ni = 0; ni < 4; ni++) {
                int row = bm + wm + mi * 16 + (lane >> 2);
                int col = bn + wn + ni * 8 + (lane & 3) * 2;
                if (J.Cf) {
                    float2 v0 = make_float2(acc[mi][ni][0], acc[mi][ni][1]);
                    float2 v1 = make_float2(acc[mi][ni][2], acc[mi][ni][3]);
                    float b0 = __ldg(J.bias + col), b1 = __ldg(J.bias + col + 1);
                    v0.x += b0; v0.y += b1; v1.x += b0; v1.y += b1;
                    *(float2*)&J.Cf[(size_t)row * EMB + col] = v0;
                    *(float2*)&J.Cf[(size_t)(row + 8) * EMB + col] = v1;
                } else {
                    uint32_t hi, lo;
                    pack_split(acc[mi][ni][0], acc[mi][ni][1], hi, lo);
                    *(uint32_t*)&J.Chi[(size_t)row * EMB + col] = hi;
                    *(uint32_t*)&J.Clo[(size_t)row * EMB + col] = lo;
                    pack_split(acc[mi][ni][2], acc[mi][ni][3], hi, lo);
                    *(uint32_t*)&J.Chi[(size_t)(row + 8) * EMB + col] = hi;
                    *(uint32_t*)&J.Clo[(size_t)(row + 8) * EMB + col] = lo;
                }
            }
        }
    }
}

// ===========================================================================
// Tensor-core flash attention over compacted keys (unchanged, proven).
// ===========================================================================
#define ASTG 32768
#define ANST 3
#define ASMEM (ANST * ASTG)

__global__ __launch_bounds__(256, 1) void attn_mma_kernel(
    const __nv_bfloat16* __restrict__ Qhi, const __nv_bfloat16* __restrict__ Qlo,
    const __nv_bfloat16* __restrict__ Khi, const __nv_bfloat16* __restrict__ Klo,
    const __nv_bfloat16* __restrict__ Vhi, const __nv_bfloat16* __restrict__ Vlo,
    const int* __restrict__ cnt,
    __nv_bfloat16* __restrict__ Chi, __nv_bfloat16* __restrict__ Clo)
{
    extern __shared__ __align__(1024) char smem[];
    const uint32_t sb = smem_u32_of(smem);
    const int t = threadIdx.x, w = t >> 5, lane = t & 31;
    const int qt = blockIdx.x, bh = blockIdx.y;
    const int b = bh >> 4, h = bh & 15;
    const int q0 = qt * 128;
    const int hcol = h * 64;
    const int n = cnt[b];
    const int ntiles = (n + 63) >> 6;

    {
        const size_t qbase = ((size_t)(b * S_LEN + q0)) * EMB + hcol;
        #pragma unroll
        for (int i = 0; i < 8; i++) {
            int u = t + 256 * i;
            int arr = u >> 10;
            int r = (u >> 3) & 127;
            int du = u & 7;
            uint32_t off = r * 128 + du * 16;
            uint32_t sw = off ^ ((off >> 3) & 0x70);
            const __nv_bfloat16* src = (arr ? Qlo : Qhi) + qbase + (size_t)r * EMB + du * 8;
            cp16(sb + (uint32_t)arr * 16384u + sw, src);
        }
        CP_COMMIT();
    }
    cp_wait<0>();
    __syncthreads();

    uint32_t qh[4][4], ql[4][4];
    {
        uint32_t off = (uint32_t)(w * 16 + (lane & 15)) * 128 + ((lane >> 4) * 16);
        uint32_t baQ = off ^ ((off >> 3) & 0x70);
        #pragma unroll
        for (int k16 = 0; k16 < 4; k16++) {
            ldsm4(qh[k16], sb + (baQ ^ (uint32_t)(k16 * 32)));
            ldsm4(ql[k16], sb + 16384u + (baQ ^ (uint32_t)(k16 * 32)));
        }
    }
    __syncthreads();

    uint32_t baK, baV;
    {
        uint32_t keyk = (uint32_t)((lane & 7) | ((lane & 16) >> 1));
        uint32_t offk = keyk * 128 + (uint32_t)((lane & 8) << 1);
        baK = offk ^ ((offk >> 3) & 0x70);
        uint32_t keyv = (uint32_t)(lane & 15);
        uint32_t offv = keyv * 128 + (uint32_t)((lane >> 4) * 16);
        baV = offv ^ ((offv >> 3) & 0x70);
    }

    auto load_tile = [&](int kt, int stg) {
        const size_t gk = ((size_t)(b * S_LEN + kt * 64)) * EMB + hcol;
        const uint32_t sdst = sb + (uint32_t)stg * ASTG;
        #pragma unroll
        for (int i = 0; i < 8; i++) {
            int u = t + 256 * i;
            int arr = u >> 9;
            int r = (u >> 3) & 63;
            int du = u & 7;
            uint32_t off = r * 128 + du * 16;
            uint32_t sw = off ^ ((off >> 3) & 0x70);
            const __nv_bfloat16* p =
                (arr < 2) ? (arr ? Klo : Khi) : ((arr == 2) ? Vhi : Vlo);
            cp16(sdst + (uint32_t)arr * 8192u + sw, p + gk + (size_t)r * EMB + du * 8);
        }
        CP_COMMIT();
    };

    float O[8][4];
    #pragma unroll
    for (int j = 0; j < 8; j++)
        #pragma unroll
        for (int r = 0; r < 4; r++) O[j][r] = 0.0f;
    float m0 = -1e30f, m1 = -1e30f, l0 = 0.0f, l1 = 0.0f;

    if (ntiles == 0) {
        size_t row0 = (size_t)(b * S_LEN + q0 + w * 16 + (lane >> 2));
        #pragma unroll
        for (int j = 0; j < 8; j++) {
            int col = hcol + j * 8 + (lane & 3) * 2;
            *(uint32_t*)&Chi[row0 * EMB + col] = 0u;
            *(uint32_t*)&Clo[row0 * EMB + col] = 0u;
            *(uint32_t*)&Chi[(row0 + 8) * EMB + col] = 0u;
            *(uint32_t*)&Clo[(row0 + 8) * EMB + col] = 0u;
        }
        return;
    }

    load_tile(0, 0);
    if (ntiles > 1) load_tile(1, 1);

    for (int kt = 0; kt < ntiles; kt++) {
        if (kt + 1 < ntiles) { cp_wait<1>(); } else { cp_wait<0>(); }
        __syncthreads();
        if (kt + 2 < ntiles) load_tile(kt + 2, (kt + 2) % ANST);

        const uint32_t so = sb + (uint32_t)(kt % ANST) * ASTG;

        float sc[8][4];
        #pragma unroll
        for (int j = 0; j < 8; j++)
            #pragma unroll
            for (int r = 0; r < 4; r++) sc[j][r] = 0.0f;

        #pragma unroll
        for (int k16 = 0; k16 < 4; k16++) {
            const uint32_t kx = (uint32_t)(k16 * 32);
            uint32_t kh[4][4], kl[4][4];
            #pragma unroll
            for (int np = 0; np < 4; np++) {
                ldsm4(kh[np], so + ((baK + (uint32_t)np * 2048u) ^ kx));
                ldsm4(kl[np], so + 8192u + ((baK + (uint32_t)np * 2048u) ^ kx));
            }
            #pragma unroll
            for (int np = 0; np < 4; np++) {
                mma16816(sc[2 * np],     qh[k16], &kh[np][0]);
                mma16816(sc[2 * np + 1], qh[k16], &kh[np][2]);
            }
            #pragma unroll
            for (int np = 0; np < 4; np++) {
                mma16816(sc[2 * np],     ql[k16], &kh[np][0]);
                mma16816(sc[2 * np + 1], ql[k16], &kh[np][2]);
            }
            #pragma unroll
            for (int np = 0; np < 4; np++) {
                mma16816(sc[2 * np],     qh[k16], &kl[np][0]);
                mma16816(sc[2 * np + 1], qh[k16], &kl[np][2]);
            }
        }

        const int c0 = (lane & 3) * 2;
        const int limit = n - kt * 64;
        float rm0 = m0, rm1 = m1;
        #pragma unroll
        for (int j = 0; j < 8; j++) {
            int kc = j * 8 + c0;
            bool v0 = kc < limit, v1 = kc + 1 < limit;
            sc[j][0] = v0 ? sc[j][0] * 0.125f : -1e10f;
            sc[j][1] = v1 ? sc[j][1] * 0.125f : -1e10f;
            sc[j][2] = v0 ? sc[j][2] * 0.125f : -1e10f;
            sc[j][3] = v1 ? sc[j][3] * 0.125f : -1e10f;
            rm0 = fmaxf(rm0, fmaxf(sc[j][0], sc[j][1]));
            rm1 = fmaxf(rm1, fmaxf(sc[j][2], sc[j][3]));
        }
        rm0 = fmaxf(rm0, __shfl_xor_sync(0xffffffffu, rm0, 1));
        rm0 = fmaxf(rm0, __shfl_xor_sync(0xffffffffu, rm0, 2));
        rm1 = fmaxf(rm1, __shfl_xor_sync(0xffffffffu, rm1, 1));
        rm1 = fmaxf(rm1, __shfl_xor_sync(0xffffffffu, rm1, 2));
        float corr0 = __expf(m0 - rm0);
        float corr1 = __expf(m1 - rm1);
        m0 = rm0; m1 = rm1;
        float ls0 = 0.0f, ls1 = 0.0f;
        #pragma unroll
        for (int j = 0; j < 8; j++) {
            sc[j][0] = __expf(sc[j][0] - m0);
            sc[j][1] = __expf(sc[j][1] - m0);
            sc[j][2] = __expf(sc[j][2] - m1);
            sc[j][3] = __expf(sc[j][3] - m1);
            ls0 += sc[j][0] + sc[j][1];
            ls1 += sc[j][2] + sc[j][3];
        }
        ls0 += __shfl_xor_sync(0xffffffffu, ls0, 1);
        ls0 += __shfl_xor_sync(0xffffffffu, ls0, 2);
        ls1 += __shfl_xor_sync(0xffffffffu, ls1, 1);
        ls1 += __shfl_xor_sync(0xffffffffu, ls1, 2);
        l0 = l0 * corr0 + ls0;
        l1 = l1 * corr1 + ls1;
        #pragma unroll
        for (int j = 0; j < 8; j++) {
            O[j][0] *= corr0; O[j][1] *= corr0;
            O[j][2] *= corr1; O[j][3] *= corr1;
        }

        uint32_t ph[4][4], pl[4][4];
        #pragma unroll
        for (int kb = 0; kb < 4; kb++) {
            pack_split(sc[2 * kb][0],     sc[2 * kb][1],     ph[kb][0], pl[kb][0]);
            pack_split(sc[2 * kb][2],     sc[2 * kb][3],     ph[kb][1], pl[kb][1]);
            pack_split(sc[2 * kb + 1][0], sc[2 * kb + 1][1], ph[kb][2], pl[kb][2]);
            pack_split(sc[2 * kb + 1][2], sc[2 * kb + 1][3], ph[kb][3], pl[kb][3]);
        }

        #pragma unroll
        for (int kb = 0; kb < 4; kb++) {
            const uint32_t kadd = (uint32_t)kb * 2048u;
            uint32_t vh[4][4], vl[4][4];
            #pragma unroll
            for (int dp = 0; dp < 4; dp++) {
                const uint32_t dx = (uint32_t)(dp * 32);
                ldsm4t(vh[dp], so + 16384u + ((baV + kadd) ^ dx));
                ldsm4t(vl[dp], so + 24576u + ((baV + kadd) ^ dx));
            }
            #pragma unroll
            for (int dp = 0; dp < 4; dp++) {
                mma16816(O[2 * dp],     ph[kb], &vh[dp][0]);
                mma16816(O[2 * dp + 1], ph[kb], &vh[dp][2]);
            }
            #pragma unroll
            for (int dp = 0; dp < 4; dp++) {
                mma16816(O[2 * dp],     pl[kb], &vh[dp][0]);
                mma16816(O[2 * dp + 1], pl[kb], &vh[dp][2]);
            }
            #pragma unroll
            for (int dp = 0; dp < 4; dp++) {
                mma16816(O[2 * dp],     ph[kb], &vl[dp][0]);
                mma16816(O[2 * dp + 1], ph[kb], &vl[dp][2]);
            }
        }
    }

    float inv0 = 1.0f / l0, inv1 = 1.0f / l1;
    size_t row0 = (size_t)(b * S_LEN + q0 + w * 16 + (lane >> 2));
    size_t row1 = row0 + 8;
    #pragma unroll
    for (int j = 0; j < 8; j++) {
        int col = hcol + j * 8 + (lane & 3) * 2;
        uint32_t hi, lo;
        pack_split(O[j][0] * inv0, O[j][1] * inv0, hi, lo);
        *(uint32_t*)&Chi[row0 * EMB + col] = hi;
        *(uint32_t*)&Clo[row0 * EMB + col] = lo;
        pack_split(O[j][2] * inv1, O[j][3] * inv1, hi, lo);
        *(uint32_t*)&Chi[row1 * EMB + col] = hi;
        *(uint32_t*)&Clo[row1 * EMB + col] = lo;
    }
}

// ===========================================================================
// Launch
// ===========================================================================
extern "C" void kernel_launch(void* const* d_in, const int* in_sizes, int n_in,
                              void* d_out, int out_size)
{
    const float* q    = (const float*)d_in[0];
    const float* k    = (const float*)d_in[1];
    const float* v    = (const float*)d_in[2];
    const int*   mask = (const int*)  d_in[3];
    const float* Wq   = (const float*)d_in[4];
    const float* Wk   = (const float*)d_in[5];
    const float* Wv   = (const float*)d_in[6];
    const float* Wo   = (const float*)d_in[7];
    const float* bo   = (const float*)d_in[8];
    float* out = (float*)d_out;

    __nv_bfloat16 *Aqhi, *Aqlo, *Akhi, *Aklo, *Avhi, *Avlo;
    __nv_bfloat16 *Bqhi, *Bqlo, *Bkhi, *Bklo, *Bvhi, *Bvlo, *Bohi, *Bolo;
    __nv_bfloat16 *Qhi, *Qlo, *Khi, *Klo, *Vhi, *Vlo, *Chi, *Clo;
    int *idx, *cnt;
    cudaGetSymbolAddress((void**)&Aqhi, g_Aqhi);
    cudaGetSymbolAddress((void**)&Aqlo, g_Aqlo);
    cudaGetSymbolAddress((void**)&Akhi, g_Akhi);
    cudaGetSymbolAddress((void**)&Aklo, g_Aklo);
    cudaGetSymbolAddress((void**)&Avhi, g_Avhi);
    cudaGetSymbolAddress((void**)&Avlo, g_Avlo);
    cudaGetSymbolAddress((void**)&Bqhi, g_Bqhi);
    cudaGetSymbolAddress((void**)&Bqlo, g_Bqlo);
    cudaGetSymbolAddress((void**)&Bkhi, g_Bkhi);
    cudaGetSymbolAddress((void**)&Bklo, g_Bklo);
    cudaGetSymbolAddress((void**)&Bvhi, g_Bvhi);
    cudaGetSymbolAddress((void**)&Bvlo, g_Bvlo);
    cudaGetSymbolAddress((void**)&Bohi, g_Bohi);
    cudaGetSymbolAddress((void**)&Bolo, g_Bolo);
    cudaGetSymbolAddress((void**)&Qhi, g_Qhi);
    cudaGetSymbolAddress((void**)&Qlo, g_Qlo);
    cudaGetSymbolAddress((void**)&Khi, g_Khi);
    cudaGetSymbolAddress((void**)&Klo, g_Klo);
    cudaGetSymbolAddress((void**)&Vhi, g_Vhi);
    cudaGetSymbolAddress((void**)&Vlo, g_Vlo);
    cudaGetSymbolAddress((void**)&Chi, g_Chi);
    cudaGetSymbolAddress((void**)&Clo, g_Clo);
    cudaGetSymbolAddress((void**)&idx, g_idx);
    cudaGetSymbolAddress((void**)&cnt, g_cnt);

    cudaFuncSetAttribute(gemm3p_kernel,
                         cudaFuncAttributeMaxDynamicSharedMemorySize, GSMEM);
    cudaFuncSetAttribute(attn_mma_kernel,
                         cudaFuncAttributeMaxDynamicSharedMemorySize, ASMEM);

    int sms = 148;
    {
        int dev = 0;
        cudaGetDevice(&dev);
        cudaDeviceGetAttribute(&sms, cudaDevAttrMultiProcessorCount, dev);
    }

    const int nA4 = MROWS * EMB / 4;
    const int nW4 = EMB * EMB / 4;

    // 1. mask compaction
    mask_compact_kernel<<<BATCH, 1024>>>(mask, idx, cnt);

    // 2. input conversions
    dim3 gIn(nA4 / 256, 1, 3);
    cvt_inputs_kernel<<<gIn, 256>>>(q, k, v, idx, cnt,
                                    Aqhi, Aqlo, Akhi, Aklo, Avhi, Avlo);

    // 3. weight conversions
    WJobs wj;
    wj.s[0] = Wq; wj.h[0] = Bqhi; wj.l[0] = Bqlo;
    wj.s[1] = Wk; wj.h[1] = Bkhi; wj.l[1] = Bklo;
    wj.s[2] = Wv; wj.h[2] = Bvhi; wj.l[2] = Bvlo;
    wj.s[3] = Wo; wj.h[3] = Bohi; wj.l[3] = Bolo;
    dim3 gW(nW4 / 256, 1, 4);
    cvt_weights_kernel<<<gW, 256>>>(wj);

    // 4. merged persistent Q/K/V projections
    GJobs gj;
    gj.j[0].Ahi = Aqhi; gj.j[0].Alo = Aqlo; gj.j[0].Bhi = Bqhi; gj.j[0].Blo = Bqlo;
    gj.j[0].Chi = Qhi;  gj.j[0].Clo = Qlo;  gj.j[0].Cf = nullptr;
    gj.j[0].bias = nullptr; gj.j[0].cnt = nullptr;
    gj.j[1].Ahi = Akhi; gj.j[1].Alo = Aklo; gj.j[1].Bhi = Bkhi; gj.j[1].Blo = Bklo;
    gj.j[1].Chi = Khi;  gj.j[1].Clo = Klo;  gj.j[1].Cf = nullptr;
    gj.j[1].bias = nullptr; gj.j[1].cnt = cnt;
    gj.j[2].Ahi = Avhi; gj.j[2].Alo = Avlo; gj.j[2].Bhi = Bvhi; gj.j[2].Blo = Bvlo;
    gj.j[2].Chi = Vhi;  gj.j[2].Clo = Vlo;  gj.j[2].Cf = nullptr;
    gj.j[2].bias = nullptr; gj.j[2].cnt = cnt;
    gj.n = 3;
    gemm3p_kernel<<<sms, 256, GSMEM>>>(gj);

    // 5. attention
    dim3 gAttn(S_LEN / 128, BATCH * NHEAD);
    attn_mma_kernel<<<gAttn, 256, ASMEM>>>(Qhi, Qlo, Khi, Klo, Vhi, Vlo, cnt, Chi, Clo);

    // 6. persistent output projection (+bias)
    GJobs go;
    go.j[0].Ahi = Chi; go.j[0].Alo = Clo; go.j[0].Bhi = Bohi; go.j[0].Blo = Bolo;
    go.j[0].Chi = nullptr; go.j[0].Clo = nullptr; go.j[0].Cf = out;
    go.j[0].bias = bo; go.j[0].cnt = nullptr;
    go.n = 1;
    gemm3p_kernel<<<sms, 256, GSMEM>>>(go);
}

// round 10
// speedup vs baseline: 1.3795x; 1.3732x over previous
#include <cuda_runtime.h>
#include <cuda_fp16.h>
#include <cstdint>

// ===========================================================================
// mma.sync / ldmatrix / cp.async helpers (base sm_103 target — no tcgen05)
// ===========================================================================
__device__ __forceinline__ uint32_t smem_u32_of(const void* p) {
    uint32_t a;
    asm("{ .reg .u64 t; cvta.to.shared.u64 t, %1; cvt.u32.u64 %0, t; }"
        : "=r"(a) : "l"(p));
    return a;
}
__device__ __forceinline__ void ldsm4(uint32_t r[4], uint32_t addr) {
    asm volatile("ldmatrix.sync.aligned.m8n8.x4.shared.b16 {%0,%1,%2,%3}, [%4];"
        : "=r"(r[0]), "=r"(r[1]), "=r"(r[2]), "=r"(r[3]) : "r"(addr));
}
__device__ __forceinline__ void ldsm4t(uint32_t r[4], uint32_t addr) {
    asm volatile("ldmatrix.sync.aligned.m8n8.x4.trans.shared.b16 {%0,%1,%2,%3}, [%4];"
        : "=r"(r[0]), "=r"(r[1]), "=r"(r[2]), "=r"(r[3]) : "r"(addr));
}
// fp16 inputs, fp32 accumulate
__device__ __forceinline__ void mma16816(float c[4], const uint32_t a[4],
                                         const uint32_t b[2]) {
    asm volatile(
        "mma.sync.aligned.m16n8k16.row.col.f32.f16.f16.f32 "
        "{%0,%1,%2,%3}, {%4,%5,%6,%7}, {%8,%9}, {%0,%1,%2,%3};"
        : "+f"(c[0]), "+f"(c[1]), "+f"(c[2]), "+f"(c[3])
        : "r"(a[0]), "r"(a[1]), "r"(a[2]), "r"(a[3]), "r"(b[0]), "r"(b[1]));
}
__device__ __forceinline__ void cp16(uint32_t dst, const void* src) {
    asm volatile("cp.async.cg.shared.global [%0], [%1], 16;" :: "r"(dst), "l"(src));
}
#define CP_COMMIT() asm volatile("cp.async.commit_group;" ::: "memory")
template <int N>
__device__ __forceinline__ void cp_wait() {
    asm volatile("cp.async.wait_group %0;" :: "n"(N) : "memory");
}

// fp16 split: hi = f16x2(a,b); lo = f16x2 of residuals
__device__ __forceinline__ void pack_split_h(float a, float b, uint32_t& hi, uint32_t& lo) {
    __half2 h2 = __floats2half2_rn(a, b);
    float2 hf = __half22float2(h2);
    __half2 l2 = __floats2half2_rn(a - hf.x, b - hf.y);
    hi = *(uint32_t*)&h2;
    lo = *(uint32_t*)&l2;
}
__device__ __forceinline__ uint32_t pack_h(float a, float b) {
    __half2 h2 = __floats2half2_rn(a, b);
    return *(uint32_t*)&h2;
}

// ===========================================================================
// Problem constants
// ===========================================================================
#define BATCH   4
#define S_LEN   2048
#define EMB     1024
#define NHEAD   16
#define DHEAD   64
#define MROWS   (BATCH * S_LEN)   // 8192

// Scratch (device globals — allocations forbidden)
__device__ __half g_Aqhi[MROWS * EMB];
__device__ __half g_Aqlo[MROWS * EMB];
__device__ __half g_Akhi[MROWS * EMB];
__device__ __half g_Aklo[MROWS * EMB];
__device__ __half g_Avhi[MROWS * EMB];
__device__ __half g_Avlo[MROWS * EMB];
__device__ __half g_Bqh[EMB * EMB];
__device__ __half g_Bkh[EMB * EMB];
__device__ __half g_Bvh[EMB * EMB];
__device__ __half g_Boh[EMB * EMB];
__device__ __half g_Qhi[MROWS * EMB];
__device__ __half g_Qlo[MROWS * EMB];
__device__ __half g_Kh[MROWS * EMB];
__device__ __half g_Vh[MROWS * EMB];
__device__ __half g_Chi[MROWS * EMB];
__device__ __half g_Clo[MROWS * EMB];
__device__ int g_idx[BATCH * S_LEN];
__device__ int g_cnt[BATCH];

// ===========================================================================
// Stable mask compaction (unchanged, proven)
// ===========================================================================
__global__ __launch_bounds__(1024) void mask_compact_kernel(
    const int* __restrict__ mask, int* __restrict__ idx, int* __restrict__ cnt)
{
    const int b = blockIdx.x, t = threadIdx.x;
    const int wid = t >> 5, lane = t & 31;
    __shared__ int wsum[32], woff[32], chunk_total;
    int base = 0;
    #pragma unroll
    for (int half = 0; half < 2; half++) {
        int e = half * 1024 + t;
        int m = mask[b * S_LEN + e];
        unsigned bal = __ballot_sync(0xffffffffu, m != 0);
        int wtot = __popc(bal);
        int pos  = __popc(bal & ((1u << lane) - 1u));
        if (lane == 0) wsum[wid] = wtot;
        __syncthreads();
        if (t < 32) {
            int v = wsum[t], s = v;
            #pragma unroll
            for (int o = 1; o < 32; o <<= 1) {
                int u = __shfl_up_sync(0xffffffffu, s, o);
                if (t >= o) s += u;
            }
            woff[t] = s - v;
            if (t == 31) chunk_total = s;
        }
        __syncthreads();
        if (m) idx[b * S_LEN + base + woff[wid] + pos] = e;
        base += chunk_total;
        __syncthreads();
    }
    if (t == 0) cnt[b] = base;
}

// ===========================================================================
// Merged input conversion: z=0 dense q, z=1 gather k, z=2 gather v (split)
// ===========================================================================
__global__ __launch_bounds__(256) void cvt_inputs_kernel(
    const float* __restrict__ q, const float* __restrict__ k,
    const float* __restrict__ v,
    const int* __restrict__ idx, const int* __restrict__ cnt,
    __half* __restrict__ qh, __half* __restrict__ ql,
    __half* __restrict__ kh, __half* __restrict__ kl,
    __half* __restrict__ vh, __half* __restrict__ vl)
{
    const int z = blockIdx.z;
    const float* src = (z == 0) ? q : ((z == 1) ? k : v);
    __half* H = (z == 0) ? qh : ((z == 1) ? kh : vh);
    __half* L = (z == 0) ? ql : ((z == 1) ? kl : vl);
    int i = blockIdx.x * blockDim.x + threadIdx.x;
    if (z == 0) {
        float4 x = ((const float4*)src)[i];
        uint2 hh, ll;
        pack_split_h(x.x, x.y, hh.x, ll.x);
        pack_split_h(x.z, x.w, hh.y, ll.y);
        ((uint2*)H)[i] = hh;
        ((uint2*)L)[i] = ll;
    } else {
        int rowq = i >> 8;
        int c4 = i & 255;
        int b = rowq >> 11, r = rowq & 2047;
        uint2 hh = make_uint2(0u, 0u), ll = make_uint2(0u, 0u);
        if (r < cnt[b]) {
            int s = idx[b * S_LEN + r];
            float4 x = ((const float4*)(src + ((size_t)(b * S_LEN + s)) * EMB))[c4];
            pack_split_h(x.x, x.y, hh.x, ll.x);
            pack_split_h(x.z, x.w, hh.y, ll.y);
        }
        ((uint2*)H)[(size_t)rowq * 256 + c4] = hh;
        ((uint2*)L)[(size_t)rowq * 256 + c4] = ll;
    }
}

// ===========================================================================
// Merged weight conversion: hi only
// ===========================================================================
struct WJobs {
    const float* s[4];
    __half* h[4];
};

__global__ __launch_bounds__(256) void cvt_weights_kernel(WJobs wj)
{
    const int z = blockIdx.z;
    int i = blockIdx.x * blockDim.x + threadIdx.x;
    float4 x = ((const float4*)wj.s[z])[i];
    uint2 hh;
    hh.x = pack_h(x.x, x.y);
    hh.y = pack_h(x.z, x.w);
    ((uint2*)wj.h[z])[i] = hh;
}

// ===========================================================================
// Persistent multi-job fp16 2-term GEMM on the ROUND-8 memory skeleton:
// stage = 64KB (Ahi@0 | Alo@16K | Bhi@32K | hole@48K), 3 stages.
// Addresses are a strict subset of the proven round-8 set.
// ===========================================================================
#define CHUNKS 16
#define STG_BYTES 65536
#define NSTAGE 3
#define GSMEM (NSTAGE * STG_BYTES)    // 196608, same as round 8

struct GJob {
    const __half* Ahi;
    const __half* Alo;
    const __half* Bhi;
    __half* Chi;
    __half* Clo;                      // null -> hi-only output
    float* Cf;                        // non-null -> fp32 output (+bias)
    const float* bias;
    const int* cnt;
};
struct GJobs { GJob j[3]; int n; };

__global__ __launch_bounds__(256, 1) void gemm2p_kernel(GJobs jobs)
{
    extern __shared__ __align__(1024) char smem[];
    const uint32_t sb = smem_u32_of(smem);
    const int t = threadIdx.x;
    const int w = t >> 5, lane = t & 31;
    const int wm = (w >> 2) * 64;
    const int wn = (w & 3) * 32;

    uint32_t lsw[4]; uint32_t lgo[4];
    #pragma unroll
    for (int i = 0; i < 4; i++) {
        int u = t + 256 * i;
        int row = u >> 3, ku = u & 7;
        uint32_t off = row * 128 + ku * 16;
        lsw[i] = off ^ ((off >> 3) & 0x70);
        lgo[i] = (uint32_t)row * EMB + ku * 8;
    }

    const uint32_t xr  = (lane & 7) << 4;
    const uint32_t ak0 = (uint32_t)(lane & 16) ^ xr;
    const int      arow = lane & 15;
    const uint32_t bk0 = (uint32_t)((lane & 8) << 1) ^ xr;
    const int      brow = (lane & 7) | ((lane & 16) >> 1);
    uint32_t baA[4], baB[2];
    #pragma unroll
    for (int mi = 0; mi < 4; mi++)
        baA[mi] = (uint32_t)(wm + mi * 16 + arow) * 128 + ak0;
    #pragma unroll
    for (int nt = 0; nt < 2; nt++)
        baB[nt] = 32768u + (uint32_t)(wn + nt * 16 + brow) * 128 + bk0;

    const int total = jobs.n << 9;
    for (int tile = blockIdx.x; tile < total; tile += gridDim.x) {
        const GJob J = jobs.j[tile >> 9];
        const int within = tile & 511;
        const int bm = (within >> 3) * 128;
        const int bn = (within & 7) * 128;
        if (J.cnt && (bm & 2047) >= J.cnt[bm >> 11]) continue;

        const __half* gAhi = J.Ahi + (size_t)bm * EMB;
        const __half* gAlo = J.Alo + (size_t)bm * EMB;
        const __half* gBhi = J.Bhi + (size_t)bn * EMB;

        float acc[4][4][4];
        #pragma unroll
        for (int mi = 0; mi < 4; mi++)
            #pragma unroll
            for (int ni = 0; ni < 4; ni++)
                #pragma unroll
                for (int r = 0; r < 4; r++) acc[mi][ni][r] = 0.0f;

        auto load_chunk = [&](int c) {
            const uint32_t so = sb + (uint32_t)(c % NSTAGE) * STG_BYTES;
            const uint32_t ko = (uint32_t)c * 64;
            #pragma unroll
            for (int i = 0; i < 4; i++) {
                cp16(so +      0 + lsw[i], gAhi + lgo[i] + ko);
                cp16(so + 16384u + lsw[i], gAlo + lgo[i] + ko);
                cp16(so + 32768u + lsw[i], gBhi + lgo[i] + ko);
            }
            CP_COMMIT();
        };

        __syncthreads();   // previous tile's compute done before stage reuse
        load_chunk(0);
        load_chunk(1);

        for (int c = 0; c < CHUNKS; c++) {
            if (c + 1 < CHUNKS) { cp_wait<1>(); } else { cp_wait<0>(); }
            __syncthreads();
            if (c + 2 < CHUNKS) load_chunk(c + 2);

            const uint32_t so = sb + (uint32_t)(c % NSTAGE) * STG_BYTES;
            #pragma unroll
            for (int ks = 0; ks < 4; ks++) {
                const uint32_t kx = (uint32_t)ks << 5;
                uint32_t ah[4][4], al[4][4], bh[2][4];
                #pragma unroll
                for (int mi = 0; mi < 4; mi++) {
                    ldsm4(ah[mi], so + (baA[mi] ^ kx));
                    ldsm4(al[mi], so + 16384u + (baA[mi] ^ kx));
                }
                #pragma unroll
                for (int nt = 0; nt < 2; nt++)
                    ldsm4(bh[nt], so + (baB[nt] ^ kx));
                // two term-major sweeps, 16 independent accumulators each
                #pragma unroll
                for (int mi = 0; mi < 4; mi++)
                    #pragma unroll
                    for (int ni = 0; ni < 4; ni++)
                        mma16816(acc[mi][ni], ah[mi], &bh[ni >> 1][(ni & 1) * 2]);
                #pragma unroll
                for (int mi = 0; mi < 4; mi++)
                    #pragma unroll
                    for (int ni = 0; ni < 4; ni++)
                        mma16816(acc[mi][ni], al[mi], &bh[ni >> 1][(ni & 1) * 2]);
            }
        }

        // ---- epilogue ----
        #pragma unroll
        for (int mi = 0; mi < 4; mi++) {
            #pragma unroll
            for (int ni = 0; ni < 4; ni++) {
                int row = bm + wm + mi * 16 + (lane >> 2);
                int col = bn + wn + ni * 8 + (lane & 3) * 2;
                if (J.Cf) {
                    float2 v0 = make_float2(acc[mi][ni][0], acc[mi][ni][1]);
                    float2 v1 = make_float2(acc[mi][ni][2], acc[mi][ni][3]);
                    float b0 = __ldg(J.bias + col), b1 = __ldg(J.bias + col + 1);
                    v0.x += b0; v0.y += b1; v1.x += b0; v1.y += b1;
                    *(float2*)&J.Cf[(size_t)row * EMB + col] = v0;
                    *(float2*)&J.Cf[(size_t)(row + 8) * EMB + col] = v1;
                } else if (J.Clo) {
                    uint32_t hi, lo;
                    pack_split_h(acc[mi][ni][0], acc[mi][ni][1], hi, lo);
                    *(uint32_t*)&J.Chi[(size_t)row * EMB + col] = hi;
                    *(uint32_t*)&J.Clo[(size_t)row * EMB + col] = lo;
                    pack_split_h(acc[mi][ni][2], acc[mi][ni][3], hi, lo);
                    *(uint32_t*)&J.Chi[(size_t)(row + 8) * EMB + col] = hi;
                    *(uint32_t*)&J.Clo[(size_t)(row + 8) * EMB + col] = lo;
                } else {
                    *(uint32_t*)&J.Chi[(size_t)row * EMB + col] =
                        pack_h(acc[mi][ni][0], acc[mi][ni][1]);
                    *(uint32_t*)&J.Chi[(size_t)(row + 8) * EMB + col] =
                        pack_h(acc[mi][ni][2], acc[mi][ni][3]);
                }
            }
        }
    }
}

// ===========================================================================
// fp16 2-term flash attention on the ROUND-8 memory skeleton:
// stage = 32KB (Kh@0 | hole@8K | Vh@16K | hole@24K), 3 stages (96KB).
// ===========================================================================
#define ASTG 32768
#define ANST 3
#define ASMEM (ANST * ASTG)           // 98304, same as round 8

__global__ __launch_bounds__(256, 1) void attn_mma_kernel(
    const __half* __restrict__ Qhi, const __half* __restrict__ Qlo,
    const __half* __restrict__ Kh, const __half* __restrict__ Vh,
    const int* __restrict__ cnt,
    __half* __restrict__ Chi, __half* __restrict__ Clo)
{
    extern __shared__ __align__(1024) char smem[];
    const uint32_t sb = smem_u32_of(smem);
    const int t = threadIdx.x, w = t >> 5, lane = t & 31;
    const int qt = blockIdx.x, bh = blockIdx.y;
    const int b = bh >> 4, h = bh & 15;
    const int q0 = qt * 128;
    const int hcol = h * 64;
    const int n = cnt[b];
    const int ntiles = (n + 63) >> 6;

    // ---- stage Q (hi@0, lo@16K — same addresses as round 8), extract ----
    {
        const size_t qbase = ((size_t)(b * S_LEN + q0)) * EMB + hcol;
        #pragma unroll
        for (int i = 0; i < 8; i++) {
            int u = t + 256 * i;
            int arr = u >> 10;
            int r = (u >> 3) & 127;
            int du = u & 7;
            uint32_t off = r * 128 + du * 16;
            uint32_t sw = off ^ ((off >> 3) & 0x70);
            const __half* src = (arr ? Qlo : Qhi) + qbase + (size_t)r * EMB + du * 8;
            cp16(sb + (uint32_t)arr * 16384u + sw, src);
        }
        CP_COMMIT();
    }
    cp_wait<0>();
    __syncthreads();

    uint32_t qh[4][4], ql[4][4];
    {
        uint32_t off = (uint32_t)(w * 16 + (lane & 15)) * 128 + ((lane >> 4) * 16);
        uint32_t baQ = off ^ ((off >> 3) & 0x70);
        #pragma unroll
        for (int k16 = 0; k16 < 4; k16++) {
            ldsm4(qh[k16], sb + (baQ ^ (uint32_t)(k16 * 32)));
            ldsm4(ql[k16], sb + 16384u + (baQ ^ (uint32_t)(k16 * 32)));
        }
    }
    __syncthreads();

    uint32_t baK, baV;
    {
        uint32_t keyk = (uint32_t)((lane & 7) | ((lane & 16) >> 1));
        uint32_t offk = keyk * 128 + (uint32_t)((lane & 8) << 1);
        baK = offk ^ ((offk >> 3) & 0x70);
        uint32_t keyv = (uint32_t)(lane & 15);
        uint32_t offv = keyv * 128 + (uint32_t)((lane >> 4) * 16);
        baV = offv ^ ((offv >> 3) & 0x70);
    }

    // K at stage+0, V at stage+16384 (round-8 Khi/Vhi slots; lo slots unused)
    auto load_tile = [&](int kt, int stg) {
        const size_t gk = ((size_t)(b * S_LEN + kt * 64)) * EMB + hcol;
        const uint32_t sdst = sb + (uint32_t)stg * ASTG;
        #pragma unroll
        for (int i = 0; i < 4; i++) {
            int u = t + 256 * i;          // 0..1023
            int arr = u >> 9;             // 0 Kh, 1 Vh
            int r = (u >> 3) & 63;
            int du = u & 7;
            uint32_t off = r * 128 + du * 16;
            uint32_t sw = off ^ ((off >> 3) & 0x70);
            const __half* p = arr ? Vh : Kh;
            cp16(sdst + (uint32_t)arr * 16384u + sw, p + gk + (size_t)r * EMB + du * 8);
        }
        CP_COMMIT();
    };

    float O[8][4];
    #pragma unroll
    for (int j = 0; j < 8; j++)
        #pragma unroll
        for (int r = 0; r < 4; r++) O[j][r] = 0.0f;
    float m0 = -1e30f, m1 = -1e30f, l0 = 0.0f, l1 = 0.0f;

    if (ntiles == 0) {
        size_t row0 = (size_t)(b * S_LEN + q0 + w * 16 + (lane >> 2));
        #pragma unroll
        for (int j = 0; j < 8; j++) {
            int col = hcol + j * 8 + (lane & 3) * 2;
            *(uint32_t*)&Chi[row0 * EMB + col] = 0u;
            *(uint32_t*)&Clo[row0 * EMB + col] = 0u;
            *(uint32_t*)&Chi[(row0 + 8) * EMB + col] = 0u;
            *(uint32_t*)&Clo[(row0 + 8) * EMB + col] = 0u;
        }
        return;
    }

    load_tile(0, 0);
    if (ntiles > 1) load_tile(1, 1);

    for (int kt = 0; kt < ntiles; kt++) {
        if (kt + 1 < ntiles) { cp_wait<1>(); } else { cp_wait<0>(); }
        __syncthreads();
        if (kt + 2 < ntiles) load_tile(kt + 2, (kt + 2) % ANST);

        const uint32_t so = sb + (uint32_t)(kt % ANST) * ASTG;

        // ---- scores = Q K^T (2-term) ----
        float sc[8][4];
        #pragma unroll
        for (int j = 0; j < 8; j++)
            #pragma unroll
            for (int r = 0; r < 4; r++) sc[j][r] = 0.0f;

        #pragma unroll
        for (int k16 = 0; k16 < 4; k16++) {
            const uint32_t kx = (uint32_t)(k16 * 32);
            uint32_t kf[4][4];
            #pragma unroll
            for (int np = 0; np < 4; np++)
                ldsm4(kf[np], so + ((baK + (uint32_t)np * 2048u) ^ kx));
            #pragma unroll
            for (int np = 0; np < 4; np++) {
                mma16816(sc[2 * np],     qh[k16], &kf[np][0]);
                mma16816(sc[2 * np + 1], qh[k16], &kf[np][2]);
            }
            #pragma unroll
            for (int np = 0; np < 4; np++) {
                mma16816(sc[2 * np],     ql[k16], &kf[np][0]);
                mma16816(sc[2 * np + 1], ql[k16], &kf[np][2]);
            }
        }

        // ---- scale + boundary mask + online softmax ----
        const int c0 = (lane & 3) * 2;
        const int limit = n - kt * 64;
        float rm0 = m0, rm1 = m1;
        #pragma unroll
        for (int j = 0; j < 8; j++) {
            int kc = j * 8 + c0;
            bool v0 = kc < limit, v1 = kc + 1 < limit;
            sc[j][0] = v0 ? sc[j][0] * 0.125f : -1e10f;
            sc[j][1] = v1 ? sc[j][1] * 0.125f : -1e10f;
            sc[j][2] = v0 ? sc[j][2] * 0.125f : -1e10f;
            sc[j][3] = v1 ? sc[j][3] * 0.125f : -1e10f;
            rm0 = fmaxf(rm0, fmaxf(sc[j][0], sc[j][1]));
            rm1 = fmaxf(rm1, fmaxf(sc[j][2], sc[j][3]));
        }
        rm0 = fmaxf(rm0, __shfl_xor_sync(0xffffffffu, rm0, 1));
        rm0 = fmaxf(rm0, __shfl_xor_sync(0xffffffffu, rm0, 2));
        rm1 = fmaxf(rm1, __shfl_xor_sync(0xffffffffu, rm1, 1));
        rm1 = fmaxf(rm1, __shfl_xor_sync(0xffffffffu, rm1, 2));
        float corr0 = __expf(m0 - rm0);
        float corr1 = __expf(m1 - rm1);
        m0 = rm0; m1 = rm1;
        float ls0 = 0.0f, ls1 = 0.0f;
        #pragma unroll
        for (int j = 0; j < 8; j++) {
            sc[j][0] = __expf(sc[j][0] - m0);
            sc[j][1] = __expf(sc[j][1] - m0);
            sc[j][2] = __expf(sc[j][2] - m1);
            sc[j][3] = __expf(sc[j][3] - m1);
            ls0 += sc[j][0] + sc[j][1];
            ls1 += sc[j][2] + sc[j][3];
        }
        ls0 += __shfl_xor_sync(0xffffffffu, ls0, 1);
        ls0 += __shfl_xor_sync(0xffffffffu, ls0, 2);
        ls1 += __shfl_xor_sync(0xffffffffu, ls1, 1);
        ls1 += __shfl_xor_sync(0xffffffffu, ls1, 2);
        l0 = l0 * corr0 + ls0;
        l1 = l1 * corr1 + ls1;
        #pragma unroll
        for (int j = 0; j < 8; j++) {
            O[j][0] *= corr0; O[j][1] *= corr0;
            O[j][2] *= corr1; O[j][3] *= corr1;
        }

        // ---- pack P into split fp16 a-frags ----
        uint32_t ph[4][4], pl[4][4];
        #pragma unroll
        for (int kb = 0; kb < 4; kb++) {
            pack_split_h(sc[2 * kb][0],     sc[2 * kb][1],     ph[kb][0], pl[kb][0]);
            pack_split_h(sc[2 * kb][2],     sc[2 * kb][3],     ph[kb][1], pl[kb][1]);
            pack_split_h(sc[2 * kb + 1][0], sc[2 * kb + 1][1], ph[kb][2], pl[kb][2]);
            pack_split_h(sc[2 * kb + 1][2], sc[2 * kb + 1][3], ph[kb][3], pl[kb][3]);
        }

        // ---- O += P V (2-term), V via ldmatrix.trans at stage+16384 ----
        #pragma unroll
        for (int kb = 0; kb < 4; kb++) {
            const uint32_t kadd = (uint32_t)kb * 2048u;
            uint32_t vf[4][4];
            #pragma unroll
            for (int dp = 0; dp < 4; dp++) {
                const uint32_t dx = (uint32_t)(dp * 32);
                ldsm4t(vf[dp], so + 16384u + ((baV + kadd) ^ dx));
            }
            #pragma unroll
            for (int dp = 0; dp < 4; dp++) {
                mma16816(O[2 * dp],     ph[kb], &vf[dp][0]);
                mma16816(O[2 * dp + 1], ph[kb], &vf[dp][2]);
            }
            #pragma unroll
            for (int dp = 0; dp < 4; dp++) {
                mma16816(O[2 * dp],     pl[kb], &vf[dp][0]);
                mma16816(O[2 * dp + 1], pl[kb], &vf[dp][2]);
            }
        }
    }

    // ---- epilogue: O/l -> split fp16 Ctx ----
    float inv0 = 1.0f / l0, inv1 = 1.0f / l1;
    size_t row0 = (size_t)(b * S_LEN + q0 + w * 16 + (lane >> 2));
    size_t row1 = row0 + 8;
    #pragma unroll
    for (int j = 0; j < 8; j++) {
        int col = hcol + j * 8 + (lane & 3) * 2;
        uint32_t hi, lo;
        pack_split_h(O[j][0] * inv0, O[j][1] * inv0, hi, lo);
        *(uint32_t*)&Chi[row0 * EMB + col] = hi;
        *(uint32_t*)&Clo[row0 * EMB + col] = lo;
        pack_split_h(O[j][2] * inv1, O[j][3] * inv1, hi, lo);
        *(uint32_t*)&Chi[row1 * EMB + col] = hi;
        *(uint32_t*)&Clo[row1 * EMB + col] = lo;
    }
}

// ===========================================================================
// Launch
// ===========================================================================
extern "C" void kernel_launch(void* const* d_in, const int* in_sizes, int n_in,
                              void* d_out, int out_size)
{
    const float* q    = (const float*)d_in[0];
    const float* k    = (const float*)d_in[1];
    const float* v    = (const float*)d_in[2];
    const int*   mask = (const int*)  d_in[3];
    const float* Wq   = (const float*)d_in[4];
    const float* Wk   = (const float*)d_in[5];
    const float* Wv   = (const float*)d_in[6];
    const float* Wo   = (const float*)d_in[7];
    const float* bo   = (const float*)d_in[8];
    float* out = (float*)d_out;

    __half *Aqhi, *Aqlo, *Akhi, *Aklo, *Avhi, *Avlo;
    __half *Bqh, *Bkh, *Bvh, *Boh;
    __half *Qhi, *Qlo, *Kh, *Vh, *Chi, *Clo;
    int *idx, *cnt;
    cudaGetSymbolAddress((void**)&Aqhi, g_Aqhi);
    cudaGetSymbolAddress((void**)&Aqlo, g_Aqlo);
    cudaGetSymbolAddress((void**)&Akhi, g_Akhi);
    cudaGetSymbolAddress((void**)&Aklo, g_Aklo);
    cudaGetSymbolAddress((void**)&Avhi, g_Avhi);
    cudaGetSymbolAddress((void**)&Avlo, g_Avlo);
    cudaGetSymbolAddress((void**)&Bqh, g_Bqh);
    cudaGetSymbolAddress((void**)&Bkh, g_Bkh);
    cudaGetSymbolAddress((void**)&Bvh, g_Bvh);
    cudaGetSymbolAddress((void**)&Boh, g_Boh);
    cudaGetSymbolAddress((void**)&Qhi, g_Qhi);
    cudaGetSymbolAddress((void**)&Qlo, g_Qlo);
    cudaGetSymbolAddress((void**)&Kh,  g_Kh);
    cudaGetSymbolAddress((void**)&Vh,  g_Vh);
    cudaGetSymbolAddress((void**)&Chi, g_Chi);
    cudaGetSymbolAddress((void**)&Clo, g_Clo);
    cudaGetSymbolAddress((void**)&idx, g_idx);
    cudaGetSymbolAddress((void**)&cnt, g_cnt);

    cudaFuncSetAttribute(gemm2p_kernel,
                         cudaFuncAttributeMaxDynamicSharedMemorySize, GSMEM);
    cudaFuncSetAttribute(attn_mma_kernel,
                         cudaFuncAttributeMaxDynamicSharedMemorySize, ASMEM);

    int sms = 148;
    {
        int dev = 0;
        cudaGetDevice(&dev);
        cudaDeviceGetAttribute(&sms, cudaDevAttrMultiProcessorCount, dev);
    }

    const int nA4 = MROWS * EMB / 4;
    const int nW4 = EMB * EMB / 4;

    // 1. mask compaction
    mask_compact_kernel<<<BATCH, 1024>>>(mask, idx, cnt);

    // 2. input conversions (split fp16)
    dim3 gIn(nA4 / 256, 1, 3);
    cvt_inputs_kernel<<<gIn, 256>>>(q, k, v, idx, cnt,
                                    Aqhi, Aqlo, Akhi, Aklo, Avhi, Avlo);

    // 3. weight conversions (hi only)
    WJobs wj;
    wj.s[0] = Wq; wj.h[0] = Bqh;
    wj.s[1] = Wk; wj.h[1] = Bkh;
    wj.s[2] = Wv; wj.h[2] = Bvh;
    wj.s[3] = Wo; wj.h[3] = Boh;
    dim3 gW(nW4 / 256, 1, 4);
    cvt_weights_kernel<<<gW, 256>>>(wj);

    // 4. merged persistent Q/K/V projections
    GJobs gj;
    gj.j[0].Ahi = Aqhi; gj.j[0].Alo = Aqlo; gj.j[0].Bhi = Bqh;
    gj.j[0].Chi = Qhi;  gj.j[0].Clo = Qlo;  gj.j[0].Cf = nullptr;
    gj.j[0].bias = nullptr; gj.j[0].cnt = nullptr;
    gj.j[1].Ahi = Akhi; gj.j[1].Alo = Aklo; gj.j[1].Bhi = Bkh;
    gj.j[1].Chi = Kh;   gj.j[1].Clo = nullptr; gj.j[1].Cf = nullptr;
    gj.j[1].bias = nullptr; gj.j[1].cnt = cnt;
    gj.j[2].Ahi = Avhi; gj.j[2].Alo = Avlo; gj.j[2].Bhi = Bvh;
    gj.j[2].Chi = Vh;   gj.j[2].Clo = nullptr; gj.j[2].Cf = nullptr;
    gj.j[2].bias = nullptr; gj.j[2].cnt = cnt;
    gj.n = 3;
    gemm2p_kernel<<<sms, 256, GSMEM>>>(gj);

    // 5. attention over compacted keys
    dim3 gAttn(S_LEN / 128, BATCH * NHEAD);   // (16, 64)
    attn_mma_kernel<<<gAttn, 256, ASMEM>>>(Qhi, Qlo, Kh, Vh, cnt, Chi, Clo);

    // 6. persistent output projection (+bias) -> fp32
    GJobs go;
    go.j[0].Ahi = Chi; go.j[0].Alo = Clo; go.j[0].Bhi = Boh;
    go.j[0].Chi = nullptr; go.j[0].Clo = nullptr; go.j[0].Cf = out;
    go.j[0].bias = bo; go.j[0].cnt = nullptr;
    go.j[1] = go.j[0];
    go.j[2] = go.j[0];
    go.n = 1;
    gemm2p_kernel<<<sms, 256, GSMEM>>>(go);
}

// round 11
// speedup vs baseline: 1.9930x; 1.4448x over previous
#include <cuda_runtime.h>
#include <cuda_fp16.h>
#include <cstdint>

// ===========================================================================
// mma.sync / ldmatrix / cp.async helpers (base sm_103 target — no tcgen05)
// ===========================================================================
__device__ __forceinline__ uint32_t smem_u32_of(const void* p) {
    uint32_t a;
    asm("{ .reg .u64 t; cvta.to.shared.u64 t, %1; cvt.u32.u64 %0, t; }"
        : "=r"(a) : "l"(p));
    return a;
}
__device__ __forceinline__ void ldsm4(uint32_t r[4], uint32_t addr) {
    asm volatile("ldmatrix.sync.aligned.m8n8.x4.shared.b16 {%0,%1,%2,%3}, [%4];"
        : "=r"(r[0]), "=r"(r[1]), "=r"(r[2]), "=r"(r[3]) : "r"(addr));
}
__device__ __forceinline__ void ldsm4t(uint32_t r[4], uint32_t addr) {
    asm volatile("ldmatrix.sync.aligned.m8n8.x4.trans.shared.b16 {%0,%1,%2,%3}, [%4];"
        : "=r"(r[0]), "=r"(r[1]), "=r"(r[2]), "=r"(r[3]) : "r"(addr));
}
// fp16 inputs, fp32 accumulate
__device__ __forceinline__ void mma16816(float c[4], const uint32_t a[4],
                                         const uint32_t b[2]) {
    asm volatile(
        "mma.sync.aligned.m16n8k16.row.col.f32.f16.f16.f32 "
        "{%0,%1,%2,%3}, {%4,%5,%6,%7}, {%8,%9}, {%0,%1,%2,%3};"
        : "+f"(c[0]), "+f"(c[1]), "+f"(c[2]), "+f"(c[3])
        : "r"(a[0]), "r"(a[1]), "r"(a[2]), "r"(a[3]), "r"(b[0]), "r"(b[1]));
}
__device__ __forceinline__ void cp16(uint32_t dst, const void* src) {
    asm volatile("cp.async.cg.shared.global [%0], [%1], 16;" :: "r"(dst), "l"(src));
}
#define CP_COMMIT() asm volatile("cp.async.commit_group;" ::: "memory")
template <int N>
__device__ __forceinline__ void cp_wait() {
    asm volatile("cp.async.wait_group %0;" :: "n"(N) : "memory");
}

__device__ __forceinline__ uint32_t pack_h(float a, float b) {
    __half2 h2 = __floats2half2_rn(a, b);
    return *(uint32_t*)&h2;
}

// ===========================================================================
// Problem constants
// ===========================================================================
#define BATCH   4
#define S_LEN   2048
#define EMB     1024
#define NHEAD   16
#define DHEAD   64
#define MROWS   (BATCH * S_LEN)   // 8192

// Scratch (device globals — allocations forbidden)
__device__ __half g_Aqh[MROWS * EMB];
__device__ __half g_Akh[MROWS * EMB];
__device__ __half g_Avh[MROWS * EMB];
__device__ __half g_Bqh[EMB * EMB];
__device__ __half g_Bkh[EMB * EMB];
__device__ __half g_Bvh[EMB * EMB];
__device__ __half g_Boh[EMB * EMB];
__device__ __half g_Qh[MROWS * EMB];
__device__ __half g_Kh[MROWS * EMB];
__device__ __half g_Vh[MROWS * EMB];
__device__ __half g_Ch[MROWS * EMB];
__device__ int g_idx[BATCH * S_LEN];
__device__ int g_cnt[BATCH];

// ===========================================================================
// Stable mask compaction (unchanged, proven)
// ===========================================================================
__global__ __launch_bounds__(1024) void mask_compact_kernel(
    const int* __restrict__ mask, int* __restrict__ idx, int* __restrict__ cnt)
{
    const int b = blockIdx.x, t = threadIdx.x;
    const int wid = t >> 5, lane = t & 31;
    __shared__ int wsum[32], woff[32], chunk_total;
    int base = 0;
    #pragma unroll
    for (int half = 0; half < 2; half++) {
        int e = half * 1024 + t;
        int m = mask[b * S_LEN + e];
        unsigned bal = __ballot_sync(0xffffffffu, m != 0);
        int wtot = __popc(bal);
        int pos  = __popc(bal & ((1u << lane) - 1u));
        if (lane == 0) wsum[wid] = wtot;
        __syncthreads();
        if (t < 32) {
            int v = wsum[t], s = v;
            #pragma unroll
            for (int o = 1; o < 32; o <<= 1) {
                int u = __shfl_up_sync(0xffffffffu, s, o);
                if (t >= o) s += u;
            }
            woff[t] = s - v;
            if (t == 31) chunk_total = s;
        }
        __syncthreads();
        if (m) idx[b * S_LEN + base + woff[wid] + pos] = e;
        base += chunk_total;
        __syncthreads();
    }
    if (t == 0) cnt[b] = base;
}

// ===========================================================================
// Merged input conversion (hi only): z=0 dense q, z=1 gather k, z=2 gather v
// ===========================================================================
__global__ __launch_bounds__(256) void cvt_inputs_kernel(
    const float* __restrict__ q, const float* __restrict__ k,
    const float* __restrict__ v,
    const int* __restrict__ idx, const int* __restrict__ cnt,
    __half* __restrict__ qh, __half* __restrict__ kh, __half* __restrict__ vh)
{
    const int z = blockIdx.z;
    const float* src = (z == 0) ? q : ((z == 1) ? k : v);
    __half* H = (z == 0) ? qh : ((z == 1) ? kh : vh);
    int i = blockIdx.x * blockDim.x + threadIdx.x;
    if (z == 0) {
        float4 x = ((const float4*)src)[i];
        ((uint2*)H)[i] = make_uint2(pack_h(x.x, x.y), pack_h(x.z, x.w));
    } else {
        int rowq = i >> 8;
        int c4 = i & 255;
        int b = rowq >> 11, r = rowq & 2047;
        uint2 hh = make_uint2(0u, 0u);
        if (r < cnt[b]) {
            int s = idx[b * S_LEN + r];
            float4 x = ((const float4*)(src + ((size_t)(b * S_LEN + s)) * EMB))[c4];
            hh = make_uint2(pack_h(x.x, x.y), pack_h(x.z, x.w));
        }
        ((uint2*)H)[(size_t)rowq * 256 + c4] = hh;
    }
}

// ===========================================================================
// Merged weight conversion: hi only
// ===========================================================================
struct WJobs {
    const float* s[4];
    __half* h[4];
};

__global__ __launch_bounds__(256) void cvt_weights_kernel(WJobs wj)
{
    const int z = blockIdx.z;
    int i = blockIdx.x * blockDim.x + threadIdx.x;
    float4 x = ((const float4*)wj.s[z])[i];
    ((uint2*)wj.h[z])[i] = make_uint2(pack_h(x.x, x.y), pack_h(x.z, x.w));
}

// ===========================================================================
// Persistent multi-job single-fp16 GEMM on the ROUND-10 memory skeleton:
// stage = 64KB (A@0 | hole@16K | B@32K | hole@48K), 3 stages.
// Addresses are a strict subset of the proven round-10 set.
// ===========================================================================
#define CHUNKS 16
#define STG_BYTES 65536
#define NSTAGE 3
#define GSMEM (NSTAGE * STG_BYTES)

struct GJob {
    const __half* Ah;
    const __half* Bh;
    __half* Ch;                       // fp16 output (null if Cf used)
    float* Cf;                        // fp32 output (+bias)
    const float* bias;
    const int* cnt;
};
struct GJobs { GJob j[3]; int n; };

__global__ __launch_bounds__(256, 1) void gemm1p_kernel(GJobs jobs)
{
    extern __shared__ __align__(1024) char smem[];
    const uint32_t sb = smem_u32_of(smem);
    const int t = threadIdx.x;
    const int w = t >> 5, lane = t & 31;
    const int wm = (w >> 2) * 64;
    const int wn = (w & 3) * 32;

    uint32_t lsw[4]; uint32_t lgo[4];
    #pragma unroll
    for (int i = 0; i < 4; i++) {
        int u = t + 256 * i;
        int row = u >> 3, ku = u & 7;
        uint32_t off = row * 128 + ku * 16;
        lsw[i] = off ^ ((off >> 3) & 0x70);
        lgo[i] = (uint32_t)row * EMB + ku * 8;
    }

    const uint32_t xr  = (lane & 7) << 4;
    const uint32_t ak0 = (uint32_t)(lane & 16) ^ xr;
    const int      arow = lane & 15;
    const uint32_t bk0 = (uint32_t)((lane & 8) << 1) ^ xr;
    const int      brow = (lane & 7) | ((lane & 16) >> 1);
    uint32_t baA[4], baB[2];
    #pragma unroll
    for (int mi = 0; mi < 4; mi++)
        baA[mi] = (uint32_t)(wm + mi * 16 + arow) * 128 + ak0;
    #pragma unroll
    for (int nt = 0; nt < 2; nt++)
        baB[nt] = 32768u + (uint32_t)(wn + nt * 16 + brow) * 128 + bk0;

    const int total = jobs.n << 9;
    for (int tile = blockIdx.x; tile < total; tile += gridDim.x) {
        const GJob J = jobs.j[tile >> 9];
        const int within = tile & 511;
        const int bm = (within >> 3) * 128;
        const int bn = (within & 7) * 128;
        if (J.cnt && (bm & 2047) >= J.cnt[bm >> 11]) continue;

        const __half* gAh = J.Ah + (size_t)bm * EMB;
        const __half* gBh = J.Bh + (size_t)bn * EMB;

        float acc[4][4][4];
        #pragma unroll
        for (int mi = 0; mi < 4; mi++)
            #pragma unroll
            for (int ni = 0; ni < 4; ni++)
                #pragma unroll
                for (int r = 0; r < 4; r++) acc[mi][ni][r] = 0.0f;

        auto load_chunk = [&](int c) {
            const uint32_t so = sb + (uint32_t)(c % NSTAGE) * STG_BYTES;
            const uint32_t ko = (uint32_t)c * 64;
            #pragma unroll
            for (int i = 0; i < 4; i++) {
                cp16(so +      0 + lsw[i], gAh + lgo[i] + ko);
                cp16(so + 32768u + lsw[i], gBh + lgo[i] + ko);
            }
            CP_COMMIT();
        };

        __syncthreads();   // previous tile's compute done before stage reuse
        load_chunk(0);
        load_chunk(1);

        for (int c = 0; c < CHUNKS; c++) {
            if (c + 1 < CHUNKS) { cp_wait<1>(); } else { cp_wait<0>(); }
            __syncthreads();
            if (c + 2 < CHUNKS) load_chunk(c + 2);

            const uint32_t so = sb + (uint32_t)(c % NSTAGE) * STG_BYTES;
            #pragma unroll
            for (int ks = 0; ks < 4; ks++) {
                const uint32_t kx = (uint32_t)ks << 5;
                uint32_t ah[4][4], bh[2][4];
                #pragma unroll
                for (int mi = 0; mi < 4; mi++)
                    ldsm4(ah[mi], so + (baA[mi] ^ kx));
                #pragma unroll
                for (int nt = 0; nt < 2; nt++)
                    ldsm4(bh[nt], so + (baB[nt] ^ kx));
                // single sweep, 16 independent accumulators
                #pragma unroll
                for (int mi = 0; mi < 4; mi++)
                    #pragma unroll
                    for (int ni = 0; ni < 4; ni++)
                        mma16816(acc[mi][ni], ah[mi], &bh[ni >> 1][(ni & 1) * 2]);
            }
        }

        // ---- epilogue ----
        #pragma unroll
        for (int mi = 0; mi < 4; mi++) {
            #pragma unroll
            for (int ni = 0; ni < 4; ni++) {
                int row = bm + wm + mi * 16 + (lane >> 2);
                int col = bn + wn + ni * 8 + (lane & 3) * 2;
                if (J.Cf) {
                    float2 v0 = make_float2(acc[mi][ni][0], acc[mi][ni][1]);
                    float2 v1 = make_float2(acc[mi][ni][2], acc[mi][ni][3]);
                    float b0 = __ldg(J.bias + col), b1 = __ldg(J.bias + col + 1);
                    v0.x += b0; v0.y += b1; v1.x += b0; v1.y += b1;
                    *(float2*)&J.Cf[(size_t)row * EMB + col] = v0;
                    *(float2*)&J.Cf[(size_t)(row + 8) * EMB + col] = v1;
                } else {
                    *(uint32_t*)&J.Ch[(size_t)row * EMB + col] =
                        pack_h(acc[mi][ni][0], acc[mi][ni][1]);
                    *(uint32_t*)&J.Ch[(size_t)(row + 8) * EMB + col] =
                        pack_h(acc[mi][ni][2], acc[mi][ni][3]);
                }
            }
        }
    }
}

// ===========================================================================
// Single-fp16 flash attention on the ROUND-10 memory skeleton:
// stage = 32KB (Kh@0 | Vh@16K), 3 stages (96KB). Q staged @0 (16KB).
// ===========================================================================
#define ASTG 32768
#define ANST 3
#define ASMEM (ANST * ASTG)

__global__ __launch_bounds__(256, 1) void attn_mma_kernel(
    const __half* __restrict__ Qh, const __half* __restrict__ Kh,
    const __half* __restrict__ Vh, const int* __restrict__ cnt,
    __half* __restrict__ Ch)
{
    extern __shared__ __align__(1024) char smem[];
    const uint32_t sb = smem_u32_of(smem);
    const int t = threadIdx.x, w = t >> 5, lane = t & 31;
    const int qt = blockIdx.x, bh = blockIdx.y;
    const int b = bh >> 4, h = bh & 15;
    const int q0 = qt * 128;
    const int hcol = h * 64;
    const int n = cnt[b];
    const int ntiles = (n + 63) >> 6;

    // ---- stage Q (hi only, 16KB @0), extract frags ----
    {
        const size_t qbase = ((size_t)(b * S_LEN + q0)) * EMB + hcol;
        #pragma unroll
        for (int i = 0; i < 4; i++) {
            int u = t + 256 * i;          // 0..1023
            int r = u >> 3;
            int du = u & 7;
            uint32_t off = r * 128 + du * 16;
            uint32_t sw = off ^ ((off >> 3) & 0x70);
            cp16(sb + sw, Qh + qbase + (size_t)r * EMB + du * 8);
        }
        CP_COMMIT();
    }
    cp_wait<0>();
    __syncthreads();

    uint32_t qf[4][4];
    {
        uint32_t off = (uint32_t)(w * 16 + (lane & 15)) * 128 + ((lane >> 4) * 16);
        uint32_t baQ = off ^ ((off >> 3) & 0x70);
        #pragma unroll
        for (int k16 = 0; k16 < 4; k16++)
            ldsm4(qf[k16], sb + (baQ ^ (uint32_t)(k16 * 32)));
    }
    __syncthreads();

    uint32_t baK, baV;
    {
        uint32_t keyk = (uint32_t)((lane & 7) | ((lane & 16) >> 1));
        uint32_t offk = keyk * 128 + (uint32_t)((lane & 8) << 1);
        baK = offk ^ ((offk >> 3) & 0x70);
        uint32_t keyv = (uint32_t)(lane & 15);
        uint32_t offv = keyv * 128 + (uint32_t)((lane >> 4) * 16);
        baV = offv ^ ((offv >> 3) & 0x70);
    }

    auto load_tile = [&](int kt, int stg) {
        const size_t gk = ((size_t)(b * S_LEN + kt * 64)) * EMB + hcol;
        const uint32_t sdst = sb + (uint32_t)stg * ASTG;
        #pragma unroll
        for (int i = 0; i < 4; i++) {
            int u = t + 256 * i;          // 0..1023
            int arr = u >> 9;             // 0 Kh, 1 Vh
            int r = (u >> 3) & 63;
            int du = u & 7;
            uint32_t off = r * 128 + du * 16;
            uint32_t sw = off ^ ((off >> 3) & 0x70);
            const __half* p = arr ? Vh : Kh;
            cp16(sdst + (uint32_t)arr * 16384u + sw, p + gk + (size_t)r * EMB + du * 8);
        }
        CP_COMMIT();
    };

    float O[8][4];
    #pragma unroll
    for (int j = 0; j < 8; j++)
        #pragma unroll
        for (int r = 0; r < 4; r++) O[j][r] = 0.0f;
    float m0 = -1e30f, m1 = -1e30f, l0 = 0.0f, l1 = 0.0f;

    if (ntiles == 0) {
        size_t row0 = (size_t)(b * S_LEN + q0 + w * 16 + (lane >> 2));
        #pragma unroll
        for (int j = 0; j < 8; j++) {
            int col = hcol + j * 8 + (lane & 3) * 2;
            *(uint32_t*)&Ch[row0 * EMB + col] = 0u;
            *(uint32_t*)&Ch[(row0 + 8) * EMB + col] = 0u;
        }
        return;
    }

    load_tile(0, 0);
    if (ntiles > 1) load_tile(1, 1);

    for (int kt = 0; kt < ntiles; kt++) {
        if (kt + 1 < ntiles) { cp_wait<1>(); } else { cp_wait<0>(); }
        __syncthreads();
        if (kt + 2 < ntiles) load_tile(kt + 2, (kt + 2) % ANST);

        const uint32_t so = sb + (uint32_t)(kt % ANST) * ASTG;

        // ---- scores = Q K^T (single term) ----
        float sc[8][4];
        #pragma unroll
        for (int j = 0; j < 8; j++)
            #pragma unroll
            for (int r = 0; r < 4; r++) sc[j][r] = 0.0f;

        #pragma unroll
        for (int k16 = 0; k16 < 4; k16++) {
            const uint32_t kx = (uint32_t)(k16 * 32);
            uint32_t kf[4][4];
            #pragma unroll
            for (int np = 0; np < 4; np++)
                ldsm4(kf[np], so + ((baK + (uint32_t)np * 2048u) ^ kx));
            #pragma unroll
            for (int np = 0; np < 4; np++) {
                mma16816(sc[2 * np],     qf[k16], &kf[np][0]);
                mma16816(sc[2 * np + 1], qf[k16], &kf[np][2]);
            }
        }

        // ---- scale + boundary mask + online softmax ----
        const int c0 = (lane & 3) * 2;
        const int limit = n - kt * 64;
        float rm0 = m0, rm1 = m1;
        #pragma unroll
        for (int j = 0; j < 8; j++) {
            int kc = j * 8 + c0;
            bool v0 = kc < limit, v1 = kc + 1 < limit;
            sc[j][0] = v0 ? sc[j][0] * 0.125f : -1e10f;
            sc[j][1] = v1 ? sc[j][1] * 0.125f : -1e10f;
            sc[j][2] = v0 ? sc[j][2] * 0.125f : -1e10f;
            sc[j][3] = v1 ? sc[j][3] * 0.125f : -1e10f;
            rm0 = fmaxf(rm0, fmaxf(sc[j][0], sc[j][1]));
            rm1 = fmaxf(rm1, fmaxf(sc[j][2], sc[j][3]));
        }
        rm0 = fmaxf(rm0, __shfl_xor_sync(0xffffffffu, rm0, 1));
        rm0 = fmaxf(rm0, __shfl_xor_sync(0xffffffffu, rm0, 2));
        rm1 = fmaxf(rm1, __shfl_xor_sync(0xffffffffu, rm1, 1));
        rm1 = fmaxf(rm1, __shfl_xor_sync(0xffffffffu, rm1, 2));
        float corr0 = __expf(m0 - rm0);
        float corr1 = __expf(m1 - rm1);
        m0 = rm0; m1 = rm1;
        float ls0 = 0.0f, ls1 = 0.0f;
        #pragma unroll
        for (int j = 0; j < 8; j++) {
            sc[j][0] = __expf(sc[j][0] - m0);
            sc[j][1] = __expf(sc[j][1] - m0);
            sc[j][2] = __expf(sc[j][2] - m1);
            sc[j][3] = __expf(sc[j][3] - m1);
            ls0 += sc[j][0] + sc[j][1];
            ls1 += sc[j][2] + sc[j][3];
        }
        ls0 += __shfl_xor_sync(0xffffffffu, ls0, 1);
        ls0 += __shfl_xor_sync(0xffffffffu, ls0, 2);
        ls1 += __shfl_xor_sync(0xffffffffu, ls1, 1);
        ls1 += __shfl_xor_sync(0xffffffffu, ls1, 2);
        l0 = l0 * corr0 + ls0;
        l1 = l1 * corr1 + ls1;
        #pragma unroll
        for (int j = 0; j < 8; j++) {
            O[j][0] *= corr0; O[j][1] *= corr0;
            O[j][2] *= corr1; O[j][3] *= corr1;
        }

        // ---- pack P into fp16 a-frags (single) ----
        uint32_t pf[4][4];
        #pragma unroll
        for (int kb = 0; kb < 4; kb++) {
            pf[kb][0] = pack_h(sc[2 * kb][0],     sc[2 * kb][1]);
            pf[kb][1] = pack_h(sc[2 * kb][2],     sc[2 * kb][3]);
            pf[kb][2] = pack_h(sc[2 * kb + 1][0], sc[2 * kb + 1][1]);
            pf[kb][3] = pack_h(sc[2 * kb + 1][2], sc[2 * kb + 1][3]);
        }

        // ---- O += P V (single term), V via ldmatrix.trans ----
        #pragma unroll
        for (int kb = 0; kb < 4; kb++) {
            const uint32_t kadd = (uint32_t)kb * 2048u;
            uint32_t vf[4][4];
            #pragma unroll
            for (int dp = 0; dp < 4; dp++) {
                const uint32_t dx = (uint32_t)(dp * 32);
                ldsm4t(vf[dp], so + 16384u + ((baV + kadd) ^ dx));
            }
            #pragma unroll
            for (int dp = 0; dp < 4; dp++) {
                mma16816(O[2 * dp],     pf[kb], &vf[dp][0]);
                mma16816(O[2 * dp + 1], pf[kb], &vf[dp][2]);
            }
        }
    }

    // ---- epilogue: O/l -> fp16 Ctx ----
    float inv0 = 1.0f / l0, inv1 = 1.0f / l1;
    size_t row0 = (size_t)(b * S_LEN + q0 + w * 16 + (lane >> 2));
    size_t row1 = row0 + 8;
    #pragma unroll
    for (int j = 0; j < 8; j++) {
        int col = hcol + j * 8 + (lane & 3) * 2;
        *(uint32_t*)&Ch[row0 * EMB + col] = pack_h(O[j][0] * inv0, O[j][1] * inv0);
        *(uint32_t*)&Ch[row1 * EMB + col] = pack_h(O[j][2] * inv1, O[j][3] * inv1);
    }
}

// ===========================================================================
// Launch
// ===========================================================================
extern "C" void kernel_launch(void* const* d_in, const int* in_sizes, int n_in,
                              void* d_out, int out_size)
{
    const float* q    = (const float*)d_in[0];
    const float* k    = (const float*)d_in[1];
    const float* v    = (const float*)d_in[2];
    const int*   mask = (const int*)  d_in[3];
    const float* Wq   = (const float*)d_in[4];
    const float* Wk   = (const float*)d_in[5];
    const float* Wv   = (const float*)d_in[6];
    const float* Wo   = (const float*)d_in[7];
    const float* bo   = (const float*)d_in[8];
    float* out = (float*)d_out;

    __half *Aqh, *Akh, *Avh, *Bqh, *Bkh, *Bvh, *Boh;
    __half *Qh, *Kh, *Vh, *Ch;
    int *idx, *cnt;
    cudaGetSymbolAddress((void**)&Aqh, g_Aqh);
    cudaGetSymbolAddress((void**)&Akh, g_Akh);
    cudaGetSymbolAddress((void**)&Avh, g_Avh);
    cudaGetSymbolAddress((void**)&Bqh, g_Bqh);
    cudaGetSymbolAddress((void**)&Bkh, g_Bkh);
    cudaGetSymbolAddress((void**)&Bvh, g_Bvh);
    cudaGetSymbolAddress((void**)&Boh, g_Boh);
    cudaGetSymbolAddress((void**)&Qh,  g_Qh);
    cudaGetSymbolAddress((void**)&Kh,  g_Kh);
    cudaGetSymbolAddress((void**)&Vh,  g_Vh);
    cudaGetSymbolAddress((void**)&Ch,  g_Ch);
    cudaGetSymbolAddress((void**)&idx, g_idx);
    cudaGetSymbolAddress((void**)&cnt, g_cnt);

    cudaFuncSetAttribute(gemm1p_kernel,
                         cudaFuncAttributeMaxDynamicSharedMemorySize, GSMEM);
    cudaFuncSetAttribute(attn_mma_kernel,
                         cudaFuncAttributeMaxDynamicSharedMemorySize, ASMEM);

    int sms = 148;
    {
        int dev = 0;
        cudaGetDevice(&dev);
        cudaDeviceGetAttribute(&sms, cudaDevAttrMultiProcessorCount, dev);
    }

    const int nA4 = MROWS * EMB / 4;
    const int nW4 = EMB * EMB / 4;

    // 1. mask compaction
    mask_compact_kernel<<<BATCH, 1024>>>(mask, idx, cnt);

    // 2. input conversions (fp16, hi only)
    dim3 gIn(nA4 / 256, 1, 3);
    cvt_inputs_kernel<<<gIn, 256>>>(q, k, v, idx, cnt, Aqh, Akh, Avh);

    // 3. weight conversions
    WJobs wj;
    wj.s[0] = Wq; wj.h[0] = Bqh;
    wj.s[1] = Wk; wj.h[1] = Bkh;
    wj.s[2] = Wv; wj.h[2] = Bvh;
    wj.s[3] = Wo; wj.h[3] = Boh;
    dim3 gW(nW4 / 256, 1, 4);
    cvt_weights_kernel<<<gW, 256>>>(wj);

    // 4. merged persistent Q/K/V projections
    GJobs gj;
    gj.j[0].Ah = Aqh; gj.j[0].Bh = Bqh; gj.j[0].Ch = Qh;
    gj.j[0].Cf = nullptr; gj.j[0].bias = nullptr; gj.j[0].cnt = nullptr;
    gj.j[1].Ah = Akh; gj.j[1].Bh = Bkh; gj.j[1].Ch = Kh;
    gj.j[1].Cf = nullptr; gj.j[1].bias = nullptr; gj.j[1].cnt = cnt;
    gj.j[2].Ah = Avh; gj.j[2].Bh = Bvh; gj.j[2].Ch = Vh;
    gj.j[2].Cf = nullptr; gj.j[2].bias = nullptr; gj.j[2].cnt = cnt;
    gj.n = 3;
    gemm1p_kernel<<<sms, 256, GSMEM>>>(gj);

    // 5. attention over compacted keys
    dim3 gAttn(S_LEN / 128, BATCH * NHEAD);   // (16, 64)
    attn_mma_kernel<<<gAttn, 256, ASMEM>>>(Qh, Kh, Vh, cnt, Ch);

    // 6. persistent output projection (+bias) -> fp32
    GJobs go;
    go.j[0].Ah = Ch; go.j[0].Bh = Boh; go.j[0].Ch = nullptr;
    go.j[0].Cf = out; go.j[0].bias = bo; go.j[0].cnt = nullptr;
    go.j[1] = go.j[0];
    go.j[2] = go.j[0];
    go.n = 1;
    gemm1p_kernel<<<sms, 256, GSMEM>>>(go);
}

// round 12
// speedup vs baseline: 2.2584x; 1.1332x over previous
#include <cuda_runtime.h>
#include <cuda_fp16.h>
#include <cstdint>

// ===========================================================================
// mma.sync / ldmatrix / cp.async helpers (base sm_103 target — no tcgen05)
// ===========================================================================
__device__ __forceinline__ uint32_t smem_u32_of(const void* p) {
    uint32_t a;
    asm("{ .reg .u64 t; cvta.to.shared.u64 t, %1; cvt.u32.u64 %0, t; }"
        : "=r"(a) : "l"(p));
    return a;
}
__device__ __forceinline__ void ldsm4(uint32_t r[4], uint32_t addr) {
    asm volatile("ldmatrix.sync.aligned.m8n8.x4.shared.b16 {%0,%1,%2,%3}, [%4];"
        : "=r"(r[0]), "=r"(r[1]), "=r"(r[2]), "=r"(r[3]) : "r"(addr));
}
__device__ __forceinline__ void ldsm4t(uint32_t r[4], uint32_t addr) {
    asm volatile("ldmatrix.sync.aligned.m8n8.x4.trans.shared.b16 {%0,%1,%2,%3}, [%4];"
        : "=r"(r[0]), "=r"(r[1]), "=r"(r[2]), "=r"(r[3]) : "r"(addr));
}
// fp16 inputs, fp32 accumulate
__device__ __forceinline__ void mma16816(float c[4], const uint32_t a[4],
                                         const uint32_t b[2]) {
    asm volatile(
        "mma.sync.aligned.m16n8k16.row.col.f32.f16.f16.f32 "
        "{%0,%1,%2,%3}, {%4,%5,%6,%7}, {%8,%9}, {%0,%1,%2,%3};"
        : "+f"(c[0]), "+f"(c[1]), "+f"(c[2]), "+f"(c[3])
        : "r"(a[0]), "r"(a[1]), "r"(a[2]), "r"(a[3]), "r"(b[0]), "r"(b[1]));
}
__device__ __forceinline__ void cp16(uint32_t dst, const void* src) {
    asm volatile("cp.async.cg.shared.global [%0], [%1], 16;" :: "r"(dst), "l"(src));
}
#define CP_COMMIT() asm volatile("cp.async.commit_group;" ::: "memory")
template <int N>
__device__ __forceinline__ void cp_wait() {
    asm volatile("cp.async.wait_group %0;" :: "n"(N) : "memory");
}

__device__ __forceinline__ uint32_t pack_h(float a, float b) {
    __half2 h2 = __floats2half2_rn(a, b);
    return *(uint32_t*)&h2;
}

// ===========================================================================
// Problem constants
// ===========================================================================
#define BATCH   4
#define S_LEN   2048
#define EMB     1024
#define NHEAD   16
#define DHEAD   64
#define MROWS   (BATCH * S_LEN)   // 8192

// Scratch (device globals — allocations forbidden)
__device__ __half g_Aqh[MROWS * EMB];
__device__ __half g_Akh[MROWS * EMB];
__device__ __half g_Avh[MROWS * EMB];
__device__ __half g_Bqh[EMB * EMB];
__device__ __half g_Bkh[EMB * EMB];
__device__ __half g_Bvh[EMB * EMB];
__device__ __half g_Boh[EMB * EMB];
__device__ __half g_Qh[MROWS * EMB];
__device__ __half g_Kh[MROWS * EMB];
__device__ __half g_Vh[MROWS * EMB];
__device__ __half g_Ch[MROWS * EMB];
__device__ int g_idx[BATCH * S_LEN];
__device__ int g_cnt[BATCH];

// ===========================================================================
// Stable mask compaction (unchanged, proven)
// ===========================================================================
__global__ __launch_bounds__(1024) void mask_compact_kernel(
    const int* __restrict__ mask, int* __restrict__ idx, int* __restrict__ cnt)
{
    const int b = blockIdx.x, t = threadIdx.x;
    const int wid = t >> 5, lane = t & 31;
    __shared__ int wsum[32], woff[32], chunk_total;
    int base = 0;
    #pragma unroll
    for (int half = 0; half < 2; half++) {
        int e = half * 1024 + t;
        int m = mask[b * S_LEN + e];
        unsigned bal = __ballot_sync(0xffffffffu, m != 0);
        int wtot = __popc(bal);
        int pos  = __popc(bal & ((1u << lane) - 1u));
        if (lane == 0) wsum[wid] = wtot;
        __syncthreads();
        if (t < 32) {
            int v = wsum[t], s = v;
            #pragma unroll
            for (int o = 1; o < 32; o <<= 1) {
                int u = __shfl_up_sync(0xffffffffu, s, o);
                if (t >= o) s += u;
            }
            woff[t] = s - v;
            if (t == 31) chunk_total = s;
        }
        __syncthreads();
        if (m) idx[b * S_LEN + base + woff[wid] + pos] = e;
        base += chunk_total;
        __syncthreads();
    }
    if (t == 0) cnt[b] = base;
}

// ===========================================================================
// Merged input conversion (hi only): z=0 dense q, z=1 gather k, z=2 gather v
// ===========================================================================
__global__ __launch_bounds__(256) void cvt_inputs_kernel(
    const float* __restrict__ q, const float* __restrict__ k,
    const float* __restrict__ v,
    const int* __restrict__ idx, const int* __restrict__ cnt,
    __half* __restrict__ qh, __half* __restrict__ kh, __half* __restrict__ vh)
{
    const int z = blockIdx.z;
    const float* src = (z == 0) ? q : ((z == 1) ? k : v);
    __half* H = (z == 0) ? qh : ((z == 1) ? kh : vh);
    int i = blockIdx.x * blockDim.x + threadIdx.x;
    if (z == 0) {
        float4 x = ((const float4*)src)[i];
        ((uint2*)H)[i] = make_uint2(pack_h(x.x, x.y), pack_h(x.z, x.w));
    } else {
        int rowq = i >> 8;
        int c4 = i & 255;
        int b = rowq >> 11, r = rowq & 2047;
        uint2 hh = make_uint2(0u, 0u);
        if (r < cnt[b]) {
            int s = idx[b * S_LEN + r];
            float4 x = ((const float4*)(src + ((size_t)(b * S_LEN + s)) * EMB))[c4];
            hh = make_uint2(pack_h(x.x, x.y), pack_h(x.z, x.w));
        }
        ((uint2*)H)[(size_t)rowq * 256 + c4] = hh;
    }
}

// ===========================================================================
// Merged weight conversion: hi only
// ===========================================================================
struct WJobs {
    const float* s[4];
    __half* h[4];
};

__global__ __launch_bounds__(256) void cvt_weights_kernel(WJobs wj)
{
    const int z = blockIdx.z;
    int i = blockIdx.x * blockDim.x + threadIdx.x;
    float4 x = ((const float4*)wj.s[z])[i];
    ((uint2*)wj.h[z])[i] = make_uint2(pack_h(x.x, x.y), pack_h(x.z, x.w));
}

// ===========================================================================
// Persistent multi-job single-fp16 GEMM, CTA 256x128, 8 warps of 64x64.
// Stage = 48KB (A 32KB @0 | B 16KB @32768), 3 stages (144KB).
// Same swizzle/address formulas as round 11; only tile multiplicities change.
// ===========================================================================
#define CHUNKS 16
#define STG_BYTES 49152
#define NSTAGE 3
#define GSMEM (NSTAGE * STG_BYTES)    // 147456

struct GJob {
    const __half* Ah;
    const __half* Bh;
    __half* Ch;                       // fp16 output (null if Cf used)
    float* Cf;                        // fp32 output (+bias)
    const float* bias;
    const int* cnt;
};
struct GJobs { GJob j[3]; int n; };

__global__ __launch_bounds__(256, 1) void gemm1p_kernel(GJobs jobs)
{
    extern __shared__ __align__(1024) char smem[];
    const uint32_t sb = smem_u32_of(smem);
    const int t = threadIdx.x;
    const int w = t >> 5, lane = t & 31;
    const int wm = (w >> 1) * 64;       // 0,64,128,192
    const int wn = (w & 1) * 64;        // 0,64

    // loader maps: A 8x16B/thread (256x64 fp16 = 32KB), B 4x16B (128x64 = 16KB)
    uint32_t lswA[8]; uint32_t lgoA[8];
    #pragma unroll
    for (int i = 0; i < 8; i++) {
        int u = t + 256 * i;            // 0..2047
        int row = u >> 3, ku = u & 7;
        uint32_t off = row * 128 + ku * 16;
        lswA[i] = off ^ ((off >> 3) & 0x70);
        lgoA[i] = (uint32_t)row * EMB + ku * 8;
    }
    uint32_t lswB[4]; uint32_t lgoB[4];
    #pragma unroll
    for (int i = 0; i < 4; i++) {
        int u = t + 256 * i;            // 0..1023
        int row = u >> 3, ku = u & 7;
        uint32_t off = row * 128 + ku * 16;
        lswB[i] = off ^ ((off >> 3) & 0x70);
        lgoB[i] = (uint32_t)row * EMB + ku * 8;
    }

    const uint32_t xr  = (lane & 7) << 4;
    const uint32_t ak0 = (uint32_t)(lane & 16) ^ xr;
    const int      arow = lane & 15;
    const uint32_t bk0 = (uint32_t)((lane & 8) << 1) ^ xr;
    const int      brow = (lane & 7) | ((lane & 16) >> 1);
    uint32_t baA[4], baB[4];
    #pragma unroll
    for (int mi = 0; mi < 4; mi++)
        baA[mi] = (uint32_t)(wm + mi * 16 + arow) * 128 + ak0;
    #pragma unroll
    for (int nt = 0; nt < 4; nt++)
        baB[nt] = 32768u + (uint32_t)(wn + nt * 16 + brow) * 128 + bk0;

    const int total = jobs.n << 8;      // 256 tiles per job
    for (int tile = blockIdx.x; tile < total; tile += gridDim.x) {
        const GJob J = jobs.j[tile >> 8];
        const int within = tile & 255;
        const int bm = (within >> 3) * 256;   // 0..7936
        const int bn = (within & 7) * 128;
        if (J.cnt && (bm & 2047) >= J.cnt[bm >> 11]) continue;

        const __half* gAh = J.Ah + (size_t)bm * EMB;
        const __half* gBh = J.Bh + (size_t)bn * EMB;

        float acc[4][8][4];
        #pragma unroll
        for (int mi = 0; mi < 4; mi++)
            #pragma unroll
            for (int ni = 0; ni < 8; ni++)
                #pragma unroll
                for (int r = 0; r < 4; r++) acc[mi][ni][r] = 0.0f;

        auto load_chunk = [&](int c) {
            const uint32_t so = sb + (uint32_t)(c % NSTAGE) * STG_BYTES;
            const uint32_t ko = (uint32_t)c * 64;
            #pragma unroll
            for (int i = 0; i < 8; i++)
                cp16(so + lswA[i], gAh + lgoA[i] + ko);
            #pragma unroll
            for (int i = 0; i < 4; i++)
                cp16(so + 32768u + lswB[i], gBh + lgoB[i] + ko);
            CP_COMMIT();
        };

        __syncthreads();   // previous tile's compute done before stage reuse
        load_chunk(0);
        load_chunk(1);

        for (int c = 0; c < CHUNKS; c++) {
            if (c + 1 < CHUNKS) { cp_wait<1>(); } else { cp_wait<0>(); }
            __syncthreads();
            if (c + 2 < CHUNKS) load_chunk(c + 2);

            const uint32_t so = sb + (uint32_t)(c % NSTAGE) * STG_BYTES;
            #pragma unroll
            for (int ks = 0; ks < 4; ks++) {
                const uint32_t kx = (uint32_t)ks << 5;
                uint32_t ah[4][4], bh[4][4];
                #pragma unroll
                for (int mi = 0; mi < 4; mi++)
                    ldsm4(ah[mi], so + (baA[mi] ^ kx));
                #pragma unroll
                for (int nt = 0; nt < 4; nt++)
                    ldsm4(bh[nt], so + (baB[nt] ^ kx));
                // 32 independent accumulators per sweep
                #pragma unroll
                for (int mi = 0; mi < 4; mi++)
                    #pragma unroll
                    for (int ni = 0; ni < 8; ni++)
                        mma16816(acc[mi][ni], ah[mi], &bh[ni >> 1][(ni & 1) * 2]);
            }
        }

        // ---- epilogue ----
        #pragma unroll
        for (int mi = 0; mi < 4; mi++) {
            #pragma unroll
            for (int ni = 0; ni < 8; ni++) {
                int row = bm + wm + mi * 16 + (lane >> 2);
                int col = bn + wn + ni * 8 + (lane & 3) * 2;
                if (J.Cf) {
                    float2 v0 = make_float2(acc[mi][ni][0], acc[mi][ni][1]);
                    float2 v1 = make_float2(acc[mi][ni][2], acc[mi][ni][3]);
                    float b0 = __ldg(J.bias + col), b1 = __ldg(J.bias + col + 1);
                    v0.x += b0; v0.y += b1; v1.x += b0; v1.y += b1;
                    *(float2*)&J.Cf[(size_t)row * EMB + col] = v0;
                    *(float2*)&J.Cf[(size_t)(row + 8) * EMB + col] = v1;
                } else {
                    *(uint32_t*)&J.Ch[(size_t)row * EMB + col] =
                        pack_h(acc[mi][ni][0], acc[mi][ni][1]);
                    *(uint32_t*)&J.Ch[(size_t)(row + 8) * EMB + col] =
                        pack_h(acc[mi][ni][2], acc[mi][ni][3]);
                }
            }
        }
    }
}

// ===========================================================================
// Single-fp16 flash attention, Br=256 (each of 8 warps owns 32 q-rows).
// K/V ring byte-identical to round 11: stage 32KB (Kh@0 | Vh@16K), 3 stages.
// ===========================================================================
#define ASTG 32768
#define ANST 3
#define ASMEM (ANST * ASTG)

__global__ __launch_bounds__(256, 1) void attn_mma_kernel(
    const __half* __restrict__ Qh, const __half* __restrict__ Kh,
    const __half* __restrict__ Vh, const int* __restrict__ cnt,
    __half* __restrict__ Ch)
{
    extern __shared__ __align__(1024) char smem[];
    const uint32_t sb = smem_u32_of(smem);
    const int t = threadIdx.x, w = t >> 5, lane = t & 31;
    const int qt = blockIdx.x, bh = blockIdx.y;
    const int b = bh >> 4, h = bh & 15;
    const int q0 = qt * 256;
    const int hcol = h * 64;
    const int n = cnt[b];
    const int ntiles = (n + 63) >> 6;

    // ---- stage Q (256x64 fp16 = 32KB @0), extract frags, region reused ----
    {
        const size_t qbase = ((size_t)(b * S_LEN + q0)) * EMB + hcol;
        #pragma unroll
        for (int i = 0; i < 8; i++) {
            int u = t + 256 * i;          // 0..2047
            int r = u >> 3;               // 0..255
            int du = u & 7;
            uint32_t off = r * 128 + du * 16;
            uint32_t sw = off ^ ((off >> 3) & 0x70);
            cp16(sb + sw, Qh + qbase + (size_t)r * EMB + du * 8);
        }
        CP_COMMIT();
    }
    cp_wait<0>();
    __syncthreads();

    uint32_t qf[2][4][4];
    #pragma unroll
    for (int rb = 0; rb < 2; rb++) {
        uint32_t rowq = (uint32_t)(w * 32 + rb * 16 + (lane & 15));
        uint32_t off = rowq * 128 + (uint32_t)((lane >> 4) * 16);
        uint32_t baQ = off ^ ((off >> 3) & 0x70);
        #pragma unroll
        for (int k16 = 0; k16 < 4; k16++)
            ldsm4(qf[rb][k16], sb + (baQ ^ (uint32_t)(k16 * 32)));
    }
    __syncthreads();

    uint32_t baK, baV;
    {
        uint32_t keyk = (uint32_t)((lane & 7) | ((lane & 16) >> 1));
        uint32_t offk = keyk * 128 + (uint32_t)((lane & 8) << 1);
        baK = offk ^ ((offk >> 3) & 0x70);
        uint32_t keyv = (uint32_t)(lane & 15);
        uint32_t offv = keyv * 128 + (uint32_t)((lane >> 4) * 16);
        baV = offv ^ ((offv >> 3) & 0x70);
    }

    auto load_tile = [&](int kt, int stg) {
        const size_t gk = ((size_t)(b * S_LEN + kt * 64)) * EMB + hcol;
        const uint32_t sdst = sb + (uint32_t)stg * ASTG;
        #pragma unroll
        for (int i = 0; i < 4; i++) {
            int u = t + 256 * i;          // 0..1023
            int arr = u >> 9;             // 0 Kh, 1 Vh
            int r = (u >> 3) & 63;
            int du = u & 7;
            uint32_t off = r * 128 + du * 16;
            uint32_t sw = off ^ ((off >> 3) & 0x70);
            const __half* p = arr ? Vh : Kh;
            cp16(sdst + (uint32_t)arr * 16384u + sw, p + gk + (size_t)r * EMB + du * 8);
        }
        CP_COMMIT();
    };

    float O[2][8][4];
    #pragma unroll
    for (int rb = 0; rb < 2; rb++)
        #pragma unroll
        for (int j = 0; j < 8; j++)
            #pragma unroll
            for (int r = 0; r < 4; r++) O[rb][j][r] = 0.0f;
    float m0[2] = { -1e30f, -1e30f }, m1[2] = { -1e30f, -1e30f };
    float l0[2] = { 0.0f, 0.0f }, l1[2] = { 0.0f, 0.0f };

    if (ntiles == 0) {
        #pragma unroll
        for (int rb = 0; rb < 2; rb++) {
            size_t row0 = (size_t)(b * S_LEN + q0 + w * 32 + rb * 16 + (lane >> 2));
            #pragma unroll
            for (int j = 0; j < 8; j++) {
                int col = hcol + j * 8 + (lane & 3) * 2;
                *(uint32_t*)&Ch[row0 * EMB + col] = 0u;
                *(uint32_t*)&Ch[(row0 + 8) * EMB + col] = 0u;
            }
        }
        return;
    }

    load_tile(0, 0);
    if (ntiles > 1) load_tile(1, 1);

    for (int kt = 0; kt < ntiles; kt++) {
        if (kt + 1 < ntiles) { cp_wait<1>(); } else { cp_wait<0>(); }
        __syncthreads();
        if (kt + 2 < ntiles) load_tile(kt + 2, (kt + 2) % ANST);

        const uint32_t so = sb + (uint32_t)(kt % ANST) * ASTG;

        // ---- scores = Q K^T (both row-blocks share K frags) ----
        float sc[2][8][4];
        #pragma unroll
        for (int rb = 0; rb < 2; rb++)
            #pragma unroll
            for (int j = 0; j < 8; j++)
                #pragma unroll
                for (int r = 0; r < 4; r++) sc[rb][j][r] = 0.0f;

        #pragma unroll
        for (int k16 = 0; k16 < 4; k16++) {
            const uint32_t kx = (uint32_t)(k16 * 32);
            uint32_t kf[4][4];
            #pragma unroll
            for (int np = 0; np < 4; np++)
                ldsm4(kf[np], so + ((baK + (uint32_t)np * 2048u) ^ kx));
            #pragma unroll
            for (int np = 0; np < 4; np++)
                #pragma unroll
                for (int rb = 0; rb < 2; rb++) {
                    mma16816(sc[rb][2 * np],     qf[rb][k16], &kf[np][0]);
                    mma16816(sc[rb][2 * np + 1], qf[rb][k16], &kf[np][2]);
                }
        }

        // ---- scale + boundary mask + online softmax (per row-block) ----
        const int c0 = (lane & 3) * 2;
        const int limit = n - kt * 64;
        float corr0[2], corr1[2];
        #pragma unroll
        for (int rb = 0; rb < 2; rb++) {
            float rm0 = m0[rb], rm1 = m1[rb];
            #pragma unroll
            for (int j = 0; j < 8; j++) {
                int kc = j * 8 + c0;
                bool v0 = kc < limit, v1 = kc + 1 < limit;
                sc[rb][j][0] = v0 ? sc[rb][j][0] * 0.125f : -1e10f;
                sc[rb][j][1] = v1 ? sc[rb][j][1] * 0.125f : -1e10f;
                sc[rb][j][2] = v0 ? sc[rb][j][2] * 0.125f : -1e10f;
                sc[rb][j][3] = v1 ? sc[rb][j][3] * 0.125f : -1e10f;
                rm0 = fmaxf(rm0, fmaxf(sc[rb][j][0], sc[rb][j][1]));
                rm1 = fmaxf(rm1, fmaxf(sc[rb][j][2], sc[rb][j][3]));
            }
            rm0 = fmaxf(rm0, __shfl_xor_sync(0xffffffffu, rm0, 1));
            rm0 = fmaxf(rm0, __shfl_xor_sync(0xffffffffu, rm0, 2));
            rm1 = fmaxf(rm1, __shfl_xor_sync(0xffffffffu, rm1, 1));
            rm1 = fmaxf(rm1, __shfl_xor_sync(0xffffffffu, rm1, 2));
            corr0[rb] = __expf(m0[rb] - rm0);
            corr1[rb] = __expf(m1[rb] - rm1);
            m0[rb] = rm0; m1[rb] = rm1;
            float ls0 = 0.0f, ls1 = 0.0f;
            #pragma unroll
            for (int j = 0; j < 8; j++) {
                sc[rb][j][0] = __expf(sc[rb][j][0] - rm0);
                sc[rb][j][1] = __expf(sc[rb][j][1] - rm0);
                sc[rb][j][2] = __expf(sc[rb][j][2] - rm1);
                sc[rb][j][3] = __expf(sc[rb][j][3] - rm1);
                ls0 += sc[rb][j][0] + sc[rb][j][1];
                ls1 += sc[rb][j][2] + sc[rb][j][3];
            }
            ls0 += __shfl_xor_sync(0xffffffffu, ls0, 1);
            ls0 += __shfl_xor_sync(0xffffffffu, ls0, 2);
            ls1 += __shfl_xor_sync(0xffffffffu, ls1, 1);
            ls1 += __shfl_xor_sync(0xffffffffu, ls1, 2);
            l0[rb] = l0[rb] * corr0[rb] + ls0;
            l1[rb] = l1[rb] * corr1[rb] + ls1;
            #pragma unroll
            for (int j = 0; j < 8; j++) {
                O[rb][j][0] *= corr0[rb]; O[rb][j][1] *= corr0[rb];
                O[rb][j][2] *= corr1[rb]; O[rb][j][3] *= corr1[rb];
            }
        }

        // ---- O += P V (pack P per-kb to limit live registers) ----
        #pragma unroll
        for (int kb = 0; kb < 4; kb++) {
            uint32_t pf[2][4];
            #pragma unroll
            for (int rb = 0; rb < 2; rb++) {
                pf[rb][0] = pack_h(sc[rb][2 * kb][0],     sc[rb][2 * kb][1]);
                pf[rb][1] = pack_h(sc[rb][2 * kb][2],     sc[rb][2 * kb][3]);
                pf[rb][2] = pack_h(sc[rb][2 * kb + 1][0], sc[rb][2 * kb + 1][1]);
                pf[rb][3] = pack_h(sc[rb][2 * kb + 1][2], sc[rb][2 * kb + 1][3]);
            }
            const uint32_t kadd = (uint32_t)kb * 2048u;
            uint32_t vf[4][4];
            #pragma unroll
            for (int dp = 0; dp < 4; dp++) {
                const uint32_t dx = (uint32_t)(dp * 32);
                ldsm4t(vf[dp], so + 16384u + ((baV + kadd) ^ dx));
            }
            #pragma unroll
            for (int dp = 0; dp < 4; dp++)
                #pragma unroll
                for (int rb = 0; rb < 2; rb++) {
                    mma16816(O[rb][2 * dp],     pf[rb], &vf[dp][0]);
                    mma16816(O[rb][2 * dp + 1], pf[rb], &vf[dp][2]);
                }
        }
    }

    // ---- epilogue: O/l -> fp16 Ctx ----
    #pragma unroll
    for (int rb = 0; rb < 2; rb++) {
        float inv0 = 1.0f / l0[rb], inv1 = 1.0f / l1[rb];
        size_t row0 = (size_t)(b * S_LEN + q0 + w * 32 + rb * 16 + (lane >> 2));
        size_t row1 = row0 + 8;
        #pragma unroll
        for (int j = 0; j < 8; j++) {
            int col = hcol + j * 8 + (lane & 3) * 2;
            *(uint32_t*)&Ch[row0 * EMB + col] =
                pack_h(O[rb][j][0] * inv0, O[rb][j][1] * inv0);
            *(uint32_t*)&Ch[row1 * EMB + col] =
                pack_h(O[rb][j][2] * inv1, O[rb][j][3] * inv1);
        }
    }
}

// ===========================================================================
// Launch
// ===========================================================================
extern "C" void kernel_launch(void* const* d_in, const int* in_sizes, int n_in,
                              void* d_out, int out_size)
{
    const float* q    = (const float*)d_in[0];
    const float* k    = (const float*)d_in[1];
    const float* v    = (const float*)d_in[2];
    const int*   mask = (const int*)  d_in[3];
    const float* Wq   = (const float*)d_in[4];
    const float* Wk   = (const float*)d_in[5];
    const float* Wv   = (const float*)d_in[6];
    const float* Wo   = (const float*)d_in[7];
    const float* bo   = (const float*)d_in[8];
    float* out = (float*)d_out;

    __half *Aqh, *Akh, *Avh, *Bqh, *Bkh, *Bvh, *Boh;
    __half *Qh, *Kh, *Vh, *Ch;
    int *idx, *cnt;
    cudaGetSymbolAddress((void**)&Aqh, g_Aqh);
    cudaGetSymbolAddress((void**)&Akh, g_Akh);
    cudaGetSymbolAddress((void**)&Avh, g_Avh);
    cudaGetSymbolAddress((void**)&Bqh, g_Bqh);
    cudaGetSymbolAddress((void**)&Bkh, g_Bkh);
    cudaGetSymbolAddress((void**)&Bvh, g_Bvh);
    cudaGetSymbolAddress((void**)&Boh, g_Boh);
    cudaGetSymbolAddress((void**)&Qh,  g_Qh);
    cudaGetSymbolAddress((void**)&Kh,  g_Kh);
    cudaGetSymbolAddress((void**)&Vh,  g_Vh);
    cudaGetSymbolAddress((void**)&Ch,  g_Ch);
    cudaGetSymbolAddress((void**)&idx, g_idx);
    cudaGetSymbolAddress((void**)&cnt, g_cnt);

    cudaFuncSetAttribute(gemm1p_kernel,
                         cudaFuncAttributeMaxDynamicSharedMemorySize, GSMEM);
    cudaFuncSetAttribute(attn_mma_kernel,
                         cudaFuncAttributeMaxDynamicSharedMemorySize, ASMEM);

    int sms = 148;
    {
        int dev = 0;
        cudaGetDevice(&dev);
        cudaDeviceGetAttribute(&sms, cudaDevAttrMultiProcessorCount, dev);
    }

    const int nA4 = MROWS * EMB / 4;
    const int nW4 = EMB * EMB / 4;

    // 1. mask compaction
    mask_compact_kernel<<<BATCH, 1024>>>(mask, idx, cnt);

    // 2. input conversions (fp16, hi only)
    dim3 gIn(nA4 / 256, 1, 3);
    cvt_inputs_kernel<<<gIn, 256>>>(q, k, v, idx, cnt, Aqh, Akh, Avh);

    // 3. weight conversions
    WJobs wj;
    wj.s[0] = Wq; wj.h[0] = Bqh;
    wj.s[1] = Wk; wj.h[1] = Bkh;
    wj.s[2] = Wv; wj.h[2] = Bvh;
    wj.s[3] = Wo; wj.h[3] = Boh;
    dim3 gW(nW4 / 256, 1, 4);
    cvt_weights_kernel<<<gW, 256>>>(wj);

    // 4. merged persistent Q/K/V projections
    GJobs gj;
    gj.j[0].Ah = Aqh; gj.j[0].Bh = Bqh; gj.j[0].Ch = Qh;
    gj.j[0].Cf = nullptr; gj.j[0].bias = nullptr; gj.j[0].cnt = nullptr;
    gj.j[1].Ah = Akh; gj.j[1].Bh = Bkh; gj.j[1].Ch = Kh;
    gj.j[1].Cf = nullptr; gj.j[1].bias = nullptr; gj.j[1].cnt = cnt;
    gj.j[2].Ah = Avh; gj.j[2].Bh = Bvh; gj.j[2].Ch = Vh;
    gj.j[2].Cf = nullptr; gj.j[2].bias = nullptr; gj.j[2].cnt = cnt;
    gj.n = 3;
    gemm1p_kernel<<<sms, 256, GSMEM>>>(gj);

    // 5. attention over compacted keys (Br=256)
    dim3 gAttn(S_LEN / 256, BATCH * NHEAD);   // (8, 64)
    attn_mma_kernel<<<gAttn, 256, ASMEM>>>(Qh, Kh, Vh, cnt, Ch);

    // 6. persistent output projection (+bias) -> fp32
    GJobs go;
    go.j[0].Ah = Ch; go.j[0].Bh = Boh; go.j[0].Ch = nullptr;
    go.j[0].Cf = out; go.j[0].bias = bo; go.j[0].cnt = nullptr;
    go.j[1] = go.j[0];
    go.j[2] = go.j[0];
    go.n = 1;
    gemm1p_kernel<<<sms, 256, GSMEM>>>(go);
}

// round 13
// speedup vs baseline: 2.2963x; 1.0168x over previous
#include <cuda_runtime.h>
#include <cuda_fp16.h>
#include <cstdint>

// ===========================================================================
// mma.sync / ldmatrix / cp.async helpers (base sm_103 target — no tcgen05)
// ===========================================================================
__device__ __forceinline__ uint32_t smem_u32_of(const void* p) {
    uint32_t a;
    asm("{ .reg .u64 t; cvta.to.shared.u64 t, %1; cvt.u32.u64 %0, t; }"
        : "=r"(a) : "l"(p));
    return a;
}
__device__ __forceinline__ void ldsm4(uint32_t r[4], uint32_t addr) {
    asm volatile("ldmatrix.sync.aligned.m8n8.x4.shared.b16 {%0,%1,%2,%3}, [%4];"
        : "=r"(r[0]), "=r"(r[1]), "=r"(r[2]), "=r"(r[3]) : "r"(addr));
}
__device__ __forceinline__ void ldsm4t(uint32_t r[4], uint32_t addr) {
    asm volatile("ldmatrix.sync.aligned.m8n8.x4.trans.shared.b16 {%0,%1,%2,%3}, [%4];"
        : "=r"(r[0]), "=r"(r[1]), "=r"(r[2]), "=r"(r[3]) : "r"(addr));
}
// fp16 inputs, fp32 accumulate
__device__ __forceinline__ void mma16816(float c[4], const uint32_t a[4],
                                         const uint32_t b[2]) {
    asm volatile(
        "mma.sync.aligned.m16n8k16.row.col.f32.f16.f16.f32 "
        "{%0,%1,%2,%3}, {%4,%5,%6,%7}, {%8,%9}, {%0,%1,%2,%3};"
        : "+f"(c[0]), "+f"(c[1]), "+f"(c[2]), "+f"(c[3])
        : "r"(a[0]), "r"(a[1]), "r"(a[2]), "r"(a[3]), "r"(b[0]), "r"(b[1]));
}
__device__ __forceinline__ void cp16(uint32_t dst, const void* src) {
    asm volatile("cp.async.cg.shared.global [%0], [%1], 16;" :: "r"(dst), "l"(src));
}
#define CP_COMMIT() asm volatile("cp.async.commit_group;" ::: "memory")
template <int N>
__device__ __forceinline__ void cp_wait() {
    asm volatile("cp.async.wait_group %0;" :: "n"(N) : "memory");
}

__device__ __forceinline__ uint32_t pack_h(float a, float b) {
    __half2 h2 = __floats2half2_rn(a, b);
    return *(uint32_t*)&h2;
}

// ===========================================================================
// Problem constants
// ===========================================================================
#define BATCH   4
#define S_LEN   2048
#define EMB     1024
#define NHEAD   16
#define DHEAD   64
#define MROWS   (BATCH * S_LEN)   // 8192

// Scratch (device globals — allocations forbidden)
__device__ __half g_Aqh[MROWS * EMB];
__device__ __half g_Akh[MROWS * EMB];
__device__ __half g_Avh[MROWS * EMB];
__device__ __half g_Bqh[EMB * EMB];
__device__ __half g_Bkh[EMB * EMB];
__device__ __half g_Bvh[EMB * EMB];
__device__ __half g_Boh[EMB * EMB];
__device__ __half g_Qh[MROWS * EMB];
__device__ __half g_Kh[MROWS * EMB];
__device__ __half g_Vh[MROWS * EMB];
__device__ __half g_Ch[MROWS * EMB];
__device__ int g_idx[BATCH * S_LEN];
__device__ int g_cnt[BATCH];

// ===========================================================================
// Stable mask compaction (unchanged, proven)
// ===========================================================================
__global__ __launch_bounds__(1024) void mask_compact_kernel(
    const int* __restrict__ mask, int* __restrict__ idx, int* __restrict__ cnt)
{
    const int b = blockIdx.x, t = threadIdx.x;
    const int wid = t >> 5, lane = t & 31;
    __shared__ int wsum[32], woff[32], chunk_total;
    int base = 0;
    #pragma unroll
    for (int half = 0; half < 2; half++) {
        int e = half * 1024 + t;
        int m = mask[b * S_LEN + e];
        unsigned bal = __ballot_sync(0xffffffffu, m != 0);
        int wtot = __popc(bal);
        int pos  = __popc(bal & ((1u << lane) - 1u));
        if (lane == 0) wsum[wid] = wtot;
        __syncthreads();
        if (t < 32) {
            int v = wsum[t], s = v;
            #pragma unroll
            for (int o = 1; o < 32; o <<= 1) {
                int u = __shfl_up_sync(0xffffffffu, s, o);
                if (t >= o) s += u;
            }
            woff[t] = s - v;
            if (t == 31) chunk_total = s;
        }
        __syncthreads();
        if (m) idx[b * S_LEN + base + woff[wid] + pos] = e;
        base += chunk_total;
        __syncthreads();
    }
    if (t == 0) cnt[b] = base;
}

// ===========================================================================
// Merged input conversion (hi only): z=0 dense q, z=1 gather k, z=2 gather v
// ===========================================================================
__global__ __launch_bounds__(256) void cvt_inputs_kernel(
    const float* __restrict__ q, const float* __restrict__ k,
    const float* __restrict__ v,
    const int* __restrict__ idx, const int* __restrict__ cnt,
    __half* __restrict__ qh, __half* __restrict__ kh, __half* __restrict__ vh)
{
    const int z = blockIdx.z;
    const float* src = (z == 0) ? q : ((z == 1) ? k : v);
    __half* H = (z == 0) ? qh : ((z == 1) ? kh : vh);
    int i = blockIdx.x * blockDim.x + threadIdx.x;
    if (z == 0) {
        float4 x = ((const float4*)src)[i];
        ((uint2*)H)[i] = make_uint2(pack_h(x.x, x.y), pack_h(x.z, x.w));
    } else {
        int rowq = i >> 8;
        int c4 = i & 255;
        int b = rowq >> 11, r = rowq & 2047;
        uint2 hh = make_uint2(0u, 0u);
        if (r < cnt[b]) {
            int s = idx[b * S_LEN + r];
            float4 x = ((const float4*)(src + ((size_t)(b * S_LEN + s)) * EMB))[c4];
            hh = make_uint2(pack_h(x.x, x.y), pack_h(x.z, x.w));
        }
        ((uint2*)H)[(size_t)rowq * 256 + c4] = hh;
    }
}

// ===========================================================================
// Merged weight conversion: hi only
// ===========================================================================
struct WJobs {
    const float* s[4];
    __half* h[4];
};

__global__ __launch_bounds__(256) void cvt_weights_kernel(WJobs wj)
{
    const int z = blockIdx.z;
    int i = blockIdx.x * blockDim.x + threadIdx.x;
    float4 x = ((const float4*)wj.s[z])[i];
    ((uint2*)wj.h[z])[i] = make_uint2(pack_h(x.x, x.y), pack_h(x.z, x.w));
}

// ===========================================================================
// Persistent multi-job single-fp16 GEMM, CTA 128x128, 8 warps of 64x32,
// COMPACT 32KB stages (A 16KB @0 | B 16KB @16384), 3 stages = 96KB/CTA,
// __launch_bounds__(256, 2): TWO independent CTAs per SM (cross-CTA overlap).
// Mainloop identical to the proven round-11 version except B base 32768->16384.
// ===========================================================================
#define CHUNKS 16
#define STG_BYTES 32768
#define NSTAGE 3
#define GSMEM (NSTAGE * STG_BYTES)    // 98304/CTA; 2 CTAs = 196608 <= 228KB

struct GJob {
    const __half* Ah;
    const __half* Bh;
    __half* Ch;                       // fp16 output (null if Cf used)
    float* Cf;                        // fp32 output (+bias)
    const float* bias;
    const int* cnt;
};
struct GJobs { GJob j[3]; int n; };

__global__ __launch_bounds__(256, 2) void gemm1p_kernel(GJobs jobs)
{
    extern __shared__ __align__(1024) char smem[];
    const uint32_t sb = smem_u32_of(smem);
    const int t = threadIdx.x;
    const int w = t >> 5, lane = t & 31;
    const int wm = (w >> 2) * 64;
    const int wn = (w & 3) * 32;

    uint32_t lsw[4]; uint32_t lgo[4];
    #pragma unroll
    for (int i = 0; i < 4; i++) {
        int u = t + 256 * i;
        int row = u >> 3, ku = u & 7;
        uint32_t off = row * 128 + ku * 16;
        lsw[i] = off ^ ((off >> 3) & 0x70);
        lgo[i] = (uint32_t)row * EMB + ku * 8;
    }

    const uint32_t xr  = (lane & 7) << 4;
    const uint32_t ak0 = (uint32_t)(lane & 16) ^ xr;
    const int      arow = lane & 15;
    const uint32_t bk0 = (uint32_t)((lane & 8) << 1) ^ xr;
    const int      brow = (lane & 7) | ((lane & 16) >> 1);
    uint32_t baA[4], baB[2];
    #pragma unroll
    for (int mi = 0; mi < 4; mi++)
        baA[mi] = (uint32_t)(wm + mi * 16 + arow) * 128 + ak0;
    #pragma unroll
    for (int nt = 0; nt < 2; nt++)
        baB[nt] = 16384u + (uint32_t)(wn + nt * 16 + brow) * 128 + bk0;

    const int total = jobs.n << 9;      // 512 tiles per job
    for (int tile = blockIdx.x; tile < total; tile += gridDim.x) {
        const GJob J = jobs.j[tile >> 9];
        const int within = tile & 511;
        const int bm = (within >> 3) * 128;
        const int bn = (within & 7) * 128;
        if (J.cnt && (bm & 2047) >= J.cnt[bm >> 11]) continue;

        const __half* gAh = J.Ah + (size_t)bm * EMB;
        const __half* gBh = J.Bh + (size_t)bn * EMB;

        float acc[4][4][4];
        #pragma unroll
        for (int mi = 0; mi < 4; mi++)
            #pragma unroll
            for (int ni = 0; ni < 4; ni++)
                #pragma unroll
                for (int r = 0; r < 4; r++) acc[mi][ni][r] = 0.0f;

        auto load_chunk = [&](int c) {
            const uint32_t so = sb + (uint32_t)(c % NSTAGE) * STG_BYTES;
            const uint32_t ko = (uint32_t)c * 64;
            #pragma unroll
            for (int i = 0; i < 4; i++) {
                cp16(so +      0 + lsw[i], gAh + lgo[i] + ko);
                cp16(so + 16384u + lsw[i], gBh + lgo[i] + ko);
            }
            CP_COMMIT();
        };

        __syncthreads();   // previous tile's compute done before stage reuse
        load_chunk(0);
        load_chunk(1);

        for (int c = 0; c < CHUNKS; c++) {
            if (c + 1 < CHUNKS) { cp_wait<1>(); } else { cp_wait<0>(); }
            __syncthreads();
            if (c + 2 < CHUNKS) load_chunk(c + 2);

            const uint32_t so = sb + (uint32_t)(c % NSTAGE) * STG_BYTES;
            #pragma unroll
            for (int ks = 0; ks < 4; ks++) {
                const uint32_t kx = (uint32_t)ks << 5;
                uint32_t ah[4][4], bh[2][4];
                #pragma unroll
                for (int mi = 0; mi < 4; mi++)
                    ldsm4(ah[mi], so + (baA[mi] ^ kx));
                #pragma unroll
                for (int nt = 0; nt < 2; nt++)
                    ldsm4(bh[nt], so + (baB[nt] ^ kx));
                // single sweep, 16 independent accumulators
                #pragma unroll
                for (int mi = 0; mi < 4; mi++)
                    #pragma unroll
                    for (int ni = 0; ni < 4; ni++)
                        mma16816(acc[mi][ni], ah[mi], &bh[ni >> 1][(ni & 1) * 2]);
            }
        }

        // ---- epilogue ----
        #pragma unroll
        for (int mi = 0; mi < 4; mi++) {
            #pragma unroll
            for (int ni = 0; ni < 4; ni++) {
                int row = bm + wm + mi * 16 + (lane >> 2);
                int col = bn + wn + ni * 8 + (lane & 3) * 2;
                if (J.Cf) {
                    float2 v0 = make_float2(acc[mi][ni][0], acc[mi][ni][1]);
                    float2 v1 = make_float2(acc[mi][ni][2], acc[mi][ni][3]);
                    float b0 = __ldg(J.bias + col), b1 = __ldg(J.bias + col + 1);
                    v0.x += b0; v0.y += b1; v1.x += b0; v1.y += b1;
                    *(float2*)&J.Cf[(size_t)row * EMB + col] = v0;
                    *(float2*)&J.Cf[(size_t)(row + 8) * EMB + col] = v1;
                } else {
                    *(uint32_t*)&J.Ch[(size_t)row * EMB + col] =
                        pack_h(acc[mi][ni][0], acc[mi][ni][1]);
                    *(uint32_t*)&J.Ch[(size_t)(row + 8) * EMB + col] =
                        pack_h(acc[mi][ni][2], acc[mi][ni][3]);
                }
            }
        }
    }
}

// ===========================================================================
// Single-fp16 flash attention, Br=256 — byte-identical to round 12 (proven).
// ===========================================================================
#define ASTG 32768
#define ANST 3
#define ASMEM (ANST * ASTG)

__global__ __launch_bounds__(256, 1) void attn_mma_kernel(
    const __half* __restrict__ Qh, const __half* __restrict__ Kh,
    const __half* __restrict__ Vh, const int* __restrict__ cnt,
    __half* __restrict__ Ch)
{
    extern __shared__ __align__(1024) char smem[];
    const uint32_t sb = smem_u32_of(smem);
    const int t = threadIdx.x, w = t >> 5, lane = t & 31;
    const int qt = blockIdx.x, bh = blockIdx.y;
    const int b = bh >> 4, h = bh & 15;
    const int q0 = qt * 256;
    const int hcol = h * 64;
    const int n = cnt[b];
    const int ntiles = (n + 63) >> 6;

    {
        const size_t qbase = ((size_t)(b * S_LEN + q0)) * EMB + hcol;
        #pragma unroll
        for (int i = 0; i < 8; i++) {
            int u = t + 256 * i;
            int r = u >> 3;
            int du = u & 7;
            uint32_t off = r * 128 + du * 16;
            uint32_t sw = off ^ ((off >> 3) & 0x70);
            cp16(sb + sw, Qh + qbase + (size_t)r * EMB + du * 8);
        }
        CP_COMMIT();
    }
    cp_wait<0>();
    __syncthreads();

    uint32_t qf[2][4][4];
    #pragma unroll
    for (int rb = 0; rb < 2; rb++) {
        uint32_t rowq = (uint32_t)(w * 32 + rb * 16 + (lane & 15));
        uint32_t off = rowq * 128 + (uint32_t)((lane >> 4) * 16);
        uint32_t baQ = off ^ ((off >> 3) & 0x70);
        #pragma unroll
        for (int k16 = 0; k16 < 4; k16++)
            ldsm4(qf[rb][k16], sb + (baQ ^ (uint32_t)(k16 * 32)));
    }
    __syncthreads();

    uint32_t baK, baV;
    {
        uint32_t keyk = (uint32_t)((lane & 7) | ((lane & 16) >> 1));
        uint32_t offk = keyk * 128 + (uint32_t)((lane & 8) << 1);
        baK = offk ^ ((offk >> 3) & 0x70);
        uint32_t keyv = (uint32_t)(lane & 15);
        uint32_t offv = keyv * 128 + (uint32_t)((lane >> 4) * 16);
        baV = offv ^ ((offv >> 3) & 0x70);
    }

    auto load_tile = [&](int kt, int stg) {
        const size_t gk = ((size_t)(b * S_LEN + kt * 64)) * EMB + hcol;
        const uint32_t sdst = sb + (uint32_t)stg * ASTG;
        #pragma unroll
        for (int i = 0; i < 4; i++) {
            int u = t + 256 * i;
            int arr = u >> 9;
            int r = (u >> 3) & 63;
            int du = u & 7;
            uint32_t off = r * 128 + du * 16;
            uint32_t sw = off ^ ((off >> 3) & 0x70);
            const __half* p = arr ? Vh : Kh;
            cp16(sdst + (uint32_t)arr * 16384u + sw, p + gk + (size_t)r * EMB + du * 8);
        }
        CP_COMMIT();
    };

    float O[2][8][4];
    #pragma unroll
    for (int rb = 0; rb < 2; rb++)
        #pragma unroll
        for (int j = 0; j < 8; j++)
            #pragma unroll
            for (int r = 0; r < 4; r++) O[rb][j][r] = 0.0f;
    float m0[2] = { -1e30f, -1e30f }, m1[2] = { -1e30f, -1e30f };
    float l0[2] = { 0.0f, 0.0f }, l1[2] = { 0.0f, 0.0f };

    if (ntiles == 0) {
        #pragma unroll
        for (int rb = 0; rb < 2; rb++) {
            size_t row0 = (size_t)(b * S_LEN + q0 + w * 32 + rb * 16 + (lane >> 2));
            #pragma unroll
            for (int j = 0; j < 8; j++) {
                int col = hcol + j * 8 + (lane & 3) * 2;
                *(uint32_t*)&Ch[row0 * EMB + col] = 0u;
                *(uint32_t*)&Ch[(row0 + 8) * EMB + col] = 0u;
            }
        }
        return;
    }

    load_tile(0, 0);
    if (ntiles > 1) load_tile(1, 1);

    for (int kt = 0; kt < ntiles; kt++) {
        if (kt + 1 < ntiles) { cp_wait<1>(); } else { cp_wait<0>(); }
        __syncthreads();
        if (kt + 2 < ntiles) load_tile(kt + 2, (kt + 2) % ANST);

        const uint32_t so = sb + (uint32_t)(kt % ANST) * ASTG;

        float sc[2][8][4];
        #pragma unroll
        for (int rb = 0; rb < 2; rb++)
            #pragma unroll
            for (int j = 0; j < 8; j++)
                #pragma unroll
                for (int r = 0; r < 4; r++) sc[rb][j][r] = 0.0f;

        #pragma unroll
        for (int k16 = 0; k16 < 4; k16++) {
            const uint32_t kx = (uint32_t)(k16 * 32);
            uint32_t kf[4][4];
            #pragma unroll
            for (int np = 0; np < 4; np++)
                ldsm4(kf[np], so + ((baK + (uint32_t)np * 2048u) ^ kx));
            #pragma unroll
            for (int np = 0; np < 4; np++)
                #pragma unroll
                for (int rb = 0; rb < 2; rb++) {
                    mma16816(sc[rb][2 * np],     qf[rb][k16], &kf[np][0]);
                    mma16816(sc[rb][2 * np + 1], qf[rb][k16], &kf[np][2]);
                }
        }

        const int c0 = (lane & 3) * 2;
        const int limit = n - kt * 64;
        float corr0[2], corr1[2];
        #pragma unroll
        for (int rb = 0; rb < 2; rb++) {
            float rm0 = m0[rb], rm1 = m1[rb];
            #pragma unroll
            for (int j = 0; j < 8; j++) {
                int kc = j * 8 + c0;
                bool v0 = kc < limit, v1 = kc + 1 < limit;
                sc[rb][j][0] = v0 ? sc[rb][j][0] * 0.125f : -1e10f;
                sc[rb][j][1] = v1 ? sc[rb][j][1] * 0.125f : -1e10f;
                sc[rb][j][2] = v0 ? sc[rb][j][2] * 0.125f : -1e10f;
                sc[rb][j][3] = v1 ? sc[rb][j][3] * 0.125f : -1e10f;
                rm0 = fmaxf(rm0, fmaxf(sc[rb][j][0], sc[rb][j][1]));
                rm1 = fmaxf(rm1, fmaxf(sc[rb][j][2], sc[rb][j][3]));
            }
            rm0 = fmaxf(rm0, __shfl_xor_sync(0xffffffffu, rm0, 1));
            rm0 = fmaxf(rm0, __shfl_xor_sync(0xffffffffu, rm0, 2));
            rm1 = fmaxf(rm1, __shfl_xor_sync(0xffffffffu, rm1, 1));
            rm1 = fmaxf(rm1, __shfl_xor_sync(0xffffffffu, rm1, 2));
            corr0[rb] = __expf(m0[rb] - rm0);
            corr1[rb] = __expf(m1[rb] - rm1);
            m0[rb] = rm0; m1[rb] = rm1;
            float ls0 = 0.0f, ls1 = 0.0f;
            #pragma unroll
            for (int j = 0; j < 8; j++) {
                sc[rb][j][0] = __expf(sc[rb][j][0] - rm0);
                sc[rb][j][1] = __expf(sc[rb][j][1] - rm0);
                sc[rb][j][2] = __expf(sc[rb][j][2] - rm1);
                sc[rb][j][3] = __expf(sc[rb][j][3] - rm1);
                ls0 += sc[rb][j][0] + sc[rb][j][1];
                ls1 += sc[rb][j][2] + sc[rb][j][3];
            }
            ls0 += __shfl_xor_sync(0xffffffffu, ls0, 1);
            ls0 += __shfl_xor_sync(0xffffffffu, ls0, 2);
            ls1 += __shfl_xor_sync(0xffffffffu, ls1, 1);
            ls1 += __shfl_xor_sync(0xffffffffu, ls1, 2);
            l0[rb] = l0[rb] * corr0[rb] + ls0;
            l1[rb] = l1[rb] * corr1[rb] + ls1;
            #pragma unroll
            for (int j = 0; j < 8; j++) {
                O[rb][j][0] *= corr0[rb]; O[rb][j][1] *= corr0[rb];
                O[rb][j][2] *= corr1[rb]; O[rb][j][3] *= corr1[rb];
            }
        }

        #pragma unroll
        for (int kb = 0; kb < 4; kb++) {
            uint32_t pf[2][4];
            #pragma unroll
            for (int rb = 0; rb < 2; rb++) {
                pf[rb][0] = pack_h(sc[rb][2 * kb][0],     sc[rb][2 * kb][1]);
                pf[rb][1] = pack_h(sc[rb][2 * kb][2],     sc[rb][2 * kb][3]);
                pf[rb][2] = pack_h(sc[rb][2 * kb + 1][0], sc[rb][2 * kb + 1][1]);
                pf[rb][3] = pack_h(sc[rb][2 * kb + 1][2], sc[rb][2 * kb + 1][3]);
            }
            const uint32_t kadd = (uint32_t)kb * 2048u;
            uint32_t vf[4][4];
            #pragma unroll
            for (int dp = 0; dp < 4; dp++) {
                const uint32_t dx = (uint32_t)(dp * 32);
                ldsm4t(vf[dp], so + 16384u + ((baV + kadd) ^ dx));
            }
            #pragma unroll
            for (int dp = 0; dp < 4; dp++)
                #pragma unroll
                for (int rb = 0; rb < 2; rb++) {
                    mma16816(O[rb][2 * dp],     pf[rb], &vf[dp][0]);
                    mma16816(O[rb][2 * dp + 1], pf[rb], &vf[dp][2]);
                }
        }
    }

    #pragma unroll
    for (int rb = 0; rb < 2; rb++) {
        float inv0 = 1.0f / l0[rb], inv1 = 1.0f / l1[rb];
        size_t row0 = (size_t)(b * S_LEN + q0 + w * 32 + rb * 16 + (lane >> 2));
        size_t row1 = row0 + 8;
        #pragma unroll
        for (int j = 0; j < 8; j++) {
            int col = hcol + j * 8 + (lane & 3) * 2;
            *(uint32_t*)&Ch[row0 * EMB + col] =
                pack_h(O[rb][j][0] * inv0, O[rb][j][1] * inv0);
            *(uint32_t*)&Ch[row1 * EMB + col] =
                pack_h(O[rb][j][2] * inv1, O[rb][j][3] * inv1);
        }
    }
}

// ===========================================================================
// Launch
// ===========================================================================
extern "C" void kernel_launch(void* const* d_in, const int* in_sizes, int n_in,
                              void* d_out, int out_size)
{
    const float* q    = (const float*)d_in[0];
    const float* k    = (const float*)d_in[1];
    const float* v    = (const float*)d_in[2];
    const int*   mask = (const int*)  d_in[3];
    const float* Wq   = (const float*)d_in[4];
    const float* Wk   = (const float*)d_in[5];
    const float* Wv   = (const float*)d_in[6];
    const float* Wo   = (const float*)d_in[7];
    const float* bo   = (const float*)d_in[8];
    float* out = (float*)d_out;

    __half *Aqh, *Akh, *Avh, *Bqh, *Bkh, *Bvh, *Boh;
    __half *Qh, *Kh, *Vh, *Ch;
    int *idx, *cnt;
    cudaGetSymbolAddress((void**)&Aqh, g_Aqh);
    cudaGetSymbolAddress((void**)&Akh, g_Akh);
    cudaGetSymbolAddress((void**)&Avh, g_Avh);
    cudaGetSymbolAddress((void**)&Bqh, g_Bqh);
    cudaGetSymbolAddress((void**)&Bkh, g_Bkh);
    cudaGetSymbolAddress((void**)&Bvh, g_Bvh);
    cudaGetSymbolAddress((void**)&Boh, g_Boh);
    cudaGetSymbolAddress((void**)&Qh,  g_Qh);
    cudaGetSymbolAddress((void**)&Kh,  g_Kh);
    cudaGetSymbolAddress((void**)&Vh,  g_Vh);
    cudaGetSymbolAddress((void**)&Ch,  g_Ch);
    cudaGetSymbolAddress((void**)&idx, g_idx);
    cudaGetSymbolAddress((void**)&cnt, g_cnt);

    cudaFuncSetAttribute(gemm1p_kernel,
                         cudaFuncAttributeMaxDynamicSharedMemorySize, GSMEM);
    cudaFuncSetAttribute(attn_mma_kernel,
                         cudaFuncAttributeMaxDynamicSharedMemorySize, ASMEM);

    int sms = 148;
    {
        int dev = 0;
        cudaGetDevice(&dev);
        cudaDeviceGetAttribute(&sms, cudaDevAttrMultiProcessorCount, dev);
    }

    const int nA4 = MROWS * EMB / 4;
    const int nW4 = EMB * EMB / 4;

    // 1. mask compaction
    mask_compact_kernel<<<BATCH, 1024>>>(mask, idx, cnt);

    // 2. input conversions (fp16, hi only)
    dim3 gIn(nA4 / 256, 1, 3);
    cvt_inputs_kernel<<<gIn, 256>>>(q, k, v, idx, cnt, Aqh, Akh, Avh);

    // 3. weight conversions
    WJobs wj;
    wj.s[0] = Wq; wj.h[0] = Bqh;
    wj.s[1] = Wk; wj.h[1] = Bkh;
    wj.s[2] = Wv; wj.h[2] = Bvh;
    wj.s[3] = Wo; wj.h[3] = Boh;
    dim3 gW(nW4 / 256, 1, 4);
    cvt_weights_kernel<<<gW, 256>>>(wj);

    // 4. merged persistent Q/K/V projections — 2 CTAs per SM
    GJobs gj;
    gj.j[0].Ah = Aqh; gj.j[0].Bh = Bqh; gj.j[0].Ch = Qh;
    gj.j[0].Cf = nullptr; gj.j[0].bias = nullptr; gj.j[0].cnt = nullptr;
    gj.j[1].Ah = Akh; gj.j[1].Bh = Bkh; gj.j[1].Ch = Kh;
    gj.j[1].Cf = nullptr; gj.j[1].bias = nullptr; gj.j[1].cnt = cnt;
    gj.j[2].Ah = Avh; gj.j[2].Bh = Bvh; gj.j[2].Ch = Vh;
    gj.j[2].Cf = nullptr; gj.j[2].bias = nullptr; gj.j[2].cnt = cnt;
    gj.n = 3;
    gemm1p_kernel<<<2 * sms, 256, GSMEM>>>(gj);

    // 5. attention over compacted keys (Br=256)
    dim3 gAttn(S_LEN / 256, BATCH * NHEAD);   // (8, 64)
    attn_mma_kernel<<<gAttn, 256, ASMEM>>>(Qh, Kh, Vh, cnt, Ch);

    // 6. persistent output projection (+bias) -> fp32, 2 CTAs per SM
    GJobs go;
    go.j[0].Ah = Ch; go.j[0].Bh = Boh; go.j[0].Ch = nullptr;
    go.j[0].Cf = out; go.j[0].bias = bo; go.j[0].cnt = nullptr;
    go.j[1] = go.j[0];
    go.j[2] = go.j[0];
    go.n = 1;
    gemm1p_kernel<<<2 * sms, 256, GSMEM>>>(go);
}

// round 14
// speedup vs baseline: 2.3590x; 1.0273x over previous
#include <cuda_runtime.h>
#include <cuda_fp16.h>
#include <cstdint>

// ===========================================================================
// mma.sync / ldmatrix / cp.async helpers (base sm_103 target — no tcgen05)
// ===========================================================================
__device__ __forceinline__ uint32_t smem_u32_of(const void* p) {
    uint32_t a;
    asm("{ .reg .u64 t; cvta.to.shared.u64 t, %1; cvt.u32.u64 %0, t; }"
        : "=r"(a) : "l"(p));
    return a;
}
__device__ __forceinline__ void ldsm4(uint32_t r[4], uint32_t addr) {
    asm volatile("ldmatrix.sync.aligned.m8n8.x4.shared.b16 {%0,%1,%2,%3}, [%4];"
        : "=r"(r[0]), "=r"(r[1]), "=r"(r[2]), "=r"(r[3]) : "r"(addr));
}
__device__ __forceinline__ void ldsm4t(uint32_t r[4], uint32_t addr) {
    asm volatile("ldmatrix.sync.aligned.m8n8.x4.trans.shared.b16 {%0,%1,%2,%3}, [%4];"
        : "=r"(r[0]), "=r"(r[1]), "=r"(r[2]), "=r"(r[3]) : "r"(addr));
}
// fp16 inputs, fp32 accumulate
__device__ __forceinline__ void mma16816(float c[4], const uint32_t a[4],
                                         const uint32_t b[2]) {
    asm volatile(
        "mma.sync.aligned.m16n8k16.row.col.f32.f16.f16.f32 "
        "{%0,%1,%2,%3}, {%4,%5,%6,%7}, {%8,%9}, {%0,%1,%2,%3};"
        : "+f"(c[0]), "+f"(c[1]), "+f"(c[2]), "+f"(c[3])
        : "r"(a[0]), "r"(a[1]), "r"(a[2]), "r"(a[3]), "r"(b[0]), "r"(b[1]));
}
__device__ __forceinline__ void cp16(uint32_t dst, const void* src) {
    asm volatile("cp.async.cg.shared.global [%0], [%1], 16;" :: "r"(dst), "l"(src));
}
#define CP_COMMIT() asm volatile("cp.async.commit_group;" ::: "memory")
template <int N>
__device__ __forceinline__ void cp_wait() {
    asm volatile("cp.async.wait_group %0;" :: "n"(N) : "memory");
}

__device__ __forceinline__ uint32_t pack_h(float a, float b) {
    __half2 h2 = __floats2half2_rn(a, b);
    return *(uint32_t*)&h2;
}

// ===========================================================================
// Problem constants
// ===========================================================================
#define BATCH   4
#define S_LEN   2048
#define EMB     1024
#define NHEAD   16
#define DHEAD   64
#define MROWS   (BATCH * S_LEN)   // 8192

// Scratch (device globals — allocations forbidden)
__device__ __half g_Aqh[MROWS * EMB];
__device__ __half g_Akh[MROWS * EMB];
__device__ __half g_Avh[MROWS * EMB];
__device__ __half g_Bqh[EMB * EMB];
__device__ __half g_Bkh[EMB * EMB];
__device__ __half g_Bvh[EMB * EMB];
__device__ __half g_Boh[EMB * EMB];
__device__ __half g_Qh[MROWS * EMB];
__device__ __half g_Kh[MROWS * EMB];
__device__ __half g_Vh[MROWS * EMB];
__device__ __half g_Ch[MROWS * EMB];
__device__ int g_idx[BATCH * S_LEN];
__device__ int g_cnt[BATCH];

// ===========================================================================
// Stable mask compaction (unchanged, proven)
// ===========================================================================
__global__ __launch_bounds__(1024) void mask_compact_kernel(
    const int* __restrict__ mask, int* __restrict__ idx, int* __restrict__ cnt)
{
    const int b = blockIdx.x, t = threadIdx.x;
    const int wid = t >> 5, lane = t & 31;
    __shared__ int wsum[32], woff[32], chunk_total;
    int base = 0;
    #pragma unroll
    for (int half = 0; half < 2; half++) {
        int e = half * 1024 + t;
        int m = mask[b * S_LEN + e];
        unsigned bal = __ballot_sync(0xffffffffu, m != 0);
        int wtot = __popc(bal);
        int pos  = __popc(bal & ((1u << lane) - 1u));
        if (lane == 0) wsum[wid] = wtot;
        __syncthreads();
        if (t < 32) {
            int v = wsum[t], s = v;
            #pragma unroll
            for (int o = 1; o < 32; o <<= 1) {
                int u = __shfl_up_sync(0xffffffffu, s, o);
                if (t >= o) s += u;
            }
            woff[t] = s - v;
            if (t == 31) chunk_total = s;
        }
        __syncthreads();
        if (m) idx[b * S_LEN + base + woff[wid] + pos] = e;
        base += chunk_total;
        __syncthreads();
    }
    if (t == 0) cnt[b] = base;
}

// ===========================================================================
// Merged input conversion (hi only): z=0 dense q, z=1 gather k, z=2 gather v
// ===========================================================================
__global__ __launch_bounds__(256) void cvt_inputs_kernel(
    const float* __restrict__ q, const float* __restrict__ k,
    const float* __restrict__ v,
    const int* __restrict__ idx, const int* __restrict__ cnt,
    __half* __restrict__ qh, __half* __restrict__ kh, __half* __restrict__ vh)
{
    const int z = blockIdx.z;
    const float* src = (z == 0) ? q : ((z == 1) ? k : v);
    __half* H = (z == 0) ? qh : ((z == 1) ? kh : vh);
    int i = blockIdx.x * blockDim.x + threadIdx.x;
    if (z == 0) {
        float4 x = ((const float4*)src)[i];
        ((uint2*)H)[i] = make_uint2(pack_h(x.x, x.y), pack_h(x.z, x.w));
    } else {
        int rowq = i >> 8;
        int c4 = i & 255;
        int b = rowq >> 11, r = rowq & 2047;
        uint2 hh = make_uint2(0u, 0u);
        if (r < cnt[b]) {
            int s = idx[b * S_LEN + r];
            float4 x = ((const float4*)(src + ((size_t)(b * S_LEN + s)) * EMB))[c4];
            hh = make_uint2(pack_h(x.x, x.y), pack_h(x.z, x.w));
        }
        ((uint2*)H)[(size_t)rowq * 256 + c4] = hh;
    }
}

// ===========================================================================
// Merged weight conversion: hi only
// ===========================================================================
struct WJobs {
    const float* s[4];
    __half* h[4];
};

__global__ __launch_bounds__(256) void cvt_weights_kernel(WJobs wj)
{
    const int z = blockIdx.z;
    int i = blockIdx.x * blockDim.x + threadIdx.x;
    float4 x = ((const float4*)wj.s[z])[i];
    ((uint2*)wj.h[z])[i] = make_uint2(pack_h(x.x, x.y), pack_h(x.z, x.w));
}

// ===========================================================================
// Persistent multi-job single-fp16 GEMM, CTA 128x128, 8 warps of 64x32,
// compact 32KB stages, 2 CTAs/SM (unchanged from round 13, proven).
// ===========================================================================
#define CHUNKS 16
#define STG_BYTES 32768
#define NSTAGE 3
#define GSMEM (NSTAGE * STG_BYTES)    // 98304/CTA

struct GJob {
    const __half* Ah;
    const __half* Bh;
    __half* Ch;
    float* Cf;
    const float* bias;
    const int* cnt;
};
struct GJobs { GJob j[3]; int n; };

__global__ __launch_bounds__(256, 2) void gemm1p_kernel(GJobs jobs)
{
    extern __shared__ __align__(1024) char smem[];
    const uint32_t sb = smem_u32_of(smem);
    const int t = threadIdx.x;
    const int w = t >> 5, lane = t & 31;
    const int wm = (w >> 2) * 64;
    const int wn = (w & 3) * 32;

    uint32_t lsw[4]; uint32_t lgo[4];
    #pragma unroll
    for (int i = 0; i < 4; i++) {
        int u = t + 256 * i;
        int row = u >> 3, ku = u & 7;
        uint32_t off = row * 128 + ku * 16;
        lsw[i] = off ^ ((off >> 3) & 0x70);
        lgo[i] = (uint32_t)row * EMB + ku * 8;
    }

    const uint32_t xr  = (lane & 7) << 4;
    const uint32_t ak0 = (uint32_t)(lane & 16) ^ xr;
    const int      arow = lane & 15;
    const uint32_t bk0 = (uint32_t)((lane & 8) << 1) ^ xr;
    const int      brow = (lane & 7) | ((lane & 16) >> 1);
    uint32_t baA[4], baB[2];
    #pragma unroll
    for (int mi = 0; mi < 4; mi++)
        baA[mi] = (uint32_t)(wm + mi * 16 + arow) * 128 + ak0;
    #pragma unroll
    for (int nt = 0; nt < 2; nt++)
        baB[nt] = 16384u + (uint32_t)(wn + nt * 16 + brow) * 128 + bk0;

    const int total = jobs.n << 9;
    for (int tile = blockIdx.x; tile < total; tile += gridDim.x) {
        const GJob J = jobs.j[tile >> 9];
        const int within = tile & 511;
        const int bm = (within >> 3) * 128;
        const int bn = (within & 7) * 128;
        if (J.cnt && (bm & 2047) >= J.cnt[bm >> 11]) continue;

        const __half* gAh = J.Ah + (size_t)bm * EMB;
        const __half* gBh = J.Bh + (size_t)bn * EMB;

        float acc[4][4][4];
        #pragma unroll
        for (int mi = 0; mi < 4; mi++)
            #pragma unroll
            for (int ni = 0; ni < 4; ni++)
                #pragma unroll
                for (int r = 0; r < 4; r++) acc[mi][ni][r] = 0.0f;

        auto load_chunk = [&](int c) {
            const uint32_t so = sb + (uint32_t)(c % NSTAGE) * STG_BYTES;
            const uint32_t ko = (uint32_t)c * 64;
            #pragma unroll
            for (int i = 0; i < 4; i++) {
                cp16(so +      0 + lsw[i], gAh + lgo[i] + ko);
                cp16(so + 16384u + lsw[i], gBh + lgo[i] + ko);
            }
            CP_COMMIT();
        };

        __syncthreads();
        load_chunk(0);
        load_chunk(1);

        for (int c = 0; c < CHUNKS; c++) {
            if (c + 1 < CHUNKS) { cp_wait<1>(); } else { cp_wait<0>(); }
            __syncthreads();
            if (c + 2 < CHUNKS) load_chunk(c + 2);

            const uint32_t so = sb + (uint32_t)(c % NSTAGE) * STG_BYTES;
            #pragma unroll
            for (int ks = 0; ks < 4; ks++) {
                const uint32_t kx = (uint32_t)ks << 5;
                uint32_t ah[4][4], bh[2][4];
                #pragma unroll
                for (int mi = 0; mi < 4; mi++)
                    ldsm4(ah[mi], so + (baA[mi] ^ kx));
                #pragma unroll
                for (int nt = 0; nt < 2; nt++)
                    ldsm4(bh[nt], so + 16384u + ((baB[nt] - 16384u) ^ kx));
                #pragma unroll
                for (int mi = 0; mi < 4; mi++)
                    #pragma unroll
                    for (int ni = 0; ni < 4; ni++)
                        mma16816(acc[mi][ni], ah[mi], &bh[ni >> 1][(ni & 1) * 2]);
            }
        }

        // ---- epilogue ----
        #pragma unroll
        for (int mi = 0; mi < 4; mi++) {
            #pragma unroll
            for (int ni = 0; ni < 4; ni++) {
                int row = bm + wm + mi * 16 + (lane >> 2);
                int col = bn + wn + ni * 8 + (lane & 3) * 2;
                if (J.Cf) {
                    float2 v0 = make_float2(acc[mi][ni][0], acc[mi][ni][1]);
                    float2 v1 = make_float2(acc[mi][ni][2], acc[mi][ni][3]);
                    float b0 = __ldg(J.bias + col), b1 = __ldg(J.bias + col + 1);
                    v0.x += b0; v0.y += b1; v1.x += b0; v1.y += b1;
                    *(float2*)&J.Cf[(size_t)row * EMB + col] = v0;
                    *(float2*)&J.Cf[(size_t)(row + 8) * EMB + col] = v1;
                } else {
                    *(uint32_t*)&J.Ch[(size_t)row * EMB + col] =
                        pack_h(acc[mi][ni][0], acc[mi][ni][1]);
                    *(uint32_t*)&J.Ch[(size_t)(row + 8) * EMB + col] =
                        pack_h(acc[mi][ni][2], acc[mi][ni][3]);
                }
            }
        }
    }
}

// ===========================================================================
// Single-fp16 flash attention, Br=128 (round-11 proven body), 2 CTAs/SM.
// stage = 32KB (Kh@0 | Vh@16K), 3 stages (96KB/CTA). Q staged 16KB @0.
// ===========================================================================
#define ASTG 32768
#define ANST 3
#define ASMEM (ANST * ASTG)           // 98304/CTA; x2 = 196608 <= 228KB

__global__ __launch_bounds__(256, 2) void attn_mma_kernel(
    const __half* __restrict__ Qh, const __half* __restrict__ Kh,
    const __half* __restrict__ Vh, const int* __restrict__ cnt,
    __half* __restrict__ Ch)
{
    extern __shared__ __align__(1024) char smem[];
    const uint32_t sb = smem_u32_of(smem);
    const int t = threadIdx.x, w = t >> 5, lane = t & 31;
    const int qt = blockIdx.x, bh = blockIdx.y;
    const int b = bh >> 4, h = bh & 15;
    const int q0 = qt * 128;
    const int hcol = h * 64;
    const int n = cnt[b];
    const int ntiles = (n + 63) >> 6;

    // ---- stage Q (hi only, 16KB @0), extract frags ----
    {
        const size_t qbase = ((size_t)(b * S_LEN + q0)) * EMB + hcol;
        #pragma unroll
        for (int i = 0; i < 4; i++) {
            int u = t + 256 * i;          // 0..1023
            int r = u >> 3;
            int du = u & 7;
            uint32_t off = r * 128 + du * 16;
            uint32_t sw = off ^ ((off >> 3) & 0x70);
            cp16(sb + sw, Qh + qbase + (size_t)r * EMB + du * 8);
        }
        CP_COMMIT();
    }
    cp_wait<0>();
    __syncthreads();

    uint32_t qf[4][4];
    {
        uint32_t off = (uint32_t)(w * 16 + (lane & 15)) * 128 + ((lane >> 4) * 16);
        uint32_t baQ = off ^ ((off >> 3) & 0x70);
        #pragma unroll
        for (int k16 = 0; k16 < 4; k16++)
            ldsm4(qf[k16], sb + (baQ ^ (uint32_t)(k16 * 32)));
    }
    __syncthreads();

    uint32_t baK, baV;
    {
        uint32_t keyk = (uint32_t)((lane & 7) | ((lane & 16) >> 1));
        uint32_t offk = keyk * 128 + (uint32_t)((lane & 8) << 1);
        baK = offk ^ ((offk >> 3) & 0x70);
        uint32_t keyv = (uint32_t)(lane & 15);
        uint32_t offv = keyv * 128 + (uint32_t)((lane >> 4) * 16);
        baV = offv ^ ((offv >> 3) & 0x70);
    }

    auto load_tile = [&](int kt, int stg) {
        const size_t gk = ((size_t)(b * S_LEN + kt * 64)) * EMB + hcol;
        const uint32_t sdst = sb + (uint32_t)stg * ASTG;
        #pragma unroll
        for (int i = 0; i < 4; i++) {
            int u = t + 256 * i;
            int arr = u >> 9;             // 0 Kh, 1 Vh
            int r = (u >> 3) & 63;
            int du = u & 7;
            uint32_t off = r * 128 + du * 16;
            uint32_t sw = off ^ ((off >> 3) & 0x70);
            const __half* p = arr ? Vh : Kh;
            cp16(sdst + (uint32_t)arr * 16384u + sw, p + gk + (size_t)r * EMB + du * 8);
        }
        CP_COMMIT();
    };

    float O[8][4];
    #pragma unroll
    for (int j = 0; j < 8; j++)
        #pragma unroll
        for (int r = 0; r < 4; r++) O[j][r] = 0.0f;
    float m0 = -1e30f, m1 = -1e30f, l0 = 0.0f, l1 = 0.0f;

    if (ntiles == 0) {
        size_t row0 = (size_t)(b * S_LEN + q0 + w * 16 + (lane >> 2));
        #pragma unroll
        for (int j = 0; j < 8; j++) {
            int col = hcol + j * 8 + (lane & 3) * 2;
            *(uint32_t*)&Ch[row0 * EMB + col] = 0u;
            *(uint32_t*)&Ch[(row0 + 8) * EMB + col] = 0u;
        }
        return;
    }

    load_tile(0, 0);
    if (ntiles > 1) load_tile(1, 1);

    for (int kt = 0; kt < ntiles; kt++) {
        if (kt + 1 < ntiles) { cp_wait<1>(); } else { cp_wait<0>(); }
        __syncthreads();
        if (kt + 2 < ntiles) load_tile(kt + 2, (kt + 2) % ANST);

        const uint32_t so = sb + (uint32_t)(kt % ANST) * ASTG;

        // ---- scores = Q K^T ----
        float sc[8][4];
        #pragma unroll
        for (int j = 0; j < 8; j++)
            #pragma unroll
            for (int r = 0; r < 4; r++) sc[j][r] = 0.0f;

        #pragma unroll
        for (int k16 = 0; k16 < 4; k16++) {
            const uint32_t kx = (uint32_t)(k16 * 32);
            uint32_t kf[4][4];
            #pragma unroll
            for (int np = 0; np < 4; np++)
                ldsm4(kf[np], so + ((baK + (uint32_t)np * 2048u) ^ kx));
            #pragma unroll
            for (int np = 0; np < 4; np++) {
                mma16816(sc[2 * np],     qf[k16], &kf[np][0]);
                mma16816(sc[2 * np + 1], qf[k16], &kf[np][2]);
            }
        }

        // ---- scale + boundary mask + online softmax ----
        const int c0 = (lane & 3) * 2;
        const int limit = n - kt * 64;
        float rm0 = m0, rm1 = m1;
        #pragma unroll
        for (int j = 0; j < 8; j++) {
            int kc = j * 8 + c0;
            bool v0 = kc < limit, v1 = kc + 1 < limit;
            sc[j][0] = v0 ? sc[j][0] * 0.125f : -1e10f;
            sc[j][1] = v1 ? sc[j][1] * 0.125f : -1e10f;
            sc[j][2] = v0 ? sc[j][2] * 0.125f : -1e10f;
            sc[j][3] = v1 ? sc[j][3] * 0.125f : -1e10f;
            rm0 = fmaxf(rm0, fmaxf(sc[j][0], sc[j][1]));
            rm1 = fmaxf(rm1, fmaxf(sc[j][2], sc[j][3]));
        }
        rm0 = fmaxf(rm0, __shfl_xor_sync(0xffffffffu, rm0, 1));
        rm0 = fmaxf(rm0, __shfl_xor_sync(0xffffffffu, rm0, 2));
        rm1 = fmaxf(rm1, __shfl_xor_sync(0xffffffffu, rm1, 1));
        rm1 = fmaxf(rm1, __shfl_xor_sync(0xffffffffu, rm1, 2));
        float corr0 = __expf(m0 - rm0);
        float corr1 = __expf(m1 - rm1);
        m0 = rm0; m1 = rm1;
        float ls0 = 0.0f, ls1 = 0.0f;
        #pragma unroll
        for (int j = 0; j < 8; j++) {
            sc[j][0] = __expf(sc[j][0] - m0);
            sc[j][1] = __expf(sc[j][1] - m0);
            sc[j][2] = __expf(sc[j][2] - m1);
            sc[j][3] = __expf(sc[j][3] - m1);
            ls0 += sc[j][0] + sc[j][1];
            ls1 += sc[j][2] + sc[j][3];
        }
        ls0 += __shfl_xor_sync(0xffffffffu, ls0, 1);
        ls0 += __shfl_xor_sync(0xffffffffu, ls0, 2);
        ls1 += __shfl_xor_sync(0xffffffffu, ls1, 1);
        ls1 += __shfl_xor_sync(0xffffffffu, ls1, 2);
        l0 = l0 * corr0 + ls0;
        l1 = l1 * corr1 + ls1;
        #pragma unroll
        for (int j = 0; j < 8; j++) {
            O[j][0] *= corr0; O[j][1] *= corr0;
            O[j][2] *= corr1; O[j][3] *= corr1;
        }

        // ---- pack P, O += P V ----
        uint32_t pf[4][4];
        #pragma unroll
        for (int kb = 0; kb < 4; kb++) {
            pf[kb][0] = pack_h(sc[2 * kb][0],     sc[2 * kb][1]);
            pf[kb][1] = pack_h(sc[2 * kb][2],     sc[2 * kb][3]);
            pf[kb][2] = pack_h(sc[2 * kb + 1][0], sc[2 * kb + 1][1]);
            pf[kb][3] = pack_h(sc[2 * kb + 1][2], sc[2 * kb + 1][3]);
        }
        #pragma unroll
        for (int kb = 0; kb < 4; kb++) {
            const uint32_t kadd = (uint32_t)kb * 2048u;
            uint32_t vf[4][4];
            #pragma unroll
            for (int dp = 0; dp < 4; dp++) {
                const uint32_t dx = (uint32_t)(dp * 32);
                ldsm4t(vf[dp], so + 16384u + ((baV + kadd) ^ dx));
            }
            #pragma unroll
            for (int dp = 0; dp < 4; dp++) {
                mma16816(O[2 * dp],     pf[kb], &vf[dp][0]);
                mma16816(O[2 * dp + 1], pf[kb], &vf[dp][2]);
            }
        }
    }

    // ---- epilogue: O/l -> fp16 Ctx ----
    float inv0 = 1.0f / l0, inv1 = 1.0f / l1;
    size_t row0 = (size_t)(b * S_LEN + q0 + w * 16 + (lane >> 2));
    size_t row1 = row0 + 8;
    #pragma unroll
    for (int j = 0; j < 8; j++) {
        int col = hcol + j * 8 + (lane & 3) * 2;
        *(uint32_t*)&Ch[row0 * EMB + col] = pack_h(O[j][0] * inv0, O[j][1] * inv0);
        *(uint32_t*)&Ch[row1 * EMB + col] = pack_h(O[j][2] * inv1, O[j][3] * inv1);
    }
}

// ===========================================================================
// Launch
// ===========================================================================
extern "C" void kernel_launch(void* const* d_in, const int* in_sizes, int n_in,
                              void* d_out, int out_size)
{
    const float* q    = (const float*)d_in[0];
    const float* k    = (const float*)d_in[1];
    const float* v    = (const float*)d_in[2];
    const int*   mask = (const int*)  d_in[3];
    const float* Wq   = (const float*)d_in[4];
    const float* Wk   = (const float*)d_in[5];
    const float* Wv   = (const float*)d_in[6];
    const float* Wo   = (const float*)d_in[7];
    const float* bo   = (const float*)d_in[8];
    float* out = (float*)d_out;

    __half *Aqh, *Akh, *Avh, *Bqh, *Bkh, *Bvh, *Boh;
    __half *Qh, *Kh, *Vh, *Ch;
    int *idx, *cnt;
    cudaGetSymbolAddress((void**)&Aqh, g_Aqh);
    cudaGetSymbolAddress((void**)&Akh, g_Akh);
    cudaGetSymbolAddress((void**)&Avh, g_Avh);
    cudaGetSymbolAddress((void**)&Bqh, g_Bqh);
    cudaGetSymbolAddress((void**)&Bkh, g_Bkh);
    cudaGetSymbolAddress((void**)&Bvh, g_Bvh);
    cudaGetSymbolAddress((void**)&Boh, g_Boh);
    cudaGetSymbolAddress((void**)&Qh,  g_Qh);
    cudaGetSymbolAddress((void**)&Kh,  g_Kh);
    cudaGetSymbolAddress((void**)&Vh,  g_Vh);
    cudaGetSymbolAddress((void**)&Ch,  g_Ch);
    cudaGetSymbolAddress((void**)&idx, g_idx);
    cudaGetSymbolAddress((void**)&cnt, g_cnt);

    cudaFuncSetAttribute(gemm1p_kernel,
                         cudaFuncAttributeMaxDynamicSharedMemorySize, GSMEM);
    cudaFuncSetAttribute(attn_mma_kernel,
                         cudaFuncAttributeMaxDynamicSharedMemorySize, ASMEM);

    int sms = 148;
    {
        int dev = 0;
        cudaGetDevice(&dev);
        cudaDeviceGetAttribute(&sms, cudaDevAttrMultiProcessorCount, dev);
    }

    const int nA4 = MROWS * EMB / 4;
    const int nW4 = EMB * EMB / 4;

    // 1. mask compaction
    mask_compact_kernel<<<BATCH, 1024>>>(mask, idx, cnt);

    // 2. input conversions (fp16, hi only)
    dim3 gIn(nA4 / 256, 1, 3);
    cvt_inputs_kernel<<<gIn, 256>>>(q, k, v, idx, cnt, Aqh, Akh, Avh);

    // 3. weight conversions
    WJobs wj;
    wj.s[0] = Wq; wj.h[0] = Bqh;
    wj.s[1] = Wk; wj.h[1] = Bkh;
    wj.s[2] = Wv; wj.h[2] = Bvh;
    wj.s[3] = Wo; wj.h[3] = Boh;
    dim3 gW(nW4 / 256, 1, 4);
    cvt_weights_kernel<<<gW, 256>>>(wj);

    // 4. merged persistent Q/K/V projections — 2 CTAs per SM
    GJobs gj;
    gj.j[0].Ah = Aqh; gj.j[0].Bh = Bqh; gj.j[0].Ch = Qh;
    gj.j[0].Cf = nullptr; gj.j[0].bias = nullptr; gj.j[0].cnt = nullptr;
    gj.j[1].Ah = Akh; gj.j[1].Bh = Bkh; gj.j[1].Ch = Kh;
    gj.j[1].Cf = nullptr; gj.j[1].bias = nullptr; gj.j[1].cnt = cnt;
    gj.j[2].Ah = Avh; gj.j[2].Bh = Bvh; gj.j[2].Ch = Vh;
    gj.j[2].Cf = nullptr; gj.j[2].bias = nullptr; gj.j[2].cnt = cnt;
    gj.n = 3;
    gemm1p_kernel<<<2 * sms, 256, GSMEM>>>(gj);

    // 5. attention over compacted keys (Br=128, 2 CTAs/SM)
    dim3 gAttn(S_LEN / 128, BATCH * NHEAD);   // (16, 64)
    attn_mma_kernel<<<gAttn, 256, ASMEM>>>(Qh, Kh, Vh, cnt, Ch);

    // 6. persistent output projection (+bias) -> fp32, 2 CTAs per SM
    GJobs go;
    go.j[0].Ah = Ch; go.j[0].Bh = Boh; go.j[0].Ch = nullptr;
    go.j[0].Cf = out; go.j[0].bias = bo; go.j[0].cnt = nullptr;
    go.j[1] = go.j[0];
    go.j[2] = go.j[0];
    go.n = 1;
    gemm1p_kernel<<<2 * sms, 256, GSMEM>>>(go);
}

// round 15
// speedup vs baseline: 2.4339x; 1.0317x over previous
#include <cuda_runtime.h>
#include <cuda_fp16.h>
#include <cstdint>

// ===========================================================================
// mma.sync / ldmatrix / cp.async helpers (base sm_103 target — no tcgen05)
// ===========================================================================
__device__ __forceinline__ uint32_t smem_u32_of(const void* p) {
    uint32_t a;
    asm("{ .reg .u64 t; cvta.to.shared.u64 t, %1; cvt.u32.u64 %0, t; }"
        : "=r"(a) : "l"(p));
    return a;
}
__device__ __forceinline__ void ldsm4(uint32_t r[4], uint32_t addr) {
    asm volatile("ldmatrix.sync.aligned.m8n8.x4.shared.b16 {%0,%1,%2,%3}, [%4];"
        : "=r"(r[0]), "=r"(r[1]), "=r"(r[2]), "=r"(r[3]) : "r"(addr));
}
__device__ __forceinline__ void ldsm4t(uint32_t r[4], uint32_t addr) {
    asm volatile("ldmatrix.sync.aligned.m8n8.x4.trans.shared.b16 {%0,%1,%2,%3}, [%4];"
        : "=r"(r[0]), "=r"(r[1]), "=r"(r[2]), "=r"(r[3]) : "r"(addr));
}
// fp16 inputs, fp32 accumulate
__device__ __forceinline__ void mma16816(float c[4], const uint32_t a[4],
                                         const uint32_t b[2]) {
    asm volatile(
        "mma.sync.aligned.m16n8k16.row.col.f32.f16.f16.f32 "
        "{%0,%1,%2,%3}, {%4,%5,%6,%7}, {%8,%9}, {%0,%1,%2,%3};"
        : "+f"(c[0]), "+f"(c[1]), "+f"(c[2]), "+f"(c[3])
        : "r"(a[0]), "r"(a[1]), "r"(a[2]), "r"(a[3]), "r"(b[0]), "r"(b[1]));
}
__device__ __forceinline__ void cp16(uint32_t dst, const void* src) {
    asm volatile("cp.async.cg.shared.global [%0], [%1], 16;" :: "r"(dst), "l"(src));
}
#define CP_COMMIT() asm volatile("cp.async.commit_group;" ::: "memory")
template <int N>
__device__ __forceinline__ void cp_wait() {
    asm volatile("cp.async.wait_group %0;" :: "n"(N) : "memory");
}

__device__ __forceinline__ uint32_t pack_h(float a, float b) {
    __half2 h2 = __floats2half2_rn(a, b);
    return *(uint32_t*)&h2;
}

// ===========================================================================
// Problem constants
// ===========================================================================
#define BATCH   4
#define S_LEN   2048
#define EMB     1024
#define NHEAD   16
#define DHEAD   64
#define MROWS   (BATCH * S_LEN)   // 8192

// Scratch (device globals — allocations forbidden)
__device__ __half g_Aqh[MROWS * EMB];
__device__ __half g_Akh[MROWS * EMB];
__device__ __half g_Avh[MROWS * EMB];
__device__ __half g_Bqh[EMB * EMB];
__device__ __half g_Bkh[EMB * EMB];
__device__ __half g_Bvh[EMB * EMB];
__device__ __half g_Boh[EMB * EMB];
__device__ __half g_Qh[MROWS * EMB];
__device__ __half g_Kh[MROWS * EMB];
__device__ __half g_Vh[MROWS * EMB];
__device__ __half g_Ch[MROWS * EMB];
__device__ int g_idx[BATCH * S_LEN];
__device__ int g_cnt[BATCH];

// ===========================================================================
// Stable mask compaction (unchanged, proven)
// ===========================================================================
__global__ __launch_bounds__(1024) void mask_compact_kernel(
    const int* __restrict__ mask, int* __restrict__ idx, int* __restrict__ cnt)
{
    const int b = blockIdx.x, t = threadIdx.x;
    const int wid = t >> 5, lane = t & 31;
    __shared__ int wsum[32], woff[32], chunk_total;
    int base = 0;
    #pragma unroll
    for (int half = 0; half < 2; half++) {
        int e = half * 1024 + t;
        int m = mask[b * S_LEN + e];
        unsigned bal = __ballot_sync(0xffffffffu, m != 0);
        int wtot = __popc(bal);
        int pos  = __popc(bal & ((1u << lane) - 1u));
        if (lane == 0) wsum[wid] = wtot;
        __syncthreads();
        if (t < 32) {
            int v = wsum[t], s = v;
            #pragma unroll
            for (int o = 1; o < 32; o <<= 1) {
                int u = __shfl_up_sync(0xffffffffu, s, o);
                if (t >= o) s += u;
            }
            woff[t] = s - v;
            if (t == 31) chunk_total = s;
        }
        __syncthreads();
        if (m) idx[b * S_LEN + base + woff[wid] + pos] = e;
        base += chunk_total;
        __syncthreads();
    }
    if (t == 0) cnt[b] = base;
}

// ===========================================================================
// Merged input conversion (hi only): z=0 dense q, z=1 gather k, z=2 gather v
// ===========================================================================
__global__ __launch_bounds__(256) void cvt_inputs_kernel(
    const float* __restrict__ q, const float* __restrict__ k,
    const float* __restrict__ v,
    const int* __restrict__ idx, const int* __restrict__ cnt,
    __half* __restrict__ qh, __half* __restrict__ kh, __half* __restrict__ vh)
{
    const int z = blockIdx.z;
    const float* src = (z == 0) ? q : ((z == 1) ? k : v);
    __half* H = (z == 0) ? qh : ((z == 1) ? kh : vh);
    int i = blockIdx.x * blockDim.x + threadIdx.x;
    if (z == 0) {
        float4 x = ((const float4*)src)[i];
        ((uint2*)H)[i] = make_uint2(pack_h(x.x, x.y), pack_h(x.z, x.w));
    } else {
        int rowq = i >> 8;
        int c4 = i & 255;
        int b = rowq >> 11, r = rowq & 2047;
        uint2 hh = make_uint2(0u, 0u);
        if (r < cnt[b]) {
            int s = idx[b * S_LEN + r];
            float4 x = ((const float4*)(src + ((size_t)(b * S_LEN + s)) * EMB))[c4];
            hh = make_uint2(pack_h(x.x, x.y), pack_h(x.z, x.w));
        }
        ((uint2*)H)[(size_t)rowq * 256 + c4] = hh;
    }
}

// ===========================================================================
// Merged weight conversion: hi only
// ===========================================================================
struct WJobs {
    const float* s[4];
    __half* h[4];
};

__global__ __launch_bounds__(256) void cvt_weights_kernel(WJobs wj)
{
    const int z = blockIdx.z;
    int i = blockIdx.x * blockDim.x + threadIdx.x;
    float4 x = ((const float4*)wj.s[z])[i];
    ((uint2*)wj.h[z])[i] = make_uint2(pack_h(x.x, x.y), pack_h(x.z, x.w));
}

// ===========================================================================
// Persistent multi-job single-fp16 GEMM, CTA 128x128, 8 warps of 64x32,
// compact 32KB stages, 2 CTAs/SM. fp16 output path applies per-job scale
// (used to fold 1/sqrt(D) into the Q projection).
// ===========================================================================
#define CHUNKS 16
#define STG_BYTES 32768
#define NSTAGE 3
#define GSMEM (NSTAGE * STG_BYTES)    // 98304/CTA

struct GJob {
    const __half* Ah;
    const __half* Bh;
    __half* Ch;
    float* Cf;
    const float* bias;
    const int* cnt;
    float scale;                      // applied on fp16 output path
};
struct GJobs { GJob j[3]; int n; };

__global__ __launch_bounds__(256, 2) void gemm1p_kernel(GJobs jobs)
{
    extern __shared__ __align__(1024) char smem[];
    const uint32_t sb = smem_u32_of(smem);
    const int t = threadIdx.x;
    const int w = t >> 5, lane = t & 31;
    const int wm = (w >> 2) * 64;
    const int wn = (w & 3) * 32;

    uint32_t lsw[4]; uint32_t lgo[4];
    #pragma unroll
    for (int i = 0; i < 4; i++) {
        int u = t + 256 * i;
        int row = u >> 3, ku = u & 7;
        uint32_t off = row * 128 + ku * 16;
        lsw[i] = off ^ ((off >> 3) & 0x70);
        lgo[i] = (uint32_t)row * EMB + ku * 8;
    }

    const uint32_t xr  = (lane & 7) << 4;
    const uint32_t ak0 = (uint32_t)(lane & 16) ^ xr;
    const int      arow = lane & 15;
    const uint32_t bk0 = (uint32_t)((lane & 8) << 1) ^ xr;
    const int      brow = (lane & 7) | ((lane & 16) >> 1);
    uint32_t baA[4], baB[2];
    #pragma unroll
    for (int mi = 0; mi < 4; mi++)
        baA[mi] = (uint32_t)(wm + mi * 16 + arow) * 128 + ak0;
    #pragma unroll
    for (int nt = 0; nt < 2; nt++)
        baB[nt] = (uint32_t)(wn + nt * 16 + brow) * 128 + bk0;

    const int total = jobs.n << 9;
    for (int tile = blockIdx.x; tile < total; tile += gridDim.x) {
        const GJob J = jobs.j[tile >> 9];
        const int within = tile & 511;
        const int bm = (within >> 3) * 128;
        const int bn = (within & 7) * 128;
        if (J.cnt && (bm & 2047) >= J.cnt[bm >> 11]) continue;

        const __half* gAh = J.Ah + (size_t)bm * EMB;
        const __half* gBh = J.Bh + (size_t)bn * EMB;

        float acc[4][4][4];
        #pragma unroll
        for (int mi = 0; mi < 4; mi++)
            #pragma unroll
            for (int ni = 0; ni < 4; ni++)
                #pragma unroll
                for (int r = 0; r < 4; r++) acc[mi][ni][r] = 0.0f;

        auto load_chunk = [&](int c) {
            const uint32_t so = sb + (uint32_t)(c % NSTAGE) * STG_BYTES;
            const uint32_t ko = (uint32_t)c * 64;
            #pragma unroll
            for (int i = 0; i < 4; i++) {
                cp16(so +      0 + lsw[i], gAh + lgo[i] + ko);
                cp16(so + 16384u + lsw[i], gBh + lgo[i] + ko);
            }
            CP_COMMIT();
        };

        __syncthreads();
        load_chunk(0);
        load_chunk(1);

        for (int c = 0; c < CHUNKS; c++) {
            if (c + 1 < CHUNKS) { cp_wait<1>(); } else { cp_wait<0>(); }
            __syncthreads();
            if (c + 2 < CHUNKS) load_chunk(c + 2);

            const uint32_t so = sb + (uint32_t)(c % NSTAGE) * STG_BYTES;
            #pragma unroll
            for (int ks = 0; ks < 4; ks++) {
                const uint32_t kx = (uint32_t)ks << 5;
                uint32_t ah[4][4], bh[2][4];
                #pragma unroll
                for (int mi = 0; mi < 4; mi++)
                    ldsm4(ah[mi], so + (baA[mi] ^ kx));
                #pragma unroll
                for (int nt = 0; nt < 2; nt++)
                    ldsm4(bh[nt], so + 16384u + (baB[nt] ^ kx));
                #pragma unroll
                for (int mi = 0; mi < 4; mi++)
                    #pragma unroll
                    for (int ni = 0; ni < 4; ni++)
                        mma16816(acc[mi][ni], ah[mi], &bh[ni >> 1][(ni & 1) * 2]);
            }
        }

        // ---- epilogue ----
        #pragma unroll
        for (int mi = 0; mi < 4; mi++) {
            #pragma unroll
            for (int ni = 0; ni < 4; ni++) {
                int row = bm + wm + mi * 16 + (lane >> 2);
                int col = bn + wn + ni * 8 + (lane & 3) * 2;
                if (J.Cf) {
                    float2 v0 = make_float2(acc[mi][ni][0], acc[mi][ni][1]);
                    float2 v1 = make_float2(acc[mi][ni][2], acc[mi][ni][3]);
                    float b0 = __ldg(J.bias + col), b1 = __ldg(J.bias + col + 1);
                    v0.x += b0; v0.y += b1; v1.x += b0; v1.y += b1;
                    *(float2*)&J.Cf[(size_t)row * EMB + col] = v0;
                    *(float2*)&J.Cf[(size_t)(row + 8) * EMB + col] = v1;
                } else {
                    float s = J.scale;
                    *(uint32_t*)&J.Ch[(size_t)row * EMB + col] =
                        pack_h(acc[mi][ni][0] * s, acc[mi][ni][1] * s);
                    *(uint32_t*)&J.Ch[(size_t)(row + 8) * EMB + col] =
                        pack_h(acc[mi][ni][2] * s, acc[mi][ni][3] * s);
                }
            }
        }
    }
}

// ===========================================================================
// Single-fp16 flash attention, Br=128, 2 CTAs/SM.
// Scale pre-folded into Qh; boundary masking hoisted to the last partial tile.
// ===========================================================================
#define ASTG 32768
#define ANST 3
#define ASMEM (ANST * ASTG)           // 98304/CTA

__global__ __launch_bounds__(256, 2) void attn_mma_kernel(
    const __half* __restrict__ Qh, const __half* __restrict__ Kh,
    const __half* __restrict__ Vh, const int* __restrict__ cnt,
    __half* __restrict__ Ch)
{
    extern __shared__ __align__(1024) char smem[];
    const uint32_t sb = smem_u32_of(smem);
    const int t = threadIdx.x, w = t >> 5, lane = t & 31;
    const int qt = blockIdx.x, bh = blockIdx.y;
    const int b = bh >> 4, h = bh & 15;
    const int q0 = qt * 128;
    const int hcol = h * 64;
    const int n = cnt[b];
    const int ntiles = (n + 63) >> 6;

    // ---- stage Q (16KB @0), extract frags ----
    {
        const size_t qbase = ((size_t)(b * S_LEN + q0)) * EMB + hcol;
        #pragma unroll
        for (int i = 0; i < 4; i++) {
            int u = t + 256 * i;
            int r = u >> 3;
            int du = u & 7;
            uint32_t off = r * 128 + du * 16;
            uint32_t sw = off ^ ((off >> 3) & 0x70);
            cp16(sb + sw, Qh + qbase + (size_t)r * EMB + du * 8);
        }
        CP_COMMIT();
    }
    cp_wait<0>();
    __syncthreads();

    uint32_t qf[4][4];
    {
        uint32_t off = (uint32_t)(w * 16 + (lane & 15)) * 128 + ((lane >> 4) * 16);
        uint32_t baQ = off ^ ((off >> 3) & 0x70);
        #pragma unroll
        for (int k16 = 0; k16 < 4; k16++)
            ldsm4(qf[k16], sb + (baQ ^ (uint32_t)(k16 * 32)));
    }
    __syncthreads();

    uint32_t baK, baV;
    {
        uint32_t keyk = (uint32_t)((lane & 7) | ((lane & 16) >> 1));
        uint32_t offk = keyk * 128 + (uint32_t)((lane & 8) << 1);
        baK = offk ^ ((offk >> 3) & 0x70);
        uint32_t keyv = (uint32_t)(lane & 15);
        uint32_t offv = keyv * 128 + (uint32_t)((lane >> 4) * 16);
        baV = offv ^ ((offv >> 3) & 0x70);
    }

    auto load_tile = [&](int kt, int stg) {
        const size_t gk = ((size_t)(b * S_LEN + kt * 64)) * EMB + hcol;
        const uint32_t sdst = sb + (uint32_t)stg * ASTG;
        #pragma unroll
        for (int i = 0; i < 4; i++) {
            int u = t + 256 * i;
            int arr = u >> 9;
            int r = (u >> 3) & 63;
            int du = u & 7;
            uint32_t off = r * 128 + du * 16;
            uint32_t sw = off ^ ((off >> 3) & 0x70);
            const __half* p = arr ? Vh : Kh;
            cp16(sdst + (uint32_t)arr * 16384u + sw, p + gk + (size_t)r * EMB + du * 8);
        }
        CP_COMMIT();
    };

    float O[8][4];
    #pragma unroll
    for (int j = 0; j < 8; j++)
        #pragma unroll
        for (int r = 0; r < 4; r++) O[j][r] = 0.0f;
    float m0 = -1e30f, m1 = -1e30f, l0 = 0.0f, l1 = 0.0f;

    if (ntiles == 0) {
        size_t row0 = (size_t)(b * S_LEN + q0 + w * 16 + (lane >> 2));
        #pragma unroll
        for (int j = 0; j < 8; j++) {
            int col = hcol + j * 8 + (lane & 3) * 2;
            *(uint32_t*)&Ch[row0 * EMB + col] = 0u;
            *(uint32_t*)&Ch[(row0 + 8) * EMB + col] = 0u;
        }
        return;
    }

    load_tile(0, 0);
    if (ntiles > 1) load_tile(1, 1);

    const int tail = n & 63;

    for (int kt = 0; kt < ntiles; kt++) {
        if (kt + 1 < ntiles) { cp_wait<1>(); } else { cp_wait<0>(); }
        __syncthreads();
        if (kt + 2 < ntiles) load_tile(kt + 2, (kt + 2) % ANST);

        const uint32_t so = sb + (uint32_t)(kt % ANST) * ASTG;

        // ---- scores = Q K^T (scale pre-folded into Q) ----
        float sc[8][4];
        #pragma unroll
        for (int j = 0; j < 8; j++)
            #pragma unroll
            for (int r = 0; r < 4; r++) sc[j][r] = 0.0f;

        #pragma unroll
        for (int k16 = 0; k16 < 4; k16++) {
            const uint32_t kx = (uint32_t)(k16 * 32);
            uint32_t kf[4][4];
            #pragma unroll
            for (int np = 0; np < 4; np++)
                ldsm4(kf[np], so + ((baK + (uint32_t)np * 2048u) ^ kx));
            #pragma unroll
            for (int np = 0; np < 4; np++) {
                mma16816(sc[2 * np],     qf[k16], &kf[np][0]);
                mma16816(sc[2 * np + 1], qf[k16], &kf[np][2]);
            }
        }

        // ---- boundary mask only on the final partial tile ----
        if (kt == ntiles - 1 && tail) {
            const int c0 = (lane & 3) * 2;
            #pragma unroll
            for (int j = 0; j < 8; j++) {
                int kc = j * 8 + c0;
                bool v0 = kc < tail, v1 = kc + 1 < tail;
                if (!v0) { sc[j][0] = -1e10f; sc[j][2] = -1e10f; }
                if (!v1) { sc[j][1] = -1e10f; sc[j][3] = -1e10f; }
            }
        }

        // ---- online softmax ----
        float rm0 = m0, rm1 = m1;
        #pragma unroll
        for (int j = 0; j < 8; j++) {
            rm0 = fmaxf(rm0, fmaxf(sc[j][0], sc[j][1]));
            rm1 = fmaxf(rm1, fmaxf(sc[j][2], sc[j][3]));
        }
        rm0 = fmaxf(rm0, __shfl_xor_sync(0xffffffffu, rm0, 1));
        rm0 = fmaxf(rm0, __shfl_xor_sync(0xffffffffu, rm0, 2));
        rm1 = fmaxf(rm1, __shfl_xor_sync(0xffffffffu, rm1, 1));
        rm1 = fmaxf(rm1, __shfl_xor_sync(0xffffffffu, rm1, 2));
        float corr0 = __expf(m0 - rm0);
        float corr1 = __expf(m1 - rm1);
        m0 = rm0; m1 = rm1;
        float ls0 = 0.0f, ls1 = 0.0f;
        #pragma unroll
        for (int j = 0; j < 8; j++) {
            sc[j][0] = __expf(sc[j][0] - m0);
            sc[j][1] = __expf(sc[j][1] - m0);
            sc[j][2] = __expf(sc[j][2] - m1);
            sc[j][3] = __expf(sc[j][3] - m1);
            ls0 += sc[j][0] + sc[j][1];
            ls1 += sc[j][2] + sc[j][3];
        }
        ls0 += __shfl_xor_sync(0xffffffffu, ls0, 1);
        ls0 += __shfl_xor_sync(0xffffffffu, ls0, 2);
        ls1 += __shfl_xor_sync(0xffffffffu, ls1, 1);
        ls1 += __shfl_xor_sync(0xffffffffu, ls1, 2);
        l0 = l0 * corr0 + ls0;
        l1 = l1 * corr1 + ls1;
        #pragma unroll
        for (int j = 0; j < 8; j++) {
            O[j][0] *= corr0; O[j][1] *= corr0;
            O[j][2] *= corr1; O[j][3] *= corr1;
        }

        // ---- pack P, O += P V ----
        uint32_t pf[4][4];
        #pragma unroll
        for (int kb = 0; kb < 4; kb++) {
            pf[kb][0] = pack_h(sc[2 * kb][0],     sc[2 * kb][1]);
            pf[kb][1] = pack_h(sc[2 * kb][2],     sc[2 * kb][3]);
            pf[kb][2] = pack_h(sc[2 * kb + 1][0], sc[2 * kb + 1][1]);
            pf[kb][3] = pack_h(sc[2 * kb + 1][2], sc[2 * kb + 1][3]);
        }
        #pragma unroll
        for (int kb = 0; kb < 4; kb++) {
            const uint32_t kadd = (uint32_t)kb * 2048u;
            uint32_t vf[4][4];
            #pragma unroll
            for (int dp = 0; dp < 4; dp++) {
                const uint32_t dx = (uint32_t)(dp * 32);
                ldsm4t(vf[dp], so + 16384u + ((baV + kadd) ^ dx));
            }
            #pragma unroll
            for (int dp = 0; dp < 4; dp++) {
                mma16816(O[2 * dp],     pf[kb], &vf[dp][0]);
                mma16816(O[2 * dp + 1], pf[kb], &vf[dp][2]);
            }
        }
    }

    // ---- epilogue: O/l -> fp16 Ctx ----
    float inv0 = 1.0f / l0, inv1 = 1.0f / l1;
    size_t row0 = (size_t)(b * S_LEN + q0 + w * 16 + (lane >> 2));
    size_t row1 = row0 + 8;
    #pragma unroll
    for (int j = 0; j < 8; j++) {
        int col = hcol + j * 8 + (lane & 3) * 2;
        *(uint32_t*)&Ch[row0 * EMB + col] = pack_h(O[j][0] * inv0, O[j][1] * inv0);
        *(uint32_t*)&Ch[row1 * EMB + col] = pack_h(O[j][2] * inv1, O[j][3] * inv1);
    }
}

// ===========================================================================
// Launch
// ===========================================================================
extern "C" void kernel_launch(void* const* d_in, const int* in_sizes, int n_in,
                              void* d_out, int out_size)
{
    const float* q    = (const float*)d_in[0];
    const float* k    = (const float*)d_in[1];
    const float* v    = (const float*)d_in[2];
    const int*   mask = (const int*)  d_in[3];
    const float* Wq   = (const float*)d_in[4];
    const float* Wk   = (const float*)d_in[5];
    const float* Wv   = (const float*)d_in[6];
    const float* Wo   = (const float*)d_in[7];
    const float* bo   = (const float*)d_in[8];
    float* out = (float*)d_out;

    __half *Aqh, *Akh, *Avh, *Bqh, *Bkh, *Bvh, *Boh;
    __half *Qh, *Kh, *Vh, *Ch;
    int *idx, *cnt;
    cudaGetSymbolAddress((void**)&Aqh, g_Aqh);
    cudaGetSymbolAddress((void**)&Akh, g_Akh);
    cudaGetSymbolAddress((void**)&Avh, g_Avh);
    cudaGetSymbolAddress((void**)&Bqh, g_Bqh);
    cudaGetSymbolAddress((void**)&Bkh, g_Bkh);
    cudaGetSymbolAddress((void**)&Bvh, g_Bvh);
    cudaGetSymbolAddress((void**)&Boh, g_Boh);
    cudaGetSymbolAddress((void**)&Qh,  g_Qh);
    cudaGetSymbolAddress((void**)&Kh,  g_Kh);
    cudaGetSymbolAddress((void**)&Vh,  g_Vh);
    cudaGetSymbolAddress((void**)&Ch,  g_Ch);
    cudaGetSymbolAddress((void**)&idx, g_idx);
    cudaGetSymbolAddress((void**)&cnt, g_cnt);

    cudaFuncSetAttribute(gemm1p_kernel,
                         cudaFuncAttributeMaxDynamicSharedMemorySize, GSMEM);
    cudaFuncSetAttribute(attn_mma_kernel,
                         cudaFuncAttributeMaxDynamicSharedMemorySize, ASMEM);

    int sms = 148;
    {
        int dev = 0;
        cudaGetDevice(&dev);
        cudaDeviceGetAttribute(&sms, cudaDevAttrMultiProcessorCount, dev);
    }

    const int nA4 = MROWS * EMB / 4;
    const int nW4 = EMB * EMB / 4;

    // 1. mask compaction
    mask_compact_kernel<<<BATCH, 1024>>>(mask, idx, cnt);

    // 2. input conversions (fp16, hi only)
    dim3 gIn(nA4 / 256, 1, 3);
    cvt_inputs_kernel<<<gIn, 256>>>(q, k, v, idx, cnt, Aqh, Akh, Avh);

    // 3. weight conversions
    WJobs wj;
    wj.s[0] = Wq; wj.h[0] = Bqh;
    wj.s[1] = Wk; wj.h[1] = Bkh;
    wj.s[2] = Wv; wj.h[2] = Bvh;
    wj.s[3] = Wo; wj.h[3] = Boh;
    dim3 gW(nW4 / 256, 1, 4);
    cvt_weights_kernel<<<gW, 256>>>(wj);

    // 4. merged persistent Q/K/V projections — 2 CTAs per SM
    //    Q projection folds in the 1/sqrt(D_HEAD*NHEAD/NHEAD)=1/8 softmax scale.
    GJobs gj;
    gj.j[0].Ah = Aqh; gj.j[0].Bh = Bqh; gj.j[0].Ch = Qh;
    gj.j[0].Cf = nullptr; gj.j[0].bias = nullptr; gj.j[0].cnt = nullptr;
    gj.j[0].scale = 0.125f;
    gj.j[1].Ah = Akh; gj.j[1].Bh = Bkh; gj.j[1].Ch = Kh;
    gj.j[1].Cf = nullptr; gj.j[1].bias = nullptr; gj.j[1].cnt = cnt;
    gj.j[1].scale = 1.0f;
    gj.j[2].Ah = Avh; gj.j[2].Bh = Bvh; gj.j[2].Ch = Vh;
    gj.j[2].Cf = nullptr; gj.j[2].bias = nullptr; gj.j[2].cnt = cnt;
    gj.j[2].scale = 1.0f;
    gj.n = 3;
    gemm1p_kernel<<<2 * sms, 256, GSMEM>>>(gj);

    // 5. attention over compacted keys (Br=128, 2 CTAs/SM)
    dim3 gAttn(S_LEN / 128, BATCH * NHEAD);   // (16, 64)
    attn_mma_kernel<<<gAttn, 256, ASMEM>>>(Qh, Kh, Vh, cnt, Ch);

    // 6. persistent output projection (+bias) -> fp32, 2 CTAs per SM
    GJobs go;
    go.j[0].Ah = Ch; go.j[0].Bh = Boh; go.j[0].Ch = nullptr;
    go.j[0].Cf = out; go.j[0].bias = bo; go.j[0].cnt = nullptr;
    go.j[0].scale = 1.0f;
    go.j[1] = go.j[0];
    go.j[2] = go.j[0];
    go.n = 1;
    gemm1p_kernel<<<2 * sms, 256, GSMEM>>>(go);
}